// round 7
// baseline (speedup 1.0000x reference)
#include <cuda_runtime.h>
#include <cuda_bf16.h>
#include <math_constants.h>
#include <cstdint>

// Problem constants
#define BATCH   4
#define SEQ     2048
#define DMODEL  1024
#define NHEADS  16
#define HDIM    64
#define TOKENS  (BATCH * SEQ)   // 8192

#define LOG2E 1.4426950408889634f

// ---------------------------------------------------------------------------
// Scratch (allocation-free rule: __device__ globals)
// ---------------------------------------------------------------------------
__device__ __nv_bfloat16 g_xhi[TOKENS * DMODEL];
__device__ __nv_bfloat16 g_xlo[TOKENS * DMODEL];
__device__ __nv_bfloat16 g_qhi[TOKENS * DMODEL];
__device__ __nv_bfloat16 g_qlo[TOKENS * DMODEL];
__device__ __nv_bfloat16 g_khi[TOKENS * DMODEL];
__device__ __nv_bfloat16 g_klo[TOKENS * DMODEL];
__device__ __nv_bfloat16 g_vhi[TOKENS * DMODEL];
__device__ __nv_bfloat16 g_vlo[TOKENS * DMODEL];
__device__ __nv_bfloat16 g_chi[TOKENS * DMODEL];
__device__ __nv_bfloat16 g_clo[TOKENS * DMODEL];
__device__ __nv_bfloat16 g_wqhi[DMODEL * DMODEL];
__device__ __nv_bfloat16 g_wqlo[DMODEL * DMODEL];
__device__ __nv_bfloat16 g_wkhi[DMODEL * DMODEL];
__device__ __nv_bfloat16 g_wklo[DMODEL * DMODEL];
__device__ __nv_bfloat16 g_wvhi[DMODEL * DMODEL];
__device__ __nv_bfloat16 g_wvlo[DMODEL * DMODEL];
__device__ __nv_bfloat16 g_wohi[DMODEL * DMODEL];
__device__ __nv_bfloat16 g_wolo[DMODEL * DMODEL];

// ---------------------------------------------------------------------------
// PTX helpers (sm_80-baseline only: cp.async, ldmatrix, mma.sync)
// ---------------------------------------------------------------------------
__device__ __forceinline__ uint32_t smem_u32(const void* p) {
    uint32_t a;
    asm("{ .reg .u64 t; cvta.to.shared.u64 t, %1; cvt.u32.u64 %0, t; }"
        : "=r"(a) : "l"(p));
    return a;
}

__device__ __forceinline__ void cp_async16(uint32_t smem, const void* gmem) {
    asm volatile("cp.async.cg.shared.global [%0], [%1], 16;\n"
                 :: "r"(smem), "l"(gmem));
}
#define CP_COMMIT() asm volatile("cp.async.commit_group;\n" ::: "memory")
#define CP_WAIT(n)  asm volatile("cp.async.wait_group %0;\n" :: "n"(n) : "memory")

__device__ __forceinline__ void ldsm_x4(uint32_t* r, uint32_t addr) {
    asm volatile("ldmatrix.sync.aligned.m8n8.x4.shared.b16 {%0,%1,%2,%3}, [%4];"
                 : "=r"(r[0]), "=r"(r[1]), "=r"(r[2]), "=r"(r[3]) : "r"(addr));
}

__device__ __forceinline__ void ldsm_x4_trans(uint32_t* r, uint32_t addr) {
    asm volatile("ldmatrix.sync.aligned.m8n8.x4.trans.shared.b16 {%0,%1,%2,%3}, [%4];"
                 : "=r"(r[0]), "=r"(r[1]), "=r"(r[2]), "=r"(r[3]) : "r"(addr));
}

__device__ __forceinline__ void mma_bf16(float* c, const uint32_t* a,
                                         uint32_t b0, uint32_t b1) {
    asm volatile(
        "mma.sync.aligned.m16n8k16.row.col.f32.bf16.bf16.f32 "
        "{%0,%1,%2,%3}, {%4,%5,%6,%7}, {%8,%9}, {%0,%1,%2,%3};"
        : "+f"(c[0]), "+f"(c[1]), "+f"(c[2]), "+f"(c[3])
        : "r"(a[0]), "r"(a[1]), "r"(a[2]), "r"(a[3]), "r"(b0), "r"(b1));
}

__device__ __forceinline__ uint32_t pack_bf16(float x, float y) {
    __nv_bfloat162 t = __floats2bfloat162_rn(x, y);
    return *(uint32_t*)&t;
}

// ---------------------------------------------------------------------------
// Split fp32 -> (bf16 hi, bf16 lo).
// ---------------------------------------------------------------------------
__global__ void split_bf16_kernel(const float* __restrict__ in,
                                  __nv_bfloat16* __restrict__ hi,
                                  __nv_bfloat16* __restrict__ lo, int n)
{
    int i = (blockIdx.x * blockDim.x + threadIdx.x) * 4;
    if (i >= n) return;
    float4 v = *(const float4*)(in + i);
    __nv_bfloat16 h0 = __float2bfloat16(v.x);
    __nv_bfloat16 h1 = __float2bfloat16(v.y);
    __nv_bfloat16 h2 = __float2bfloat16(v.z);
    __nv_bfloat16 h3 = __float2bfloat16(v.w);
    __nv_bfloat16 l0 = __float2bfloat16(v.x - __bfloat162float(h0));
    __nv_bfloat16 l1 = __float2bfloat16(v.y - __bfloat162float(h1));
    __nv_bfloat16 l2 = __float2bfloat16(v.z - __bfloat162float(h2));
    __nv_bfloat16 l3 = __float2bfloat16(v.w - __bfloat162float(h3));
    ((__nv_bfloat162*)(hi + i))[0] = __nv_bfloat162(h0, h1);
    ((__nv_bfloat162*)(hi + i))[1] = __nv_bfloat162(h2, h3);
    ((__nv_bfloat162*)(lo + i))[0] = __nv_bfloat162(l0, l1);
    ((__nv_bfloat162*)(lo + i))[1] = __nv_bfloat162(l2, l3);
}

// ---------------------------------------------------------------------------
// GEMM core shared geometry: CTA 128x128, BK=32, 512 threads (16 warps, 4x4),
// warp tile 32x32, 3-stage cp.async pipeline.
// ---------------------------------------------------------------------------
#define GK_BK       32
#define GK_ROW_B    80
#define GK_TILE_B   (128 * GK_ROW_B)
#define GK_STAGE_B  (4 * GK_TILE_B)            // 40960
#define GK_STAGES   3
#define GK_SMEM     (GK_STAGES * GK_STAGE_B)   // 122880
#define GK_NCHUNKS  (DMODEL / GK_BK)           // 32

// Loads one 128x32 K-chunk of all 4 operand tiles into stage st.
__device__ __forceinline__ void gk_load_chunk(
    const __nv_bfloat16* const* srcs, int bm, int bn, int c, int st,
    uint32_t sbase, int tid)
{
    const int k0 = c * GK_BK;
#pragma unroll
    for (int t = 0; t < 4; t++) {
        const __nv_bfloat16* src = srcs[t];
        const int rbase = (t < 2) ? bm : bn;
        const uint32_t tb = sbase + st * GK_STAGE_B + t * GK_TILE_B;
        const int i = tid;          // 512 threads cover 512 16B-transfers
        const int r = i >> 2;
        const int q = i & 3;
        cp_async16(tb + r * GK_ROW_B + q * 16,
                   src + (size_t)(rbase + r) * DMODEL + k0 + q * 8);
    }
    CP_COMMIT();
}

// Mainloop: accumulate into acc[2][4][4].
__device__ __forceinline__ void gk_mainloop(
    const __nv_bfloat16* const* srcs, int bm, int bn,
    uint32_t sbase, int tid, float acc[2][4][4])
{
    const int wid  = tid >> 5;
    const int lane = tid & 31;
    const int warp_m = wid >> 2;     // 0..3
    const int warp_n = wid & 3;      // 0..3

    gk_load_chunk(srcs, bm, bn, 0, 0, sbase, tid);
    gk_load_chunk(srcs, bm, bn, 1, 1, sbase, tid);

    const uint32_t lrow16 = (uint32_t)(lane & 15);
    const uint32_t lcolb  = (uint32_t)((lane >> 4) << 4);

    for (int c = 0; c < GK_NCHUNKS; c++) {
        const int st = c % GK_STAGES;
        if (c + 1 < GK_NCHUNKS) { CP_WAIT(1); } else { CP_WAIT(0); }
        __syncthreads();
        if (c + 2 < GK_NCHUNKS)
            gk_load_chunk(srcs, bm, bn, c + 2, (c + 2) % GK_STAGES, sbase, tid);

        const uint32_t stg = sbase + st * GK_STAGE_B;
        const uint32_t a_r = (uint32_t)(warp_m * 32) + lrow16;
        const uint32_t b_r = (uint32_t)(warp_n * 32) + lrow16;

#pragma unroll
        for (int ks = 0; ks < 2; ks++) {
            const uint32_t kb = lcolb + ks * 32;
            uint32_t ah[2][4], al[2][4], bh[2][4], bl[2][4];
#pragma unroll
            for (int mi = 0; mi < 2; mi++) {
                uint32_t ro = (a_r + mi * 16) * GK_ROW_B + kb;
                ldsm_x4(ah[mi], stg + 0 * GK_TILE_B + ro);
                ldsm_x4(al[mi], stg + 1 * GK_TILE_B + ro);
            }
#pragma unroll
            for (int p = 0; p < 2; p++) {
                uint32_t ro = (b_r + p * 16) * GK_ROW_B + kb;
                ldsm_x4(bh[p], stg + 2 * GK_TILE_B + ro);
                ldsm_x4(bl[p], stg + 3 * GK_TILE_B + ro);
            }
#pragma unroll
            for (int mi = 0; mi < 2; mi++)
#pragma unroll
                for (int ni = 0; ni < 4; ni++) {
                    const int p = ni >> 1, s = ni & 1;
                    mma_bf16(acc[mi][ni], ah[mi], bh[p][s], bh[p][s + 2]);
                    mma_bf16(acc[mi][ni], ah[mi], bl[p][s], bl[p][s + 2]);
                    mma_bf16(acc[mi][ni], al[mi], bh[p][s], bh[p][s + 2]);
                }
        }
        __syncthreads();
    }
}

// ---------------------------------------------------------------------------
// Fused QKV projection: grid.z in {0,1,2} selects (Wq->Q, Wk->K, Wv->V).
// Output: bf16 hi/lo split.
// ---------------------------------------------------------------------------
__global__ __launch_bounds__(512) void gemm_qkv(
    const __nv_bfloat16* __restrict__ xhi, const __nv_bfloat16* __restrict__ xlo,
    const __nv_bfloat16* __restrict__ wqhi, const __nv_bfloat16* __restrict__ wqlo,
    const __nv_bfloat16* __restrict__ wkhi, const __nv_bfloat16* __restrict__ wklo,
    const __nv_bfloat16* __restrict__ wvhi, const __nv_bfloat16* __restrict__ wvlo,
    __nv_bfloat16* __restrict__ qhi, __nv_bfloat16* __restrict__ qlo,
    __nv_bfloat16* __restrict__ khi, __nv_bfloat16* __restrict__ klo,
    __nv_bfloat16* __restrict__ vhi, __nv_bfloat16* __restrict__ vlo)
{
    extern __shared__ char smem[];
    const uint32_t sbase = smem_u32(smem);
    const int tid = threadIdx.x;
    const int bm = blockIdx.y * 128;
    const int bn = blockIdx.x * 128;

    const __nv_bfloat16 *Bhi, *Blo;
    __nv_bfloat16 *Chi, *Clo;
    if (blockIdx.z == 0)      { Bhi = wqhi; Blo = wqlo; Chi = qhi; Clo = qlo; }
    else if (blockIdx.z == 1) { Bhi = wkhi; Blo = wklo; Chi = khi; Clo = klo; }
    else                      { Bhi = wvhi; Blo = wvlo; Chi = vhi; Clo = vlo; }

    const __nv_bfloat16* srcs[4] = {xhi, xlo, Bhi, Blo};

    float acc[2][4][4];
#pragma unroll
    for (int i = 0; i < 2; i++)
#pragma unroll
        for (int j = 0; j < 4; j++)
#pragma unroll
            for (int r = 0; r < 4; r++) acc[i][j][r] = 0.f;

    gk_mainloop(srcs, bm, bn, sbase, tid, acc);

    const int wid  = tid >> 5;
    const int lane = tid & 31;
    const int warp_m = wid >> 2;
    const int warp_n = wid & 3;
    const int er = lane >> 2;
    const int ec = (lane & 3) * 2;
#pragma unroll
    for (int mi = 0; mi < 2; mi++) {
        const int row0 = bm + warp_m * 32 + mi * 16 + er;
#pragma unroll
        for (int ni = 0; ni < 4; ni++) {
            const int col = bn + warp_n * 32 + ni * 8 + ec;
            float a0 = acc[mi][ni][0], a1 = acc[mi][ni][1];
            float a2 = acc[mi][ni][2], a3 = acc[mi][ni][3];
            float h0 = __bfloat162float(__float2bfloat16(a0));
            float h1 = __bfloat162float(__float2bfloat16(a1));
            float h2 = __bfloat162float(__float2bfloat16(a2));
            float h3 = __bfloat162float(__float2bfloat16(a3));
            *(uint32_t*)(Chi + (size_t)row0 * DMODEL + col)       = pack_bf16(a0, a1);
            *(uint32_t*)(Clo + (size_t)row0 * DMODEL + col)       = pack_bf16(a0 - h0, a1 - h1);
            *(uint32_t*)(Chi + (size_t)(row0 + 8) * DMODEL + col) = pack_bf16(a2, a3);
            *(uint32_t*)(Clo + (size_t)(row0 + 8) * DMODEL + col) = pack_bf16(a2 - h2, a3 - h3);
        }
    }
}

// ---------------------------------------------------------------------------
// Output projection: fp32 out + bias.
// ---------------------------------------------------------------------------
__global__ __launch_bounds__(512) void gemm_out(
    const __nv_bfloat16* __restrict__ Ahi, const __nv_bfloat16* __restrict__ Alo,
    const __nv_bfloat16* __restrict__ Bhi, const __nv_bfloat16* __restrict__ Blo,
    const float* __restrict__ bias, float* __restrict__ C)
{
    extern __shared__ char smem[];
    const uint32_t sbase = smem_u32(smem);
    const int tid = threadIdx.x;
    const int bm = blockIdx.y * 128;
    const int bn = blockIdx.x * 128;

    const __nv_bfloat16* srcs[4] = {Ahi, Alo, Bhi, Blo};

    float acc[2][4][4];
#pragma unroll
    for (int i = 0; i < 2; i++)
#pragma unroll
        for (int j = 0; j < 4; j++)
#pragma unroll
            for (int r = 0; r < 4; r++) acc[i][j][r] = 0.f;

    gk_mainloop(srcs, bm, bn, sbase, tid, acc);

    const int wid  = tid >> 5;
    const int lane = tid & 31;
    const int warp_m = wid >> 2;
    const int warp_n = wid & 3;
    const int er = lane >> 2;
    const int ec = (lane & 3) * 2;
#pragma unroll
    for (int mi = 0; mi < 2; mi++) {
        const int row0 = bm + warp_m * 32 + mi * 16 + er;
#pragma unroll
        for (int ni = 0; ni < 4; ni++) {
            const int col = bn + warp_n * 32 + ni * 8 + ec;
            const float b0 = bias[col];
            const float b1 = bias[col + 1];
            float2 v0 = make_float2(acc[mi][ni][0] + b0, acc[mi][ni][1] + b1);
            float2 v1 = make_float2(acc[mi][ni][2] + b0, acc[mi][ni][3] + b1);
            *(float2*)(C + (size_t)row0 * DMODEL + col)       = v0;
            *(float2*)(C + (size_t)(row0 + 8) * DMODEL + col) = v1;
        }
    }
}

// ---------------------------------------------------------------------------
// Tensor-core flash attention (causal), bf16x3 MMA, fp32 softmax.
// Inputs: Q/K/V as bf16 hi/lo splits [token, DMODEL]. Output: ctx hi/lo.
// 3-stage cp.async K/V pipeline; 256 threads; 8 warps x 16 q rows.
// ---------------------------------------------------------------------------
#define FA_PITCH   72
#define FA_ARR_B   (64 * FA_PITCH * 2)      // 9216 bytes per array
#define FA_STAGE_B (4 * FA_ARR_B)           // 36864 (khi, klo, vhi, vlo)
#define FA_STAGES  3
#define FA_SMEM    (FA_STAGES * FA_STAGE_B) // 110592

__global__ __launch_bounds__(256) void flash_mma_kernel(
    const __nv_bfloat16* __restrict__ Qhi, const __nv_bfloat16* __restrict__ Qlo,
    const __nv_bfloat16* __restrict__ Khi, const __nv_bfloat16* __restrict__ Klo,
    const __nv_bfloat16* __restrict__ Vhi, const __nv_bfloat16* __restrict__ Vlo,
    __nv_bfloat16* __restrict__ Chi, __nv_bfloat16* __restrict__ Clo)
{
    extern __shared__ char fsm[];
    const uint32_t sbase = smem_u32(fsm);

    const int tid  = threadIdx.x;
    const int wid  = tid >> 5;
    const int lane = tid & 31;
    const int qt = blockIdx.x;
    const int h  = blockIdx.y;
    const int b  = blockIdx.z;

    const int q0_tok = b * SEQ + qt * 128;
    const int qrow_w = qt * 128 + wid * 16;

    uint32_t qhi[4][4], qlo[4][4];
    {
        const __nv_bfloat16* Qh = Qhi + (size_t)(q0_tok + wid * 16) * DMODEL + h * HDIM;
        const __nv_bfloat16* Ql = Qlo + (size_t)(q0_tok + wid * 16) * DMODEL + h * HDIM;
        const __nv_bfloat162 s2 = __floats2bfloat162_rn(0.125f, 0.125f);
        const int r = lane >> 2;
        const int c = (lane & 3) * 2;
#pragma unroll
        for (int t = 0; t < 4; t++)
#pragma unroll
            for (int i = 0; i < 4; i++) {
                const int rr = r + (i & 1) * 8;
                const int cc = t * 16 + c + (i >> 1) * 8;
                __nv_bfloat162 hv = *(const __nv_bfloat162*)(Qh + (size_t)rr * DMODEL + cc);
                __nv_bfloat162 lv = *(const __nv_bfloat162*)(Ql + (size_t)rr * DMODEL + cc);
                hv = __hmul2(hv, s2);
                lv = __hmul2(lv, s2);
                qhi[t][i] = *(uint32_t*)&hv;
                qlo[t][i] = *(uint32_t*)&lv;
            }
    }

    float o[8][4];
    float m[2], l[2];
#pragma unroll
    for (int i = 0; i < 8; i++)
#pragma unroll
        for (int j = 0; j < 4; j++) o[i][j] = 0.f;
    m[0] = m[1] = -CUDART_INF_F;
    l[0] = l[1] = 0.f;

    const uint32_t k_loff = (uint32_t)(((lane & 7) + ((lane >> 4) << 3)) * (FA_PITCH * 2)
                                       + (((lane >> 3) & 1) << 4));
    const uint32_t v_loff = (uint32_t)(((lane & 7) + (((lane >> 3) & 1) << 3)) * (FA_PITCH * 2)
                                       + ((lane >> 4) << 4));

    const __nv_bfloat16* kv_srcs[4] = {
        Khi + h * HDIM, Klo + h * HDIM, Vhi + h * HDIM, Vlo + h * HDIM };

    auto load_tile = [&](int kt, int stg) {
        const size_t tok0 = (size_t)(b * SEQ + kt * 64);
        const uint32_t sb = sbase + stg * FA_STAGE_B;
#pragma unroll
        for (int t = 0; t < 4; t++) {
            const __nv_bfloat16* src = kv_srcs[t] + tok0 * DMODEL;
            const uint32_t db = sb + t * FA_ARR_B;
#pragma unroll
            for (int i = tid; i < 512; i += 256) {
                const int r  = i >> 3;
                const int c8 = i & 7;
                cp_async16(db + r * (FA_PITCH * 2) + c8 * 16,
                           src + (size_t)r * DMODEL + c8 * 8);
            }
        }
        CP_COMMIT();
    };

    const int nkt = 2 * qt + 2;

    load_tile(0, 0);
    if (nkt > 1) load_tile(1, 1);

    for (int kt = 0; kt < nkt; kt++) {
        const int kb = kt * 64;
        const int stg = kt % FA_STAGES;
        if (kt + 1 < nkt) { CP_WAIT(1); } else { CP_WAIT(0); }
        __syncthreads();
        if (kt + 2 < nkt) load_tile(kt + 2, (kt + 2) % FA_STAGES);

        if (kb > qrow_w + 15) continue;

        const uint32_t ks_hi_b = sbase + stg * FA_STAGE_B;
        const uint32_t ks_lo_b = ks_hi_b + FA_ARR_B;
        const uint32_t vs_hi_b = ks_hi_b + 2 * FA_ARR_B;
        const uint32_t vs_lo_b = ks_hi_b + 3 * FA_ARR_B;

        // ---- S = Q K^T (bf16x3), warp tile 16 x 64 ----
        float s[8][4];
#pragma unroll
        for (int i = 0; i < 8; i++)
#pragma unroll
            for (int j = 0; j < 4; j++) s[i][j] = 0.f;

#pragma unroll
        for (int t = 0; t < 4; t++) {
#pragma unroll
            for (int pp = 0; pp < 4; pp++) {
                const uint32_t ro = (uint32_t)(pp * 16 * (FA_PITCH * 2) + t * 32) + k_loff;
                uint32_t kh[4], kl[4];
                ldsm_x4(kh, ks_hi_b + ro);
                ldsm_x4(kl, ks_lo_b + ro);
                mma_bf16(s[2 * pp],     qhi[t], kh[0], kh[1]);
                mma_bf16(s[2 * pp],     qhi[t], kl[0], kl[1]);
                mma_bf16(s[2 * pp],     qlo[t], kh[0], kh[1]);
                mma_bf16(s[2 * pp + 1], qhi[t], kh[2], kh[3]);
                mma_bf16(s[2 * pp + 1], qhi[t], kl[2], kl[3]);
                mma_bf16(s[2 * pp + 1], qlo[t], kh[2], kh[3]);
            }
        }

        // ---- causal mask ----
        const int row_g0 = qrow_w + (lane >> 2);
        if (kb + 63 > qrow_w) {
#pragma unroll
            for (int nt = 0; nt < 8; nt++) {
                const int colb = kb + nt * 8 + (lane & 3) * 2;
#pragma unroll
                for (int i = 0; i < 4; i++) {
                    const int row = row_g0 + (i >> 1) * 8;
                    const int col = colb + (i & 1);
                    if (col > row) s[nt][i] = -CUDART_INF_F;
                }
            }
        }

        // ---- online softmax ----
        float rmax[2];
        rmax[0] = rmax[1] = -CUDART_INF_F;
#pragma unroll
        for (int nt = 0; nt < 8; nt++) {
            rmax[0] = fmaxf(rmax[0], fmaxf(s[nt][0], s[nt][1]));
            rmax[1] = fmaxf(rmax[1], fmaxf(s[nt][2], s[nt][3]));
        }
#pragma unroll
        for (int off = 1; off <= 2; off <<= 1) {
            rmax[0] = fmaxf(rmax[0], __shfl_xor_sync(0xffffffffu, rmax[0], off));
            rmax[1] = fmaxf(rmax[1], __shfl_xor_sync(0xffffffffu, rmax[1], off));
        }

        float alpha[2], rsum[2];
#pragma unroll
        for (int i = 0; i < 2; i++) {
            float mn = fmaxf(m[i], rmax[i]);
            alpha[i] = exp2f((m[i] - mn) * LOG2E);
            m[i] = mn;
            rsum[i] = 0.f;
        }

#pragma unroll
        for (int nt = 0; nt < 8; nt++) {
            s[nt][0] = exp2f((s[nt][0] - m[0]) * LOG2E);
            s[nt][1] = exp2f((s[nt][1] - m[0]) * LOG2E);
            s[nt][2] = exp2f((s[nt][2] - m[1]) * LOG2E);
            s[nt][3] = exp2f((s[nt][3] - m[1]) * LOG2E);
            rsum[0] += s[nt][0] + s[nt][1];
            rsum[1] += s[nt][2] + s[nt][3];
        }
#pragma unroll
        for (int off = 1; off <= 2; off <<= 1) {
            rsum[0] += __shfl_xor_sync(0xffffffffu, rsum[0], off);
            rsum[1] += __shfl_xor_sync(0xffffffffu, rsum[1], off);
        }
        l[0] = l[0] * alpha[0] + rsum[0];
        l[1] = l[1] * alpha[1] + rsum[1];
#pragma unroll
        for (int nt = 0; nt < 8; nt++) {
            o[nt][0] *= alpha[0]; o[nt][1] *= alpha[0];
            o[nt][2] *= alpha[1]; o[nt][3] *= alpha[1];
        }

        // ---- O += P V (bf16x3) ----
#pragma unroll
        for (int t = 0; t < 4; t++) {
            uint32_t ahi[4], alo[4];
            {
                float x0 = s[2 * t][0],     x1 = s[2 * t][1];
                float x2 = s[2 * t][2],     x3 = s[2 * t][3];
                float y0 = s[2 * t + 1][0], y1 = s[2 * t + 1][1];
                float y2 = s[2 * t + 1][2], y3 = s[2 * t + 1][3];
                float hx0 = __bfloat162float(__float2bfloat16(x0));
                float hx1 = __bfloat162float(__float2bfloat16(x1));
                float hx2 = __bfloat162float(__float2bfloat16(x2));
                float hx3 = __bfloat162float(__float2bfloat16(x3));
                float hy0 = __bfloat162float(__float2bfloat16(y0));
                float hy1 = __bfloat162float(__float2bfloat16(y1));
                float hy2 = __bfloat162float(__float2bfloat16(y2));
                float hy3 = __bfloat162float(__float2bfloat16(y3));
                ahi[0] = pack_bf16(x0, x1);  alo[0] = pack_bf16(x0 - hx0, x1 - hx1);
                ahi[1] = pack_bf16(x2, x3);  alo[1] = pack_bf16(x2 - hx2, x3 - hx3);
                ahi[2] = pack_bf16(y0, y1);  alo[2] = pack_bf16(y0 - hy0, y1 - hy1);
                ahi[3] = pack_bf16(y2, y3);  alo[3] = pack_bf16(y2 - hy2, y3 - hy3);
            }
#pragma unroll
            for (int dp = 0; dp < 4; dp++) {
                const uint32_t ro = (uint32_t)(t * 16 * (FA_PITCH * 2) + dp * 32) + v_loff;
                uint32_t bh[4], bl[4];
                ldsm_x4_trans(bh, vs_hi_b + ro);
                ldsm_x4_trans(bl, vs_lo_b + ro);
                mma_bf16(o[2 * dp],     ahi, bh[0], bh[1]);
                mma_bf16(o[2 * dp],     ahi, bl[0], bl[1]);
                mma_bf16(o[2 * dp],     alo, bh[0], bh[1]);
                mma_bf16(o[2 * dp + 1], ahi, bh[2], bh[3]);
                mma_bf16(o[2 * dp + 1], ahi, bl[2], bl[3]);
                mma_bf16(o[2 * dp + 1], alo, bh[2], bh[3]);
            }
        }
    }

    // ---- epilogue: normalize, split to hi/lo, store ctx ----
    const float inv0 = 1.f / l[0];
    const float inv1 = 1.f / l[1];
    const int orow = q0_tok + wid * 16 + (lane >> 2);
    const int colb = h * HDIM + (lane & 3) * 2;
#pragma unroll
    for (int nt = 0; nt < 8; nt++) {
        const int col = colb + nt * 8;
        float v00 = o[nt][0] * inv0, v01 = o[nt][1] * inv0;
        float v10 = o[nt][2] * inv1, v11 = o[nt][3] * inv1;
        float h00 = __bfloat162float(__float2bfloat16(v00));
        float h01 = __bfloat162float(__float2bfloat16(v01));
        float h10 = __bfloat162float(__float2bfloat16(v10));
        float h11 = __bfloat162float(__float2bfloat16(v11));
        *(uint32_t*)(Chi + (size_t)orow * DMODEL + col)       = pack_bf16(v00, v01);
        *(uint32_t*)(Clo + (size_t)orow * DMODEL + col)       = pack_bf16(v00 - h00, v01 - h01);
        *(uint32_t*)(Chi + (size_t)(orow + 8) * DMODEL + col) = pack_bf16(v10, v11);
        *(uint32_t*)(Clo + (size_t)(orow + 8) * DMODEL + col) = pack_bf16(v10 - h10, v11 - h11);
    }
}

// ---------------------------------------------------------------------------
// Launch
// ---------------------------------------------------------------------------
extern "C" void kernel_launch(void* const* d_in, const int* in_sizes, int n_in,
                              void* d_out, int out_size)
{
    const float* x  = (const float*)d_in[0];
    const float* wq = (const float*)d_in[1];
    const float* wk = (const float*)d_in[2];
    const float* wv = (const float*)d_in[3];
    const float* wo = (const float*)d_in[4];
    const float* bo = (const float*)d_in[5];
    float* out = (float*)d_out;

    __nv_bfloat16 *xhi, *xlo, *qhi, *qlo, *khi, *klo, *vhi, *vlo, *chi, *clo;
    __nv_bfloat16 *wqhi, *wqlo, *wkhi, *wklo, *wvhi, *wvlo, *wohi, *wolo;
    cudaGetSymbolAddress((void**)&xhi,  g_xhi);
    cudaGetSymbolAddress((void**)&xlo,  g_xlo);
    cudaGetSymbolAddress((void**)&qhi,  g_qhi);
    cudaGetSymbolAddress((void**)&qlo,  g_qlo);
    cudaGetSymbolAddress((void**)&khi,  g_khi);
    cudaGetSymbolAddress((void**)&klo,  g_klo);
    cudaGetSymbolAddress((void**)&vhi,  g_vhi);
    cudaGetSymbolAddress((void**)&vlo,  g_vlo);
    cudaGetSymbolAddress((void**)&chi,  g_chi);
    cudaGetSymbolAddress((void**)&clo,  g_clo);
    cudaGetSymbolAddress((void**)&wqhi, g_wqhi);
    cudaGetSymbolAddress((void**)&wqlo, g_wqlo);
    cudaGetSymbolAddress((void**)&wkhi, g_wkhi);
    cudaGetSymbolAddress((void**)&wklo, g_wklo);
    cudaGetSymbolAddress((void**)&wvhi, g_wvhi);
    cudaGetSymbolAddress((void**)&wvlo, g_wvlo);
    cudaGetSymbolAddress((void**)&wohi, g_wohi);
    cudaGetSymbolAddress((void**)&wolo, g_wolo);

    const int nx = TOKENS * DMODEL;
    const int nw = DMODEL * DMODEL;

    split_bf16_kernel<<<nx / 4 / 256, 256>>>(x,  xhi,  xlo,  nx);
    split_bf16_kernel<<<nw / 4 / 256, 256>>>(wq, wqhi, wqlo, nw);
    split_bf16_kernel<<<nw / 4 / 256, 256>>>(wk, wkhi, wklo, nw);
    split_bf16_kernel<<<nw / 4 / 256, 256>>>(wv, wvhi, wvlo, nw);
    split_bf16_kernel<<<nw / 4 / 256, 256>>>(wo, wohi, wolo, nw);

    cudaFuncSetAttribute(gemm_qkv,
                         cudaFuncAttributeMaxDynamicSharedMemorySize, GK_SMEM);
    cudaFuncSetAttribute(gemm_out,
                         cudaFuncAttributeMaxDynamicSharedMemorySize, GK_SMEM);

    gemm_qkv<<<dim3(DMODEL / 128, TOKENS / 128, 3), 512, GK_SMEM>>>(
        xhi, xlo, wqhi, wqlo, wkhi, wklo, wvhi, wvlo,
        qhi, qlo, khi, klo, vhi, vlo);

    cudaFuncSetAttribute(flash_mma_kernel,
                         cudaFuncAttributeMaxDynamicSharedMemorySize, FA_SMEM);
    flash_mma_kernel<<<dim3(SEQ / 128, NHEADS, BATCH), 256, FA_SMEM>>>(
        qhi, qlo, khi, klo, vhi, vlo, chi, clo);

    gemm_out<<<dim3(DMODEL / 128, TOKENS / 128), 512, GK_SMEM>>>(
        chi, clo, wohi, wolo, bo, out);
}

// round 8
// speedup vs baseline: 1.0906x; 1.0906x over previous
#include <cuda_runtime.h>
#include <cuda_bf16.h>
#include <math_constants.h>
#include <cstdint>

// Problem constants
#define BATCH   4
#define SEQ     2048
#define DMODEL  1024
#define NHEADS  16
#define HDIM    64
#define TOKENS  (BATCH * SEQ)   // 8192

#define LOG2E 1.4426950408889634f

// ---------------------------------------------------------------------------
// Scratch (allocation-free rule: __device__ globals)
// ---------------------------------------------------------------------------
__device__ __nv_bfloat16 g_xhi[TOKENS * DMODEL];
__device__ __nv_bfloat16 g_xlo[TOKENS * DMODEL];
__device__ __nv_bfloat16 g_qhi[TOKENS * DMODEL];
__device__ __nv_bfloat16 g_qlo[TOKENS * DMODEL];
__device__ __nv_bfloat16 g_khi[TOKENS * DMODEL];
__device__ __nv_bfloat16 g_klo[TOKENS * DMODEL];
__device__ __nv_bfloat16 g_vhi[TOKENS * DMODEL];
__device__ __nv_bfloat16 g_vlo[TOKENS * DMODEL];
__device__ __nv_bfloat16 g_chi[TOKENS * DMODEL];
__device__ __nv_bfloat16 g_clo[TOKENS * DMODEL];
__device__ __nv_bfloat16 g_wqhi[DMODEL * DMODEL];
__device__ __nv_bfloat16 g_wqlo[DMODEL * DMODEL];
__device__ __nv_bfloat16 g_wkhi[DMODEL * DMODEL];
__device__ __nv_bfloat16 g_wklo[DMODEL * DMODEL];
__device__ __nv_bfloat16 g_wvhi[DMODEL * DMODEL];
__device__ __nv_bfloat16 g_wvlo[DMODEL * DMODEL];
__device__ __nv_bfloat16 g_wohi[DMODEL * DMODEL];
__device__ __nv_bfloat16 g_wolo[DMODEL * DMODEL];

// ---------------------------------------------------------------------------
// PTX helpers (sm_80-baseline only: cp.async, ldmatrix, mma.sync)
// ---------------------------------------------------------------------------
__device__ __forceinline__ uint32_t smem_u32(const void* p) {
    uint32_t a;
    asm("{ .reg .u64 t; cvta.to.shared.u64 t, %1; cvt.u32.u64 %0, t; }"
        : "=r"(a) : "l"(p));
    return a;
}

__device__ __forceinline__ void cp_async16(uint32_t smem, const void* gmem) {
    asm volatile("cp.async.cg.shared.global [%0], [%1], 16;\n"
                 :: "r"(smem), "l"(gmem));
}
#define CP_COMMIT() asm volatile("cp.async.commit_group;\n" ::: "memory")
#define CP_WAIT(n)  asm volatile("cp.async.wait_group %0;\n" :: "n"(n) : "memory")

__device__ __forceinline__ void ldsm_x4(uint32_t* r, uint32_t addr) {
    asm volatile("ldmatrix.sync.aligned.m8n8.x4.shared.b16 {%0,%1,%2,%3}, [%4];"
                 : "=r"(r[0]), "=r"(r[1]), "=r"(r[2]), "=r"(r[3]) : "r"(addr));
}

__device__ __forceinline__ void ldsm_x4_trans(uint32_t* r, uint32_t addr) {
    asm volatile("ldmatrix.sync.aligned.m8n8.x4.trans.shared.b16 {%0,%1,%2,%3}, [%4];"
                 : "=r"(r[0]), "=r"(r[1]), "=r"(r[2]), "=r"(r[3]) : "r"(addr));
}

__device__ __forceinline__ void mma_bf16(float* c, const uint32_t* a,
                                         uint32_t b0, uint32_t b1) {
    asm volatile(
        "mma.sync.aligned.m16n8k16.row.col.f32.bf16.bf16.f32 "
        "{%0,%1,%2,%3}, {%4,%5,%6,%7}, {%8,%9}, {%0,%1,%2,%3};"
        : "+f"(c[0]), "+f"(c[1]), "+f"(c[2]), "+f"(c[3])
        : "r"(a[0]), "r"(a[1]), "r"(a[2]), "r"(a[3]), "r"(b0), "r"(b1));
}

__device__ __forceinline__ uint32_t pack_bf16(float x, float y) {
    __nv_bfloat162 t = __floats2bfloat162_rn(x, y);
    return *(uint32_t*)&t;
}

// ---------------------------------------------------------------------------
// Split fp32 -> (bf16 hi, bf16 lo).
// ---------------------------------------------------------------------------
__global__ void split_bf16_kernel(const float* __restrict__ in,
                                  __nv_bfloat16* __restrict__ hi,
                                  __nv_bfloat16* __restrict__ lo, int n)
{
    int i = (blockIdx.x * blockDim.x + threadIdx.x) * 4;
    if (i >= n) return;
    float4 v = *(const float4*)(in + i);
    __nv_bfloat16 h0 = __float2bfloat16(v.x);
    __nv_bfloat16 h1 = __float2bfloat16(v.y);
    __nv_bfloat16 h2 = __float2bfloat16(v.z);
    __nv_bfloat16 h3 = __float2bfloat16(v.w);
    __nv_bfloat16 l0 = __float2bfloat16(v.x - __bfloat162float(h0));
    __nv_bfloat16 l1 = __float2bfloat16(v.y - __bfloat162float(h1));
    __nv_bfloat16 l2 = __float2bfloat16(v.z - __bfloat162float(h2));
    __nv_bfloat16 l3 = __float2bfloat16(v.w - __bfloat162float(h3));
    ((__nv_bfloat162*)(hi + i))[0] = __nv_bfloat162(h0, h1);
    ((__nv_bfloat162*)(hi + i))[1] = __nv_bfloat162(h2, h3);
    ((__nv_bfloat162*)(lo + i))[0] = __nv_bfloat162(l0, l1);
    ((__nv_bfloat162*)(lo + i))[1] = __nv_bfloat162(l2, l3);
}

// ---------------------------------------------------------------------------
// GEMM core: CTA 128x128, BK=32, 256 threads (8 warps, 2x4), warp tile 64x32.
// 2-stage cp.async pipeline (81,920 B SMEM); __launch_bounds__(256,2) caps
// registers at 128/thread so 2 CTAs co-reside per SM.
// ---------------------------------------------------------------------------
#define GK_BK       32
#define GK_ROW_B    80
#define GK_TILE_B   (128 * GK_ROW_B)
#define GK_STAGE_B  (4 * GK_TILE_B)            // 40960
#define GK_STAGES   2
#define GK_SMEM     (GK_STAGES * GK_STAGE_B)   // 81920
#define GK_NCHUNKS  (DMODEL / GK_BK)           // 32

__device__ __forceinline__ void gk_load_chunk(
    const __nv_bfloat16* const* srcs, int bm, int bn, int c, int st,
    uint32_t sbase, int tid)
{
    const int k0 = c * GK_BK;
#pragma unroll
    for (int t = 0; t < 4; t++) {
        const __nv_bfloat16* src = srcs[t];
        const int rbase = (t < 2) ? bm : bn;
        const uint32_t tb = sbase + st * GK_STAGE_B + t * GK_TILE_B;
#pragma unroll
        for (int i = tid; i < 512; i += 256) {
            const int r = i >> 2;
            const int q = i & 3;
            cp_async16(tb + r * GK_ROW_B + q * 16,
                       src + (size_t)(rbase + r) * DMODEL + k0 + q * 8);
        }
    }
    CP_COMMIT();
}

__device__ __forceinline__ void gk_mainloop(
    const __nv_bfloat16* const* srcs, int bm, int bn,
    uint32_t sbase, int tid, float acc[4][4][4])
{
    const int wid  = tid >> 5;
    const int lane = tid & 31;
    const int warp_m = wid >> 2;     // 0..1
    const int warp_n = wid & 3;      // 0..3

    gk_load_chunk(srcs, bm, bn, 0, 0, sbase, tid);

    const uint32_t lrow16 = (uint32_t)(lane & 15);
    const uint32_t lcolb  = (uint32_t)((lane >> 4) << 4);

    for (int c = 0; c < GK_NCHUNKS; c++) {
        const int st = c & 1;
        CP_WAIT(0);
        __syncthreads();
        if (c + 1 < GK_NCHUNKS)
            gk_load_chunk(srcs, bm, bn, c + 1, (c + 1) & 1, sbase, tid);

        const uint32_t stg = sbase + st * GK_STAGE_B;
        const uint32_t a_r = (uint32_t)(warp_m * 64) + lrow16;
        const uint32_t b_r = (uint32_t)(warp_n * 32) + lrow16;

#pragma unroll
        for (int ks = 0; ks < 2; ks++) {
            const uint32_t kb = lcolb + ks * 32;
            uint32_t ah[4][4], al[4][4], bh[2][4], bl[2][4];
#pragma unroll
            for (int mi = 0; mi < 4; mi++) {
                uint32_t ro = (a_r + mi * 16) * GK_ROW_B + kb;
                ldsm_x4(ah[mi], stg + 0 * GK_TILE_B + ro);
                ldsm_x4(al[mi], stg + 1 * GK_TILE_B + ro);
            }
#pragma unroll
            for (int p = 0; p < 2; p++) {
                uint32_t ro = (b_r + p * 16) * GK_ROW_B + kb;
                ldsm_x4(bh[p], stg + 2 * GK_TILE_B + ro);
                ldsm_x4(bl[p], stg + 3 * GK_TILE_B + ro);
            }
#pragma unroll
            for (int mi = 0; mi < 4; mi++)
#pragma unroll
                for (int ni = 0; ni < 4; ni++) {
                    const int p = ni >> 1, s = ni & 1;
                    mma_bf16(acc[mi][ni], ah[mi], bh[p][s], bh[p][s + 2]);
                    mma_bf16(acc[mi][ni], ah[mi], bl[p][s], bl[p][s + 2]);
                    mma_bf16(acc[mi][ni], al[mi], bh[p][s], bh[p][s + 2]);
                }
        }
        __syncthreads();
    }
}

// ---------------------------------------------------------------------------
// Fused QKV projection: grid.z in {0,1,2} selects (Wq->Q, Wk->K, Wv->V).
// Output: bf16 hi/lo split.
// ---------------------------------------------------------------------------
__global__ __launch_bounds__(256, 2) void gemm_qkv(
    const __nv_bfloat16* __restrict__ xhi, const __nv_bfloat16* __restrict__ xlo,
    const __nv_bfloat16* __restrict__ wqhi, const __nv_bfloat16* __restrict__ wqlo,
    const __nv_bfloat16* __restrict__ wkhi, const __nv_bfloat16* __restrict__ wklo,
    const __nv_bfloat16* __restrict__ wvhi, const __nv_bfloat16* __restrict__ wvlo,
    __nv_bfloat16* __restrict__ qhi, __nv_bfloat16* __restrict__ qlo,
    __nv_bfloat16* __restrict__ khi, __nv_bfloat16* __restrict__ klo,
    __nv_bfloat16* __restrict__ vhi, __nv_bfloat16* __restrict__ vlo)
{
    extern __shared__ char smem[];
    const uint32_t sbase = smem_u32(smem);
    const int tid = threadIdx.x;
    const int bm = blockIdx.y * 128;
    const int bn = blockIdx.x * 128;

    const __nv_bfloat16 *Bhi, *Blo;
    __nv_bfloat16 *Chi, *Clo;
    if (blockIdx.z == 0)      { Bhi = wqhi; Blo = wqlo; Chi = qhi; Clo = qlo; }
    else if (blockIdx.z == 1) { Bhi = wkhi; Blo = wklo; Chi = khi; Clo = klo; }
    else                      { Bhi = wvhi; Blo = wvlo; Chi = vhi; Clo = vlo; }

    const __nv_bfloat16* srcs[4] = {xhi, xlo, Bhi, Blo};

    float acc[4][4][4];
#pragma unroll
    for (int i = 0; i < 4; i++)
#pragma unroll
        for (int j = 0; j < 4; j++)
#pragma unroll
            for (int r = 0; r < 4; r++) acc[i][j][r] = 0.f;

    gk_mainloop(srcs, bm, bn, sbase, tid, acc);

    const int wid  = tid >> 5;
    const int lane = tid & 31;
    const int warp_m = wid >> 2;
    const int warp_n = wid & 3;
    const int er = lane >> 2;
    const int ec = (lane & 3) * 2;
#pragma unroll
    for (int mi = 0; mi < 4; mi++) {
        const int row0 = bm + warp_m * 64 + mi * 16 + er;
#pragma unroll
        for (int ni = 0; ni < 4; ni++) {
            const int col = bn + warp_n * 32 + ni * 8 + ec;
            float a0 = acc[mi][ni][0], a1 = acc[mi][ni][1];
            float a2 = acc[mi][ni][2], a3 = acc[mi][ni][3];
            float h0 = __bfloat162float(__float2bfloat16(a0));
            float h1 = __bfloat162float(__float2bfloat16(a1));
            float h2 = __bfloat162float(__float2bfloat16(a2));
            float h3 = __bfloat162float(__float2bfloat16(a3));
            *(uint32_t*)(Chi + (size_t)row0 * DMODEL + col)       = pack_bf16(a0, a1);
            *(uint32_t*)(Clo + (size_t)row0 * DMODEL + col)       = pack_bf16(a0 - h0, a1 - h1);
            *(uint32_t*)(Chi + (size_t)(row0 + 8) * DMODEL + col) = pack_bf16(a2, a3);
            *(uint32_t*)(Clo + (size_t)(row0 + 8) * DMODEL + col) = pack_bf16(a2 - h2, a3 - h3);
        }
    }
}

// ---------------------------------------------------------------------------
// Output projection: fp32 out + bias.
// ---------------------------------------------------------------------------
__global__ __launch_bounds__(256, 2) void gemm_out(
    const __nv_bfloat16* __restrict__ Ahi, const __nv_bfloat16* __restrict__ Alo,
    const __nv_bfloat16* __restrict__ Bhi, const __nv_bfloat16* __restrict__ Blo,
    const float* __restrict__ bias, float* __restrict__ C)
{
    extern __shared__ char smem[];
    const uint32_t sbase = smem_u32(smem);
    const int tid = threadIdx.x;
    const int bm = blockIdx.y * 128;
    const int bn = blockIdx.x * 128;

    const __nv_bfloat16* srcs[4] = {Ahi, Alo, Bhi, Blo};

    float acc[4][4][4];
#pragma unroll
    for (int i = 0; i < 4; i++)
#pragma unroll
        for (int j = 0; j < 4; j++)
#pragma unroll
            for (int r = 0; r < 4; r++) acc[i][j][r] = 0.f;

    gk_mainloop(srcs, bm, bn, sbase, tid, acc);

    const int wid  = tid >> 5;
    const int lane = tid & 31;
    const int warp_m = wid >> 2;
    const int warp_n = wid & 3;
    const int er = lane >> 2;
    const int ec = (lane & 3) * 2;
#pragma unroll
    for (int mi = 0; mi < 4; mi++) {
        const int row0 = bm + warp_m * 64 + mi * 16 + er;
#pragma unroll
        for (int ni = 0; ni < 4; ni++) {
            const int col = bn + warp_n * 32 + ni * 8 + ec;
            const float b0 = bias[col];
            const float b1 = bias[col + 1];
            float2 v0 = make_float2(acc[mi][ni][0] + b0, acc[mi][ni][1] + b1);
            float2 v1 = make_float2(acc[mi][ni][2] + b0, acc[mi][ni][3] + b1);
            *(float2*)(C + (size_t)row0 * DMODEL + col)       = v0;
            *(float2*)(C + (size_t)(row0 + 8) * DMODEL + col) = v1;
        }
    }
}

// ---------------------------------------------------------------------------
// Tensor-core flash attention (causal), bf16x3 MMA, fp32 softmax.
// Round-6 configuration: 2-stage cp.async K/V pipeline, 256 threads.
// ---------------------------------------------------------------------------
#define FA_PITCH   72
#define FA_ARR_B   (64 * FA_PITCH * 2)      // 9216 bytes per array
#define FA_STAGE_B (4 * FA_ARR_B)           // 36864 (khi, klo, vhi, vlo)
#define FA_SMEM    (2 * FA_STAGE_B)         // 73728

__global__ __launch_bounds__(256) void flash_mma_kernel(
    const __nv_bfloat16* __restrict__ Qhi, const __nv_bfloat16* __restrict__ Qlo,
    const __nv_bfloat16* __restrict__ Khi, const __nv_bfloat16* __restrict__ Klo,
    const __nv_bfloat16* __restrict__ Vhi, const __nv_bfloat16* __restrict__ Vlo,
    __nv_bfloat16* __restrict__ Chi, __nv_bfloat16* __restrict__ Clo)
{
    extern __shared__ char fsm[];
    const uint32_t sbase = smem_u32(fsm);

    const int tid  = threadIdx.x;
    const int wid  = tid >> 5;
    const int lane = tid & 31;
    const int qt = blockIdx.x;
    const int h  = blockIdx.y;
    const int b  = blockIdx.z;

    const int q0_tok = b * SEQ + qt * 128;
    const int qrow_w = qt * 128 + wid * 16;

    uint32_t qhi[4][4], qlo[4][4];
    {
        const __nv_bfloat16* Qh = Qhi + (size_t)(q0_tok + wid * 16) * DMODEL + h * HDIM;
        const __nv_bfloat16* Ql = Qlo + (size_t)(q0_tok + wid * 16) * DMODEL + h * HDIM;
        const __nv_bfloat162 s2 = __floats2bfloat162_rn(0.125f, 0.125f);
        const int r = lane >> 2;
        const int c = (lane & 3) * 2;
#pragma unroll
        for (int t = 0; t < 4; t++)
#pragma unroll
            for (int i = 0; i < 4; i++) {
                const int rr = r + (i & 1) * 8;
                const int cc = t * 16 + c + (i >> 1) * 8;
                __nv_bfloat162 hv = *(const __nv_bfloat162*)(Qh + (size_t)rr * DMODEL + cc);
                __nv_bfloat162 lv = *(const __nv_bfloat162*)(Ql + (size_t)rr * DMODEL + cc);
                hv = __hmul2(hv, s2);
                lv = __hmul2(lv, s2);
                qhi[t][i] = *(uint32_t*)&hv;
                qlo[t][i] = *(uint32_t*)&lv;
            }
    }

    float o[8][4];
    float m[2], l[2];
#pragma unroll
    for (int i = 0; i < 8; i++)
#pragma unroll
        for (int j = 0; j < 4; j++) o[i][j] = 0.f;
    m[0] = m[1] = -CUDART_INF_F;
    l[0] = l[1] = 0.f;

    const uint32_t k_loff = (uint32_t)(((lane & 7) + ((lane >> 4) << 3)) * (FA_PITCH * 2)
                                       + (((lane >> 3) & 1) << 4));
    const uint32_t v_loff = (uint32_t)(((lane & 7) + (((lane >> 3) & 1) << 3)) * (FA_PITCH * 2)
                                       + ((lane >> 4) << 4));

    const __nv_bfloat16* kv_srcs[4] = {
        Khi + h * HDIM, Klo + h * HDIM, Vhi + h * HDIM, Vlo + h * HDIM };

    auto load_tile = [&](int kt, int stg) {
        const size_t tok0 = (size_t)(b * SEQ + kt * 64);
        const uint32_t sb = sbase + stg * FA_STAGE_B;
#pragma unroll
        for (int t = 0; t < 4; t++) {
            const __nv_bfloat16* src = kv_srcs[t] + tok0 * DMODEL;
            const uint32_t db = sb + t * FA_ARR_B;
#pragma unroll
            for (int i = tid; i < 512; i += 256) {
                const int r  = i >> 3;
                const int c8 = i & 7;
                cp_async16(db + r * (FA_PITCH * 2) + c8 * 16,
                           src + (size_t)r * DMODEL + c8 * 8);
            }
        }
        CP_COMMIT();
    };

    const int nkt = 2 * qt + 2;

    load_tile(0, 0);

    for (int kt = 0; kt < nkt; kt++) {
        const int kb = kt * 64;
        const int stg = kt & 1;
        CP_WAIT(0);
        __syncthreads();
        if (kt + 1 < nkt) load_tile(kt + 1, stg ^ 1);

        if (kb > qrow_w + 15) continue;

        const uint32_t ks_hi_b = sbase + stg * FA_STAGE_B;
        const uint32_t ks_lo_b = ks_hi_b + FA_ARR_B;
        const uint32_t vs_hi_b = ks_hi_b + 2 * FA_ARR_B;
        const uint32_t vs_lo_b = ks_hi_b + 3 * FA_ARR_B;

        // ---- S = Q K^T (bf16x3), warp tile 16 x 64 ----
        float s[8][4];
#pragma unroll
        for (int i = 0; i < 8; i++)
#pragma unroll
            for (int j = 0; j < 4; j++) s[i][j] = 0.f;

#pragma unroll
        for (int t = 0; t < 4; t++) {
#pragma unroll
            for (int pp = 0; pp < 4; pp++) {
                const uint32_t ro = (uint32_t)(pp * 16 * (FA_PITCH * 2) + t * 32) + k_loff;
                uint32_t kh[4], kl[4];
                ldsm_x4(kh, ks_hi_b + ro);
                ldsm_x4(kl, ks_lo_b + ro);
                mma_bf16(s[2 * pp],     qhi[t], kh[0], kh[1]);
                mma_bf16(s[2 * pp],     qhi[t], kl[0], kl[1]);
                mma_bf16(s[2 * pp],     qlo[t], kh[0], kh[1]);
                mma_bf16(s[2 * pp + 1], qhi[t], kh[2], kh[3]);
                mma_bf16(s[2 * pp + 1], qhi[t], kl[2], kl[3]);
                mma_bf16(s[2 * pp + 1], qlo[t], kh[2], kh[3]);
            }
        }

        // ---- causal mask ----
        const int row_g0 = qrow_w + (lane >> 2);
        if (kb + 63 > qrow_w) {
#pragma unroll
            for (int nt = 0; nt < 8; nt++) {
                const int colb = kb + nt * 8 + (lane & 3) * 2;
#pragma unroll
                for (int i = 0; i < 4; i++) {
                    const int row = row_g0 + (i >> 1) * 8;
                    const int col = colb + (i & 1);
                    if (col > row) s[nt][i] = -CUDART_INF_F;
                }
            }
        }

        // ---- online softmax ----
        float rmax[2];
        rmax[0] = rmax[1] = -CUDART_INF_F;
#pragma unroll
        for (int nt = 0; nt < 8; nt++) {
            rmax[0] = fmaxf(rmax[0], fmaxf(s[nt][0], s[nt][1]));
            rmax[1] = fmaxf(rmax[1], fmaxf(s[nt][2], s[nt][3]));
        }
#pragma unroll
        for (int off = 1; off <= 2; off <<= 1) {
            rmax[0] = fmaxf(rmax[0], __shfl_xor_sync(0xffffffffu, rmax[0], off));
            rmax[1] = fmaxf(rmax[1], __shfl_xor_sync(0xffffffffu, rmax[1], off));
        }

        float alpha[2], rsum[2];
#pragma unroll
        for (int i = 0; i < 2; i++) {
            float mn = fmaxf(m[i], rmax[i]);
            alpha[i] = exp2f((m[i] - mn) * LOG2E);
            m[i] = mn;
            rsum[i] = 0.f;
        }

#pragma unroll
        for (int nt = 0; nt < 8; nt++) {
            s[nt][0] = exp2f((s[nt][0] - m[0]) * LOG2E);
            s[nt][1] = exp2f((s[nt][1] - m[0]) * LOG2E);
            s[nt][2] = exp2f((s[nt][2] - m[1]) * LOG2E);
            s[nt][3] = exp2f((s[nt][3] - m[1]) * LOG2E);
            rsum[0] += s[nt][0] + s[nt][1];
            rsum[1] += s[nt][2] + s[nt][3];
        }
#pragma unroll
        for (int off = 1; off <= 2; off <<= 1) {
            rsum[0] += __shfl_xor_sync(0xffffffffu, rsum[0], off);
            rsum[1] += __shfl_xor_sync(0xffffffffu, rsum[1], off);
        }
        l[0] = l[0] * alpha[0] + rsum[0];
        l[1] = l[1] * alpha[1] + rsum[1];
#pragma unroll
        for (int nt = 0; nt < 8; nt++) {
            o[nt][0] *= alpha[0]; o[nt][1] *= alpha[0];
            o[nt][2] *= alpha[1]; o[nt][3] *= alpha[1];
        }

        // ---- O += P V (bf16x3) ----
#pragma unroll
        for (int t = 0; t < 4; t++) {
            uint32_t ahi[4], alo[4];
            {
                float x0 = s[2 * t][0],     x1 = s[2 * t][1];
                float x2 = s[2 * t][2],     x3 = s[2 * t][3];
                float y0 = s[2 * t + 1][0], y1 = s[2 * t + 1][1];
                float y2 = s[2 * t + 1][2], y3 = s[2 * t + 1][3];
                float hx0 = __bfloat162float(__float2bfloat16(x0));
                float hx1 = __bfloat162float(__float2bfloat16(x1));
                float hx2 = __bfloat162float(__float2bfloat16(x2));
                float hx3 = __bfloat162float(__float2bfloat16(x3));
                float hy0 = __bfloat162float(__float2bfloat16(y0));
                float hy1 = __bfloat162float(__float2bfloat16(y1));
                float hy2 = __bfloat162float(__float2bfloat16(y2));
                float hy3 = __bfloat162float(__float2bfloat16(y3));
                ahi[0] = pack_bf16(x0, x1);  alo[0] = pack_bf16(x0 - hx0, x1 - hx1);
                ahi[1] = pack_bf16(x2, x3);  alo[1] = pack_bf16(x2 - hx2, x3 - hx3);
                ahi[2] = pack_bf16(y0, y1);  alo[2] = pack_bf16(y0 - hy0, y1 - hy1);
                ahi[3] = pack_bf16(y2, y3);  alo[3] = pack_bf16(y2 - hy2, y3 - hy3);
            }
#pragma unroll
            for (int dp = 0; dp < 4; dp++) {
                const uint32_t ro = (uint32_t)(t * 16 * (FA_PITCH * 2) + dp * 32) + v_loff;
                uint32_t bh[4], bl[4];
                ldsm_x4_trans(bh, vs_hi_b + ro);
                ldsm_x4_trans(bl, vs_lo_b + ro);
                mma_bf16(o[2 * dp],     ahi, bh[0], bh[1]);
                mma_bf16(o[2 * dp],     ahi, bl[0], bl[1]);
                mma_bf16(o[2 * dp],     alo, bh[0], bh[1]);
                mma_bf16(o[2 * dp + 1], ahi, bh[2], bh[3]);
                mma_bf16(o[2 * dp + 1], ahi, bl[2], bl[3]);
                mma_bf16(o[2 * dp + 1], alo, bh[2], bh[3]);
            }
        }
    }

    // ---- epilogue: normalize, split to hi/lo, store ctx ----
    const float inv0 = 1.f / l[0];
    const float inv1 = 1.f / l[1];
    const int orow = q0_tok + wid * 16 + (lane >> 2);
    const int colb = h * HDIM + (lane & 3) * 2;
#pragma unroll
    for (int nt = 0; nt < 8; nt++) {
        const int col = colb + nt * 8;
        float v00 = o[nt][0] * inv0, v01 = o[nt][1] * inv0;
        float v10 = o[nt][2] * inv1, v11 = o[nt][3] * inv1;
        float h00 = __bfloat162float(__float2bfloat16(v00));
        float h01 = __bfloat162float(__float2bfloat16(v01));
        float h10 = __bfloat162float(__float2bfloat16(v10));
        float h11 = __bfloat162float(__float2bfloat16(v11));
        *(uint32_t*)(Chi + (size_t)orow * DMODEL + col)       = pack_bf16(v00, v01);
        *(uint32_t*)(Clo + (size_t)orow * DMODEL + col)       = pack_bf16(v00 - h00, v01 - h01);
        *(uint32_t*)(Chi + (size_t)(orow + 8) * DMODEL + col) = pack_bf16(v10, v11);
        *(uint32_t*)(Clo + (size_t)(orow + 8) * DMODEL + col) = pack_bf16(v10 - h10, v11 - h11);
    }
}

// ---------------------------------------------------------------------------
// Launch
// ---------------------------------------------------------------------------
extern "C" void kernel_launch(void* const* d_in, const int* in_sizes, int n_in,
                              void* d_out, int out_size)
{
    const float* x  = (const float*)d_in[0];
    const float* wq = (const float*)d_in[1];
    const float* wk = (const float*)d_in[2];
    const float* wv = (const float*)d_in[3];
    const float* wo = (const float*)d_in[4];
    const float* bo = (const float*)d_in[5];
    float* out = (float*)d_out;

    __nv_bfloat16 *xhi, *xlo, *qhi, *qlo, *khi, *klo, *vhi, *vlo, *chi, *clo;
    __nv_bfloat16 *wqhi, *wqlo, *wkhi, *wklo, *wvhi, *wvlo, *wohi, *wolo;
    cudaGetSymbolAddress((void**)&xhi,  g_xhi);
    cudaGetSymbolAddress((void**)&xlo,  g_xlo);
    cudaGetSymbolAddress((void**)&qhi,  g_qhi);
    cudaGetSymbolAddress((void**)&qlo,  g_qlo);
    cudaGetSymbolAddress((void**)&khi,  g_khi);
    cudaGetSymbolAddress((void**)&klo,  g_klo);
    cudaGetSymbolAddress((void**)&vhi,  g_vhi);
    cudaGetSymbolAddress((void**)&vlo,  g_vlo);
    cudaGetSymbolAddress((void**)&chi,  g_chi);
    cudaGetSymbolAddress((void**)&clo,  g_clo);
    cudaGetSymbolAddress((void**)&wqhi, g_wqhi);
    cudaGetSymbolAddress((void**)&wqlo, g_wqlo);
    cudaGetSymbolAddress((void**)&wkhi, g_wkhi);
    cudaGetSymbolAddress((void**)&wklo, g_wklo);
    cudaGetSymbolAddress((void**)&wvhi, g_wvhi);
    cudaGetSymbolAddress((void**)&wvlo, g_wvlo);
    cudaGetSymbolAddress((void**)&wohi, g_wohi);
    cudaGetSymbolAddress((void**)&wolo, g_wolo);

    const int nx = TOKENS * DMODEL;
    const int nw = DMODEL * DMODEL;

    split_bf16_kernel<<<nx / 4 / 256, 256>>>(x,  xhi,  xlo,  nx);
    split_bf16_kernel<<<nw / 4 / 256, 256>>>(wq, wqhi, wqlo, nw);
    split_bf16_kernel<<<nw / 4 / 256, 256>>>(wk, wkhi, wklo, nw);
    split_bf16_kernel<<<nw / 4 / 256, 256>>>(wv, wvhi, wvlo, nw);
    split_bf16_kernel<<<nw / 4 / 256, 256>>>(wo, wohi, wolo, nw);

    cudaFuncSetAttribute(gemm_qkv,
                         cudaFuncAttributeMaxDynamicSharedMemorySize, GK_SMEM);
    cudaFuncSetAttribute(gemm_out,
                         cudaFuncAttributeMaxDynamicSharedMemorySize, GK_SMEM);

    gemm_qkv<<<dim3(DMODEL / 128, TOKENS / 128, 3), 256, GK_SMEM>>>(
        xhi, xlo, wqhi, wqlo, wkhi, wklo, wvhi, wvlo,
        qhi, qlo, khi, klo, vhi, vlo);

    cudaFuncSetAttribute(flash_mma_kernel,
                         cudaFuncAttributeMaxDynamicSharedMemorySize, FA_SMEM);
    flash_mma_kernel<<<dim3(SEQ / 128, NHEADS, BATCH), 256, FA_SMEM>>>(
        qhi, qlo, khi, klo, vhi, vlo, chi, clo);

    gemm_out<<<dim3(DMODEL / 128, TOKENS / 128), 256, GK_SMEM>>>(
        chi, clo, wohi, wolo, bo, out);
}

// round 9
// speedup vs baseline: 1.1318x; 1.0378x over previous
#include <cuda_runtime.h>
#include <cuda_bf16.h>
#include <math_constants.h>
#include <cstdint>

// Problem constants
#define BATCH   4
#define SEQ     2048
#define DMODEL  1024
#define NHEADS  16
#define HDIM    64
#define TOKENS  (BATCH * SEQ)   // 8192

#define LOG2E 1.4426950408889634f
#define SCL2E (0.125f * LOG2E)   // softmax scale folded into exponent

// ---------------------------------------------------------------------------
// Scratch (allocation-free rule: __device__ globals)
// ---------------------------------------------------------------------------
__device__ __nv_bfloat16 g_xhi[TOKENS * DMODEL];
__device__ __nv_bfloat16 g_xlo[TOKENS * DMODEL];
__device__ __nv_bfloat16 g_qhi[TOKENS * DMODEL];
__device__ __nv_bfloat16 g_qlo[TOKENS * DMODEL];
__device__ __nv_bfloat16 g_khi[TOKENS * DMODEL];
__device__ __nv_bfloat16 g_klo[TOKENS * DMODEL];
__device__ __nv_bfloat16 g_vhi[TOKENS * DMODEL];
__device__ __nv_bfloat16 g_vlo[TOKENS * DMODEL];
__device__ __nv_bfloat16 g_chi[TOKENS * DMODEL];
__device__ __nv_bfloat16 g_clo[TOKENS * DMODEL];
__device__ __nv_bfloat16 g_wqhi[DMODEL * DMODEL];
__device__ __nv_bfloat16 g_wqlo[DMODEL * DMODEL];
__device__ __nv_bfloat16 g_wkhi[DMODEL * DMODEL];
__device__ __nv_bfloat16 g_wklo[DMODEL * DMODEL];
__device__ __nv_bfloat16 g_wvhi[DMODEL * DMODEL];
__device__ __nv_bfloat16 g_wvlo[DMODEL * DMODEL];
__device__ __nv_bfloat16 g_wohi[DMODEL * DMODEL];
__device__ __nv_bfloat16 g_wolo[DMODEL * DMODEL];

// ---------------------------------------------------------------------------
// PTX helpers (sm_80-baseline only: cp.async, ldmatrix, mma.sync)
// ---------------------------------------------------------------------------
__device__ __forceinline__ uint32_t smem_u32(const void* p) {
    uint32_t a;
    asm("{ .reg .u64 t; cvta.to.shared.u64 t, %1; cvt.u32.u64 %0, t; }"
        : "=r"(a) : "l"(p));
    return a;
}

__device__ __forceinline__ void cp_async16(uint32_t smem, const void* gmem) {
    asm volatile("cp.async.cg.shared.global [%0], [%1], 16;\n"
                 :: "r"(smem), "l"(gmem));
}
#define CP_COMMIT() asm volatile("cp.async.commit_group;\n" ::: "memory")
#define CP_WAIT(n)  asm volatile("cp.async.wait_group %0;\n" :: "n"(n) : "memory")

__device__ __forceinline__ void ldsm_x4(uint32_t* r, uint32_t addr) {
    asm volatile("ldmatrix.sync.aligned.m8n8.x4.shared.b16 {%0,%1,%2,%3}, [%4];"
                 : "=r"(r[0]), "=r"(r[1]), "=r"(r[2]), "=r"(r[3]) : "r"(addr));
}

__device__ __forceinline__ void ldsm_x4_trans(uint32_t* r, uint32_t addr) {
    asm volatile("ldmatrix.sync.aligned.m8n8.x4.trans.shared.b16 {%0,%1,%2,%3}, [%4];"
                 : "=r"(r[0]), "=r"(r[1]), "=r"(r[2]), "=r"(r[3]) : "r"(addr));
}

__device__ __forceinline__ void mma_bf16(float* c, const uint32_t* a,
                                         uint32_t b0, uint32_t b1) {
    asm volatile(
        "mma.sync.aligned.m16n8k16.row.col.f32.bf16.bf16.f32 "
        "{%0,%1,%2,%3}, {%4,%5,%6,%7}, {%8,%9}, {%0,%1,%2,%3};"
        : "+f"(c[0]), "+f"(c[1]), "+f"(c[2]), "+f"(c[3])
        : "r"(a[0]), "r"(a[1]), "r"(a[2]), "r"(a[3]), "r"(b0), "r"(b1));
}

__device__ __forceinline__ uint32_t pack_bf16(float x, float y) {
    __nv_bfloat162 t = __floats2bfloat162_rn(x, y);
    return *(uint32_t*)&t;
}

// ---------------------------------------------------------------------------
// Split fp32 -> (bf16 hi, bf16 lo).
// ---------------------------------------------------------------------------
__device__ __forceinline__ void split4(const float* __restrict__ in,
                                       __nv_bfloat16* __restrict__ hi,
                                       __nv_bfloat16* __restrict__ lo, int i)
{
    float4 v = *(const float4*)(in + i);
    __nv_bfloat16 h0 = __float2bfloat16(v.x);
    __nv_bfloat16 h1 = __float2bfloat16(v.y);
    __nv_bfloat16 h2 = __float2bfloat16(v.z);
    __nv_bfloat16 h3 = __float2bfloat16(v.w);
    __nv_bfloat16 l0 = __float2bfloat16(v.x - __bfloat162float(h0));
    __nv_bfloat16 l1 = __float2bfloat16(v.y - __bfloat162float(h1));
    __nv_bfloat16 l2 = __float2bfloat16(v.z - __bfloat162float(h2));
    __nv_bfloat16 l3 = __float2bfloat16(v.w - __bfloat162float(h3));
    ((__nv_bfloat162*)(hi + i))[0] = __nv_bfloat162(h0, h1);
    ((__nv_bfloat162*)(hi + i))[1] = __nv_bfloat162(h2, h3);
    ((__nv_bfloat162*)(lo + i))[0] = __nv_bfloat162(l0, l1);
    ((__nv_bfloat162*)(lo + i))[1] = __nv_bfloat162(l2, l3);
}

__global__ void split_bf16_kernel(const float* __restrict__ in,
                                  __nv_bfloat16* __restrict__ hi,
                                  __nv_bfloat16* __restrict__ lo, int n)
{
    int i = (blockIdx.x * blockDim.x + threadIdx.x) * 4;
    if (i < n) split4(in, hi, lo, i);
}

// Fused 4-weight split: blockIdx.y selects the weight.
__global__ void split_w4_kernel(
    const float* __restrict__ w0, const float* __restrict__ w1,
    const float* __restrict__ w2, const float* __restrict__ w3,
    __nv_bfloat16* __restrict__ h0, __nv_bfloat16* __restrict__ l0,
    __nv_bfloat16* __restrict__ h1, __nv_bfloat16* __restrict__ l1,
    __nv_bfloat16* __restrict__ h2, __nv_bfloat16* __restrict__ l2,
    __nv_bfloat16* __restrict__ h3, __nv_bfloat16* __restrict__ l3)
{
    const float* in;
    __nv_bfloat16 *hi, *lo;
    switch (blockIdx.y) {
        case 0:  in = w0; hi = h0; lo = l0; break;
        case 1:  in = w1; hi = h1; lo = l1; break;
        case 2:  in = w2; hi = h2; lo = l2; break;
        default: in = w3; hi = h3; lo = l3; break;
    }
    int i = (blockIdx.x * blockDim.x + threadIdx.x) * 4;
    if (i < DMODEL * DMODEL) split4(in, hi, lo, i);
}

// ---------------------------------------------------------------------------
// GEMM core (round-8 config, known good): CTA 128x128, BK=32, 256 threads
// (8 warps, 2x4), warp tile 64x32, 2-stage cp.async, launch_bounds(256,2).
// ---------------------------------------------------------------------------
#define GK_BK       32
#define GK_ROW_B    80
#define GK_TILE_B   (128 * GK_ROW_B)
#define GK_STAGE_B  (4 * GK_TILE_B)            // 40960
#define GK_STAGES   2
#define GK_SMEM     (GK_STAGES * GK_STAGE_B)   // 81920
#define GK_NCHUNKS  (DMODEL / GK_BK)           // 32

__device__ __forceinline__ void gk_load_chunk(
    const __nv_bfloat16* const* srcs, int bm, int bn, int c, int st,
    uint32_t sbase, int tid)
{
    const int k0 = c * GK_BK;
#pragma unroll
    for (int t = 0; t < 4; t++) {
        const __nv_bfloat16* src = srcs[t];
        const int rbase = (t < 2) ? bm : bn;
        const uint32_t tb = sbase + st * GK_STAGE_B + t * GK_TILE_B;
#pragma unroll
        for (int i = tid; i < 512; i += 256) {
            const int r = i >> 2;
            const int q = i & 3;
            cp_async16(tb + r * GK_ROW_B + q * 16,
                       src + (size_t)(rbase + r) * DMODEL + k0 + q * 8);
        }
    }
    CP_COMMIT();
}

__device__ __forceinline__ void gk_mainloop(
    const __nv_bfloat16* const* srcs, int bm, int bn,
    uint32_t sbase, int tid, float acc[4][4][4])
{
    const int wid  = tid >> 5;
    const int lane = tid & 31;
    const int warp_m = wid >> 2;
    const int warp_n = wid & 3;

    gk_load_chunk(srcs, bm, bn, 0, 0, sbase, tid);

    const uint32_t lrow16 = (uint32_t)(lane & 15);
    const uint32_t lcolb  = (uint32_t)((lane >> 4) << 4);

    for (int c = 0; c < GK_NCHUNKS; c++) {
        const int st = c & 1;
        CP_WAIT(0);
        __syncthreads();
        if (c + 1 < GK_NCHUNKS)
            gk_load_chunk(srcs, bm, bn, c + 1, (c + 1) & 1, sbase, tid);

        const uint32_t stg = sbase + st * GK_STAGE_B;
        const uint32_t a_r = (uint32_t)(warp_m * 64) + lrow16;
        const uint32_t b_r = (uint32_t)(warp_n * 32) + lrow16;

#pragma unroll
        for (int ks = 0; ks < 2; ks++) {
            const uint32_t kb = lcolb + ks * 32;
            uint32_t ah[4][4], al[4][4], bh[2][4], bl[2][4];
#pragma unroll
            for (int mi = 0; mi < 4; mi++) {
                uint32_t ro = (a_r + mi * 16) * GK_ROW_B + kb;
                ldsm_x4(ah[mi], stg + 0 * GK_TILE_B + ro);
                ldsm_x4(al[mi], stg + 1 * GK_TILE_B + ro);
            }
#pragma unroll
            for (int p = 0; p < 2; p++) {
                uint32_t ro = (b_r + p * 16) * GK_ROW_B + kb;
                ldsm_x4(bh[p], stg + 2 * GK_TILE_B + ro);
                ldsm_x4(bl[p], stg + 3 * GK_TILE_B + ro);
            }
#pragma unroll
            for (int mi = 0; mi < 4; mi++)
#pragma unroll
                for (int ni = 0; ni < 4; ni++) {
                    const int p = ni >> 1, s = ni & 1;
                    mma_bf16(acc[mi][ni], ah[mi], bh[p][s], bh[p][s + 2]);
                    mma_bf16(acc[mi][ni], ah[mi], bl[p][s], bl[p][s + 2]);
                    mma_bf16(acc[mi][ni], al[mi], bh[p][s], bh[p][s + 2]);
                }
        }
        __syncthreads();
    }
}

// ---------------------------------------------------------------------------
// Fused QKV projection: grid.z in {0,1,2}. Output: bf16 hi/lo split.
// ---------------------------------------------------------------------------
__global__ __launch_bounds__(256, 2) void gemm_qkv(
    const __nv_bfloat16* __restrict__ xhi, const __nv_bfloat16* __restrict__ xlo,
    const __nv_bfloat16* __restrict__ wqhi, const __nv_bfloat16* __restrict__ wqlo,
    const __nv_bfloat16* __restrict__ wkhi, const __nv_bfloat16* __restrict__ wklo,
    const __nv_bfloat16* __restrict__ wvhi, const __nv_bfloat16* __restrict__ wvlo,
    __nv_bfloat16* __restrict__ qhi, __nv_bfloat16* __restrict__ qlo,
    __nv_bfloat16* __restrict__ khi, __nv_bfloat16* __restrict__ klo,
    __nv_bfloat16* __restrict__ vhi, __nv_bfloat16* __restrict__ vlo)
{
    extern __shared__ char smem[];
    const uint32_t sbase = smem_u32(smem);
    const int tid = threadIdx.x;
    const int bm = blockIdx.y * 128;
    const int bn = blockIdx.x * 128;

    const __nv_bfloat16 *Bhi, *Blo;
    __nv_bfloat16 *Chi, *Clo;
    if (blockIdx.z == 0)      { Bhi = wqhi; Blo = wqlo; Chi = qhi; Clo = qlo; }
    else if (blockIdx.z == 1) { Bhi = wkhi; Blo = wklo; Chi = khi; Clo = klo; }
    else                      { Bhi = wvhi; Blo = wvlo; Chi = vhi; Clo = vlo; }

    const __nv_bfloat16* srcs[4] = {xhi, xlo, Bhi, Blo};

    float acc[4][4][4];
#pragma unroll
    for (int i = 0; i < 4; i++)
#pragma unroll
        for (int j = 0; j < 4; j++)
#pragma unroll
            for (int r = 0; r < 4; r++) acc[i][j][r] = 0.f;

    gk_mainloop(srcs, bm, bn, sbase, tid, acc);

    const int wid  = tid >> 5;
    const int lane = tid & 31;
    const int warp_m = wid >> 2;
    const int warp_n = wid & 3;
    const int er = lane >> 2;
    const int ec = (lane & 3) * 2;
#pragma unroll
    for (int mi = 0; mi < 4; mi++) {
        const int row0 = bm + warp_m * 64 + mi * 16 + er;
#pragma unroll
        for (int ni = 0; ni < 4; ni++) {
            const int col = bn + warp_n * 32 + ni * 8 + ec;
            float a0 = acc[mi][ni][0], a1 = acc[mi][ni][1];
            float a2 = acc[mi][ni][2], a3 = acc[mi][ni][3];
            float h0 = __bfloat162float(__float2bfloat16(a0));
            float h1 = __bfloat162float(__float2bfloat16(a1));
            float h2 = __bfloat162float(__float2bfloat16(a2));
            float h3 = __bfloat162float(__float2bfloat16(a3));
            *(uint32_t*)(Chi + (size_t)row0 * DMODEL + col)       = pack_bf16(a0, a1);
            *(uint32_t*)(Clo + (size_t)row0 * DMODEL + col)       = pack_bf16(a0 - h0, a1 - h1);
            *(uint32_t*)(Chi + (size_t)(row0 + 8) * DMODEL + col) = pack_bf16(a2, a3);
            *(uint32_t*)(Clo + (size_t)(row0 + 8) * DMODEL + col) = pack_bf16(a2 - h2, a3 - h3);
        }
    }
}

// ---------------------------------------------------------------------------
// Output projection: fp32 out + bias.
// ---------------------------------------------------------------------------
__global__ __launch_bounds__(256, 2) void gemm_out(
    const __nv_bfloat16* __restrict__ Ahi, const __nv_bfloat16* __restrict__ Alo,
    const __nv_bfloat16* __restrict__ Bhi, const __nv_bfloat16* __restrict__ Blo,
    const float* __restrict__ bias, float* __restrict__ C)
{
    extern __shared__ char smem[];
    const uint32_t sbase = smem_u32(smem);
    const int tid = threadIdx.x;
    const int bm = blockIdx.y * 128;
    const int bn = blockIdx.x * 128;

    const __nv_bfloat16* srcs[4] = {Ahi, Alo, Bhi, Blo};

    float acc[4][4][4];
#pragma unroll
    for (int i = 0; i < 4; i++)
#pragma unroll
        for (int j = 0; j < 4; j++)
#pragma unroll
            for (int r = 0; r < 4; r++) acc[i][j][r] = 0.f;

    gk_mainloop(srcs, bm, bn, sbase, tid, acc);

    const int wid  = tid >> 5;
    const int lane = tid & 31;
    const int warp_m = wid >> 2;
    const int warp_n = wid & 3;
    const int er = lane >> 2;
    const int ec = (lane & 3) * 2;
#pragma unroll
    for (int mi = 0; mi < 4; mi++) {
        const int row0 = bm + warp_m * 64 + mi * 16 + er;
#pragma unroll
        for (int ni = 0; ni < 4; ni++) {
            const int col = bn + warp_n * 32 + ni * 8 + ec;
            const float b0 = bias[col];
            const float b1 = bias[col + 1];
            float2 v0 = make_float2(acc[mi][ni][0] + b0, acc[mi][ni][1] + b1);
            float2 v1 = make_float2(acc[mi][ni][2] + b0, acc[mi][ni][3] + b1);
            *(float2*)(C + (size_t)row0 * DMODEL + col)       = v0;
            *(float2*)(C + (size_t)(row0 + 8) * DMODEL + col) = v1;
        }
    }
}

// ---------------------------------------------------------------------------
// Tensor-core flash attention v2 (causal), bf16x3 MMA, fp32 softmax.
// Q kept in SMEM (hi/lo), re-fetched per tile via ldmatrix -> ~110 live regs,
// launch_bounds(256,2) -> 2 CTAs/SM. Softmax scale folded into exp constant.
// SMEM: Q hi/lo 2x18432 + 2 KV stages x 36864 = 110592 B.
// ---------------------------------------------------------------------------
#define FA_PITCH   72
#define FA_ROW_B   (FA_PITCH * 2)           // 144
#define FA_Q_ARR_B (128 * FA_ROW_B)         // 18432 per Q array
#define FA_ARR_B   (64 * FA_ROW_B)          // 9216 per KV array
#define FA_STAGE_B (4 * FA_ARR_B)           // 36864
#define FA_KV_OFF  (2 * FA_Q_ARR_B)         // 36864
#define FA_SMEM    (FA_KV_OFF + 2 * FA_STAGE_B)  // 110592

__global__ __launch_bounds__(256, 2) void flash_mma_kernel(
    const __nv_bfloat16* __restrict__ Qhi, const __nv_bfloat16* __restrict__ Qlo,
    const __nv_bfloat16* __restrict__ Khi, const __nv_bfloat16* __restrict__ Klo,
    const __nv_bfloat16* __restrict__ Vhi, const __nv_bfloat16* __restrict__ Vlo,
    __nv_bfloat16* __restrict__ Chi, __nv_bfloat16* __restrict__ Clo)
{
    extern __shared__ char fsm[];
    const uint32_t sbase = smem_u32(fsm);

    const int tid  = threadIdx.x;
    const int wid  = tid >> 5;
    const int lane = tid & 31;
    const int qt = blockIdx.x;
    const int h  = blockIdx.y;
    const int b  = blockIdx.z;

    const int q0_tok = b * SEQ + qt * 128;
    const int qrow_w = qt * 128 + wid * 16;

    // ---- load Q tile (128 rows x 64 cols, hi+lo) into SMEM ----
    {
        const __nv_bfloat16* Qh = Qhi + (size_t)q0_tok * DMODEL + h * HDIM;
        const __nv_bfloat16* Ql = Qlo + (size_t)q0_tok * DMODEL + h * HDIM;
#pragma unroll
        for (int i = tid; i < 1024; i += 256) {
            const int r  = i >> 3;
            const int c8 = i & 7;
            cp_async16(sbase + r * FA_ROW_B + c8 * 16,
                       Qh + (size_t)r * DMODEL + c8 * 8);
            cp_async16(sbase + FA_Q_ARR_B + r * FA_ROW_B + c8 * 16,
                       Ql + (size_t)r * DMODEL + c8 * 8);
        }
        CP_COMMIT();
    }

    float o[8][4];
    float m[2], l[2];
#pragma unroll
    for (int i = 0; i < 8; i++)
#pragma unroll
        for (int j = 0; j < 4; j++) o[i][j] = 0.f;
    m[0] = m[1] = -CUDART_INF_F;
    l[0] = l[1] = 0.f;

    // ldmatrix lane offsets (bytes)
    const uint32_t a_loff = (uint32_t)((lane & 15) * FA_ROW_B + ((lane >> 4) << 4));
    const uint32_t k_loff = (uint32_t)(((lane & 7) + ((lane >> 4) << 3)) * FA_ROW_B
                                       + (((lane >> 3) & 1) << 4));
    const uint32_t v_loff = (uint32_t)(((lane & 7) + (((lane >> 3) & 1) << 3)) * FA_ROW_B
                                       + ((lane >> 4) << 4));

    const uint32_t q_hi_w = sbase + (uint32_t)(wid * 16) * FA_ROW_B + a_loff;
    const uint32_t q_lo_w = q_hi_w + FA_Q_ARR_B;

    const __nv_bfloat16* kv_srcs[4] = {
        Khi + h * HDIM, Klo + h * HDIM, Vhi + h * HDIM, Vlo + h * HDIM };

    auto load_tile = [&](int kt, int stg) {
        const size_t tok0 = (size_t)(b * SEQ + kt * 64);
        const uint32_t sb = sbase + FA_KV_OFF + stg * FA_STAGE_B;
#pragma unroll
        for (int t = 0; t < 4; t++) {
            const __nv_bfloat16* src = kv_srcs[t] + tok0 * DMODEL;
            const uint32_t db = sb + t * FA_ARR_B;
#pragma unroll
            for (int i = tid; i < 512; i += 256) {
                const int r  = i >> 3;
                const int c8 = i & 7;
                cp_async16(db + r * FA_ROW_B + c8 * 16,
                           src + (size_t)r * DMODEL + c8 * 8);
            }
        }
        CP_COMMIT();
    };

    const int nkt = 2 * qt + 2;

    load_tile(0, 0);

    for (int kt = 0; kt < nkt; kt++) {
        const int kb = kt * 64;
        const int stg = kt & 1;
        CP_WAIT(0);
        __syncthreads();
        if (kt + 1 < nkt) load_tile(kt + 1, stg ^ 1);

        if (kb > qrow_w + 15) continue;

        const uint32_t ks_hi_b = sbase + FA_KV_OFF + stg * FA_STAGE_B;
        const uint32_t ks_lo_b = ks_hi_b + FA_ARR_B;
        const uint32_t vs_hi_b = ks_hi_b + 2 * FA_ARR_B;
        const uint32_t vs_lo_b = ks_hi_b + 3 * FA_ARR_B;

        // ---- S = Q K^T (bf16x3), warp tile 16 x 64; Q frags from SMEM ----
        float s[8][4];
#pragma unroll
        for (int i = 0; i < 8; i++)
#pragma unroll
            for (int j = 0; j < 4; j++) s[i][j] = 0.f;

#pragma unroll
        for (int t = 0; t < 4; t++) {
            uint32_t qh4[4], ql4[4];
            ldsm_x4(qh4, q_hi_w + t * 32);
            ldsm_x4(ql4, q_lo_w + t * 32);
#pragma unroll
            for (int pp = 0; pp < 4; pp++) {
                const uint32_t ro = (uint32_t)(pp * 16 * FA_ROW_B + t * 32) + k_loff;
                uint32_t kh[4], kl[4];
                ldsm_x4(kh, ks_hi_b + ro);
                ldsm_x4(kl, ks_lo_b + ro);
                mma_bf16(s[2 * pp],     qh4, kh[0], kh[1]);
                mma_bf16(s[2 * pp],     qh4, kl[0], kl[1]);
                mma_bf16(s[2 * pp],     ql4, kh[0], kh[1]);
                mma_bf16(s[2 * pp + 1], qh4, kh[2], kh[3]);
                mma_bf16(s[2 * pp + 1], qh4, kl[2], kl[3]);
                mma_bf16(s[2 * pp + 1], ql4, kh[2], kh[3]);
            }
        }

        // ---- causal mask (raw scores; scale folded into exp) ----
        const int row_g0 = qrow_w + (lane >> 2);
        if (kb + 63 > qrow_w) {
#pragma unroll
            for (int nt = 0; nt < 8; nt++) {
                const int colb = kb + nt * 8 + (lane & 3) * 2;
#pragma unroll
                for (int i = 0; i < 4; i++) {
                    const int row = row_g0 + (i >> 1) * 8;
                    const int col = colb + (i & 1);
                    if (col > row) s[nt][i] = -CUDART_INF_F;
                }
            }
        }

        // ---- online softmax (on raw scores, exponent scaled by SCL2E) ----
        float rmax[2];
        rmax[0] = rmax[1] = -CUDART_INF_F;
#pragma unroll
        for (int nt = 0; nt < 8; nt++) {
            rmax[0] = fmaxf(rmax[0], fmaxf(s[nt][0], s[nt][1]));
            rmax[1] = fmaxf(rmax[1], fmaxf(s[nt][2], s[nt][3]));
        }
#pragma unroll
        for (int off = 1; off <= 2; off <<= 1) {
            rmax[0] = fmaxf(rmax[0], __shfl_xor_sync(0xffffffffu, rmax[0], off));
            rmax[1] = fmaxf(rmax[1], __shfl_xor_sync(0xffffffffu, rmax[1], off));
        }

        float alpha[2], rsum[2];
#pragma unroll
        for (int i = 0; i < 2; i++) {
            float mn = fmaxf(m[i], rmax[i]);
            alpha[i] = exp2f((m[i] - mn) * SCL2E);
            m[i] = mn;
            rsum[i] = 0.f;
        }

#pragma unroll
        for (int nt = 0; nt < 8; nt++) {
            s[nt][0] = exp2f((s[nt][0] - m[0]) * SCL2E);
            s[nt][1] = exp2f((s[nt][1] - m[0]) * SCL2E);
            s[nt][2] = exp2f((s[nt][2] - m[1]) * SCL2E);
            s[nt][3] = exp2f((s[nt][3] - m[1]) * SCL2E);
            rsum[0] += s[nt][0] + s[nt][1];
            rsum[1] += s[nt][2] + s[nt][3];
        }
#pragma unroll
        for (int off = 1; off <= 2; off <<= 1) {
            rsum[0] += __shfl_xor_sync(0xffffffffu, rsum[0], off);
            rsum[1] += __shfl_xor_sync(0xffffffffu, rsum[1], off);
        }
        l[0] = l[0] * alpha[0] + rsum[0];
        l[1] = l[1] * alpha[1] + rsum[1];
#pragma unroll
        for (int nt = 0; nt < 8; nt++) {
            o[nt][0] *= alpha[0]; o[nt][1] *= alpha[0];
            o[nt][2] *= alpha[1]; o[nt][3] *= alpha[1];
        }

        // ---- O += P V (bf16x3); P C-frags -> A-frags in registers ----
#pragma unroll
        for (int t = 0; t < 4; t++) {
            uint32_t ahi[4], alo[4];
            {
                float x0 = s[2 * t][0],     x1 = s[2 * t][1];
                float x2 = s[2 * t][2],     x3 = s[2 * t][3];
                float y0 = s[2 * t + 1][0], y1 = s[2 * t + 1][1];
                float y2 = s[2 * t + 1][2], y3 = s[2 * t + 1][3];
                float hx0 = __bfloat162float(__float2bfloat16(x0));
                float hx1 = __bfloat162float(__float2bfloat16(x1));
                float hx2 = __bfloat162float(__float2bfloat16(x2));
                float hx3 = __bfloat162float(__float2bfloat16(x3));
                float hy0 = __bfloat162float(__float2bfloat16(y0));
                float hy1 = __bfloat162float(__float2bfloat16(y1));
                float hy2 = __bfloat162float(__float2bfloat16(y2));
                float hy3 = __bfloat162float(__float2bfloat16(y3));
                ahi[0] = pack_bf16(x0, x1);  alo[0] = pack_bf16(x0 - hx0, x1 - hx1);
                ahi[1] = pack_bf16(x2, x3);  alo[1] = pack_bf16(x2 - hx2, x3 - hx3);
                ahi[2] = pack_bf16(y0, y1);  alo[2] = pack_bf16(y0 - hy0, y1 - hy1);
                ahi[3] = pack_bf16(y2, y3);  alo[3] = pack_bf16(y2 - hy2, y3 - hy3);
            }
#pragma unroll
            for (int dp = 0; dp < 4; dp++) {
                const uint32_t ro = (uint32_t)(t * 16 * FA_ROW_B + dp * 32) + v_loff;
                uint32_t bh[4], bl[4];
                ldsm_x4_trans(bh, vs_hi_b + ro);
                ldsm_x4_trans(bl, vs_lo_b + ro);
                mma_bf16(o[2 * dp],     ahi, bh[0], bh[1]);
                mma_bf16(o[2 * dp],     ahi, bl[0], bl[1]);
                mma_bf16(o[2 * dp],     alo, bh[0], bh[1]);
                mma_bf16(o[2 * dp + 1], ahi, bh[2], bh[3]);
                mma_bf16(o[2 * dp + 1], ahi, bl[2], bl[3]);
                mma_bf16(o[2 * dp + 1], alo, bh[2], bh[3]);
            }
        }
    }

    // ---- epilogue: normalize, split to hi/lo, store ctx ----
    const float inv0 = 1.f / l[0];
    const float inv1 = 1.f / l[1];
    const int orow = q0_tok + wid * 16 + (lane >> 2);
    const int colb = h * HDIM + (lane & 3) * 2;
#pragma unroll
    for (int nt = 0; nt < 8; nt++) {
        const int col = colb + nt * 8;
        float v00 = o[nt][0] * inv0, v01 = o[nt][1] * inv0;
        float v10 = o[nt][2] * inv1, v11 = o[nt][3] * inv1;
        float h00 = __bfloat162float(__float2bfloat16(v00));
        float h01 = __bfloat162float(__float2bfloat16(v01));
        float h10 = __bfloat162float(__float2bfloat16(v10));
        float h11 = __bfloat162float(__float2bfloat16(v11));
        *(uint32_t*)(Chi + (size_t)orow * DMODEL + col)       = pack_bf16(v00, v01);
        *(uint32_t*)(Clo + (size_t)orow * DMODEL + col)       = pack_bf16(v00 - h00, v01 - h01);
        *(uint32_t*)(Chi + (size_t)(orow + 8) * DMODEL + col) = pack_bf16(v10, v11);
        *(uint32_t*)(Clo + (size_t)(orow + 8) * DMODEL + col) = pack_bf16(v10 - h10, v11 - h11);
    }
}

// ---------------------------------------------------------------------------
// Launch
// ---------------------------------------------------------------------------
extern "C" void kernel_launch(void* const* d_in, const int* in_sizes, int n_in,
                              void* d_out, int out_size)
{
    const float* x  = (const float*)d_in[0];
    const float* wq = (const float*)d_in[1];
    const float* wk = (const float*)d_in[2];
    const float* wv = (const float*)d_in[3];
    const float* wo = (const float*)d_in[4];
    const float* bo = (const float*)d_in[5];
    float* out = (float*)d_out;

    __nv_bfloat16 *xhi, *xlo, *qhi, *qlo, *khi, *klo, *vhi, *vlo, *chi, *clo;
    __nv_bfloat16 *wqhi, *wqlo, *wkhi, *wklo, *wvhi, *wvlo, *wohi, *wolo;
    cudaGetSymbolAddress((void**)&xhi,  g_xhi);
    cudaGetSymbolAddress((void**)&xlo,  g_xlo);
    cudaGetSymbolAddress((void**)&qhi,  g_qhi);
    cudaGetSymbolAddress((void**)&qlo,  g_qlo);
    cudaGetSymbolAddress((void**)&khi,  g_khi);
    cudaGetSymbolAddress((void**)&klo,  g_klo);
    cudaGetSymbolAddress((void**)&vhi,  g_vhi);
    cudaGetSymbolAddress((void**)&vlo,  g_vlo);
    cudaGetSymbolAddress((void**)&chi,  g_chi);
    cudaGetSymbolAddress((void**)&clo,  g_clo);
    cudaGetSymbolAddress((void**)&wqhi, g_wqhi);
    cudaGetSymbolAddress((void**)&wqlo, g_wqlo);
    cudaGetSymbolAddress((void**)&wkhi, g_wkhi);
    cudaGetSymbolAddress((void**)&wklo, g_wklo);
    cudaGetSymbolAddress((void**)&wvhi, g_wvhi);
    cudaGetSymbolAddress((void**)&wvlo, g_wvlo);
    cudaGetSymbolAddress((void**)&wohi, g_wohi);
    cudaGetSymbolAddress((void**)&wolo, g_wolo);

    const int nx = TOKENS * DMODEL;
    const int nw = DMODEL * DMODEL;

    split_bf16_kernel<<<nx / 4 / 256, 256>>>(x, xhi, xlo, nx);
    split_w4_kernel<<<dim3(nw / 4 / 256, 4), 256>>>(
        wq, wk, wv, wo,
        wqhi, wqlo, wkhi, wklo, wvhi, wvlo, wohi, wolo);

    cudaFuncSetAttribute(gemm_qkv,
                         cudaFuncAttributeMaxDynamicSharedMemorySize, GK_SMEM);
    cudaFuncSetAttribute(gemm_out,
                         cudaFuncAttributeMaxDynamicSharedMemorySize, GK_SMEM);

    gemm_qkv<<<dim3(DMODEL / 128, TOKENS / 128, 3), 256, GK_SMEM>>>(
        xhi, xlo, wqhi, wqlo, wkhi, wklo, wvhi, wvlo,
        qhi, qlo, khi, klo, vhi, vlo);

    cudaFuncSetAttribute(flash_mma_kernel,
                         cudaFuncAttributeMaxDynamicSharedMemorySize, FA_SMEM);
    flash_mma_kernel<<<dim3(SEQ / 128, NHEADS, BATCH), 256, FA_SMEM>>>(
        qhi, qlo, khi, klo, vhi, vlo, chi, clo);

    gemm_out<<<dim3(DMODEL / 128, TOKENS / 128), 256, GK_SMEM>>>(
        chi, clo, wohi, wolo, bo, out);
}

// round 10
// speedup vs baseline: 1.4341x; 1.2671x over previous
#include <cuda_runtime.h>
#include <cuda_bf16.h>
#include <cuda_fp16.h>
#include <math_constants.h>
#include <cstdint>

// Problem constants
#define BATCH   4
#define SEQ     2048
#define DMODEL  1024
#define NHEADS  16
#define HDIM    64
#define TOKENS  (BATCH * SEQ)   // 8192

#define LOG2E 1.4426950408889634f
#define SCL2E (0.125f * LOG2E)   // softmax scale folded into exponent

// ---------------------------------------------------------------------------
// Scratch (allocation-free rule: __device__ globals)
// ---------------------------------------------------------------------------
__device__ __nv_bfloat16 g_xhi[TOKENS * DMODEL];
__device__ __nv_bfloat16 g_xlo[TOKENS * DMODEL];
__device__ __half        g_qh [TOKENS * DMODEL];
__device__ __half        g_kh [TOKENS * DMODEL];
__device__ __half        g_vh [TOKENS * DMODEL];
__device__ __nv_bfloat16 g_chi[TOKENS * DMODEL];
__device__ __nv_bfloat16 g_clo[TOKENS * DMODEL];
__device__ __nv_bfloat16 g_wqhi[DMODEL * DMODEL];
__device__ __nv_bfloat16 g_wqlo[DMODEL * DMODEL];
__device__ __nv_bfloat16 g_wkhi[DMODEL * DMODEL];
__device__ __nv_bfloat16 g_wklo[DMODEL * DMODEL];
__device__ __nv_bfloat16 g_wvhi[DMODEL * DMODEL];
__device__ __nv_bfloat16 g_wvlo[DMODEL * DMODEL];
__device__ __nv_bfloat16 g_wohi[DMODEL * DMODEL];
__device__ __nv_bfloat16 g_wolo[DMODEL * DMODEL];

// ---------------------------------------------------------------------------
// PTX helpers (sm_80-baseline only: cp.async, ldmatrix, mma.sync)
// ---------------------------------------------------------------------------
__device__ __forceinline__ uint32_t smem_u32(const void* p) {
    uint32_t a;
    asm("{ .reg .u64 t; cvta.to.shared.u64 t, %1; cvt.u32.u64 %0, t; }"
        : "=r"(a) : "l"(p));
    return a;
}

__device__ __forceinline__ void cp_async16(uint32_t smem, const void* gmem) {
    asm volatile("cp.async.cg.shared.global [%0], [%1], 16;\n"
                 :: "r"(smem), "l"(gmem));
}
#define CP_COMMIT() asm volatile("cp.async.commit_group;\n" ::: "memory")
#define CP_WAIT(n)  asm volatile("cp.async.wait_group %0;\n" :: "n"(n) : "memory")

__device__ __forceinline__ void ldsm_x4(uint32_t* r, uint32_t addr) {
    asm volatile("ldmatrix.sync.aligned.m8n8.x4.shared.b16 {%0,%1,%2,%3}, [%4];"
                 : "=r"(r[0]), "=r"(r[1]), "=r"(r[2]), "=r"(r[3]) : "r"(addr));
}

__device__ __forceinline__ void ldsm_x4_trans(uint32_t* r, uint32_t addr) {
    asm volatile("ldmatrix.sync.aligned.m8n8.x4.trans.shared.b16 {%0,%1,%2,%3}, [%4];"
                 : "=r"(r[0]), "=r"(r[1]), "=r"(r[2]), "=r"(r[3]) : "r"(addr));
}

__device__ __forceinline__ void mma_bf16(float* c, const uint32_t* a,
                                         uint32_t b0, uint32_t b1) {
    asm volatile(
        "mma.sync.aligned.m16n8k16.row.col.f32.bf16.bf16.f32 "
        "{%0,%1,%2,%3}, {%4,%5,%6,%7}, {%8,%9}, {%0,%1,%2,%3};"
        : "+f"(c[0]), "+f"(c[1]), "+f"(c[2]), "+f"(c[3])
        : "r"(a[0]), "r"(a[1]), "r"(a[2]), "r"(a[3]), "r"(b0), "r"(b1));
}

__device__ __forceinline__ void mma_f16(float* c, const uint32_t* a,
                                        uint32_t b0, uint32_t b1) {
    asm volatile(
        "mma.sync.aligned.m16n8k16.row.col.f32.f16.f16.f32 "
        "{%0,%1,%2,%3}, {%4,%5,%6,%7}, {%8,%9}, {%0,%1,%2,%3};"
        : "+f"(c[0]), "+f"(c[1]), "+f"(c[2]), "+f"(c[3])
        : "r"(a[0]), "r"(a[1]), "r"(a[2]), "r"(a[3]), "r"(b0), "r"(b1));
}

__device__ __forceinline__ uint32_t pack_bf16(float x, float y) {
    __nv_bfloat162 t = __floats2bfloat162_rn(x, y);
    return *(uint32_t*)&t;
}

__device__ __forceinline__ uint32_t pack_f16(float x, float y) {
    __half2 t = __floats2half2_rn(x, y);
    return *(uint32_t*)&t;
}

// ---------------------------------------------------------------------------
// Split fp32 -> (bf16 hi, bf16 lo).
// ---------------------------------------------------------------------------
__device__ __forceinline__ void split4(const float* __restrict__ in,
                                       __nv_bfloat16* __restrict__ hi,
                                       __nv_bfloat16* __restrict__ lo, int i)
{
    float4 v = *(const float4*)(in + i);
    __nv_bfloat16 h0 = __float2bfloat16(v.x);
    __nv_bfloat16 h1 = __float2bfloat16(v.y);
    __nv_bfloat16 h2 = __float2bfloat16(v.z);
    __nv_bfloat16 h3 = __float2bfloat16(v.w);
    __nv_bfloat16 l0 = __float2bfloat16(v.x - __bfloat162float(h0));
    __nv_bfloat16 l1 = __float2bfloat16(v.y - __bfloat162float(h1));
    __nv_bfloat16 l2 = __float2bfloat16(v.z - __bfloat162float(h2));
    __nv_bfloat16 l3 = __float2bfloat16(v.w - __bfloat162float(h3));
    ((__nv_bfloat162*)(hi + i))[0] = __nv_bfloat162(h0, h1);
    ((__nv_bfloat162*)(hi + i))[1] = __nv_bfloat162(h2, h3);
    ((__nv_bfloat162*)(lo + i))[0] = __nv_bfloat162(l0, l1);
    ((__nv_bfloat162*)(lo + i))[1] = __nv_bfloat162(l2, l3);
}

__global__ void split_bf16_kernel(const float* __restrict__ in,
                                  __nv_bfloat16* __restrict__ hi,
                                  __nv_bfloat16* __restrict__ lo, int n)
{
    int i = (blockIdx.x * blockDim.x + threadIdx.x) * 4;
    if (i < n) split4(in, hi, lo, i);
}

// Fused 4-weight split: blockIdx.y selects the weight.
__global__ void split_w4_kernel(
    const float* __restrict__ w0, const float* __restrict__ w1,
    const float* __restrict__ w2, const float* __restrict__ w3,
    __nv_bfloat16* __restrict__ h0, __nv_bfloat16* __restrict__ l0,
    __nv_bfloat16* __restrict__ h1, __nv_bfloat16* __restrict__ l1,
    __nv_bfloat16* __restrict__ h2, __nv_bfloat16* __restrict__ l2,
    __nv_bfloat16* __restrict__ h3, __nv_bfloat16* __restrict__ l3)
{
    const float* in;
    __nv_bfloat16 *hi, *lo;
    switch (blockIdx.y) {
        case 0:  in = w0; hi = h0; lo = l0; break;
        case 1:  in = w1; hi = h1; lo = l1; break;
        case 2:  in = w2; hi = h2; lo = l2; break;
        default: in = w3; hi = h3; lo = l3; break;
    }
    int i = (blockIdx.x * blockDim.x + threadIdx.x) * 4;
    if (i < DMODEL * DMODEL) split4(in, hi, lo, i);
}

// ---------------------------------------------------------------------------
// GEMM core (round-8 config, known good): CTA 128x128, BK=32, 256 threads
// (8 warps, 2x4), warp tile 64x32, 2-stage cp.async, launch_bounds(256,2).
// ---------------------------------------------------------------------------
#define GK_BK       32
#define GK_ROW_B    80
#define GK_TILE_B   (128 * GK_ROW_B)
#define GK_STAGE_B  (4 * GK_TILE_B)            // 40960
#define GK_STAGES   2
#define GK_SMEM     (GK_STAGES * GK_STAGE_B)   // 81920
#define GK_NCHUNKS  (DMODEL / GK_BK)           // 32

__device__ __forceinline__ void gk_load_chunk(
    const __nv_bfloat16* const* srcs, int bm, int bn, int c, int st,
    uint32_t sbase, int tid)
{
    const int k0 = c * GK_BK;
#pragma unroll
    for (int t = 0; t < 4; t++) {
        const __nv_bfloat16* src = srcs[t];
        const int rbase = (t < 2) ? bm : bn;
        const uint32_t tb = sbase + st * GK_STAGE_B + t * GK_TILE_B;
#pragma unroll
        for (int i = tid; i < 512; i += 256) {
            const int r = i >> 2;
            const int q = i & 3;
            cp_async16(tb + r * GK_ROW_B + q * 16,
                       src + (size_t)(rbase + r) * DMODEL + k0 + q * 8);
        }
    }
    CP_COMMIT();
}

__device__ __forceinline__ void gk_mainloop(
    const __nv_bfloat16* const* srcs, int bm, int bn,
    uint32_t sbase, int tid, float acc[4][4][4])
{
    const int wid  = tid >> 5;
    const int lane = tid & 31;
    const int warp_m = wid >> 2;
    const int warp_n = wid & 3;

    gk_load_chunk(srcs, bm, bn, 0, 0, sbase, tid);

    const uint32_t lrow16 = (uint32_t)(lane & 15);
    const uint32_t lcolb  = (uint32_t)((lane >> 4) << 4);

    for (int c = 0; c < GK_NCHUNKS; c++) {
        const int st = c & 1;
        CP_WAIT(0);
        __syncthreads();
        if (c + 1 < GK_NCHUNKS)
            gk_load_chunk(srcs, bm, bn, c + 1, (c + 1) & 1, sbase, tid);

        const uint32_t stg = sbase + st * GK_STAGE_B;
        const uint32_t a_r = (uint32_t)(warp_m * 64) + lrow16;
        const uint32_t b_r = (uint32_t)(warp_n * 32) + lrow16;

#pragma unroll
        for (int ks = 0; ks < 2; ks++) {
            const uint32_t kb = lcolb + ks * 32;
            uint32_t ah[4][4], al[4][4], bh[2][4], bl[2][4];
#pragma unroll
            for (int mi = 0; mi < 4; mi++) {
                uint32_t ro = (a_r + mi * 16) * GK_ROW_B + kb;
                ldsm_x4(ah[mi], stg + 0 * GK_TILE_B + ro);
                ldsm_x4(al[mi], stg + 1 * GK_TILE_B + ro);
            }
#pragma unroll
            for (int p = 0; p < 2; p++) {
                uint32_t ro = (b_r + p * 16) * GK_ROW_B + kb;
                ldsm_x4(bh[p], stg + 2 * GK_TILE_B + ro);
                ldsm_x4(bl[p], stg + 3 * GK_TILE_B + ro);
            }
#pragma unroll
            for (int mi = 0; mi < 4; mi++)
#pragma unroll
                for (int ni = 0; ni < 4; ni++) {
                    const int p = ni >> 1, s = ni & 1;
                    mma_bf16(acc[mi][ni], ah[mi], bh[p][s], bh[p][s + 2]);
                    mma_bf16(acc[mi][ni], ah[mi], bl[p][s], bl[p][s + 2]);
                    mma_bf16(acc[mi][ni], al[mi], bh[p][s], bh[p][s + 2]);
                }
        }
        __syncthreads();
    }
}

// ---------------------------------------------------------------------------
// Fused QKV projection: grid.z in {0,1,2}. Output: fp16 (single array).
// ---------------------------------------------------------------------------
__global__ __launch_bounds__(256, 2) void gemm_qkv(
    const __nv_bfloat16* __restrict__ xhi, const __nv_bfloat16* __restrict__ xlo,
    const __nv_bfloat16* __restrict__ wqhi, const __nv_bfloat16* __restrict__ wqlo,
    const __nv_bfloat16* __restrict__ wkhi, const __nv_bfloat16* __restrict__ wklo,
    const __nv_bfloat16* __restrict__ wvhi, const __nv_bfloat16* __restrict__ wvlo,
    __half* __restrict__ qh, __half* __restrict__ kh, __half* __restrict__ vh)
{
    extern __shared__ char smem[];
    const uint32_t sbase = smem_u32(smem);
    const int tid = threadIdx.x;
    const int bm = blockIdx.y * 128;
    const int bn = blockIdx.x * 128;

    const __nv_bfloat16 *Bhi, *Blo;
    __half* C;
    if (blockIdx.z == 0)      { Bhi = wqhi; Blo = wqlo; C = qh; }
    else if (blockIdx.z == 1) { Bhi = wkhi; Blo = wklo; C = kh; }
    else                      { Bhi = wvhi; Blo = wvlo; C = vh; }

    const __nv_bfloat16* srcs[4] = {xhi, xlo, Bhi, Blo};

    float acc[4][4][4];
#pragma unroll
    for (int i = 0; i < 4; i++)
#pragma unroll
        for (int j = 0; j < 4; j++)
#pragma unroll
            for (int r = 0; r < 4; r++) acc[i][j][r] = 0.f;

    gk_mainloop(srcs, bm, bn, sbase, tid, acc);

    const int wid  = tid >> 5;
    const int lane = tid & 31;
    const int warp_m = wid >> 2;
    const int warp_n = wid & 3;
    const int er = lane >> 2;
    const int ec = (lane & 3) * 2;
#pragma unroll
    for (int mi = 0; mi < 4; mi++) {
        const int row0 = bm + warp_m * 64 + mi * 16 + er;
#pragma unroll
        for (int ni = 0; ni < 4; ni++) {
            const int col = bn + warp_n * 32 + ni * 8 + ec;
            *(uint32_t*)(C + (size_t)row0 * DMODEL + col) =
                pack_f16(acc[mi][ni][0], acc[mi][ni][1]);
            *(uint32_t*)(C + (size_t)(row0 + 8) * DMODEL + col) =
                pack_f16(acc[mi][ni][2], acc[mi][ni][3]);
        }
    }
}

// ---------------------------------------------------------------------------
// Output projection: fp32 out + bias (bf16x3, unchanged).
// ---------------------------------------------------------------------------
__global__ __launch_bounds__(256, 2) void gemm_out(
    const __nv_bfloat16* __restrict__ Ahi, const __nv_bfloat16* __restrict__ Alo,
    const __nv_bfloat16* __restrict__ Bhi, const __nv_bfloat16* __restrict__ Blo,
    const float* __restrict__ bias, float* __restrict__ C)
{
    extern __shared__ char smem[];
    const uint32_t sbase = smem_u32(smem);
    const int tid = threadIdx.x;
    const int bm = blockIdx.y * 128;
    const int bn = blockIdx.x * 128;

    const __nv_bfloat16* srcs[4] = {Ahi, Alo, Bhi, Blo};

    float acc[4][4][4];
#pragma unroll
    for (int i = 0; i < 4; i++)
#pragma unroll
        for (int j = 0; j < 4; j++)
#pragma unroll
            for (int r = 0; r < 4; r++) acc[i][j][r] = 0.f;

    gk_mainloop(srcs, bm, bn, sbase, tid, acc);

    const int wid  = tid >> 5;
    const int lane = tid & 31;
    const int warp_m = wid >> 2;
    const int warp_n = wid & 3;
    const int er = lane >> 2;
    const int ec = (lane & 3) * 2;
#pragma unroll
    for (int mi = 0; mi < 4; mi++) {
        const int row0 = bm + warp_m * 64 + mi * 16 + er;
#pragma unroll
        for (int ni = 0; ni < 4; ni++) {
            const int col = bn + warp_n * 32 + ni * 8 + ec;
            const float b0 = bias[col];
            const float b1 = bias[col + 1];
            float2 v0 = make_float2(acc[mi][ni][0] + b0, acc[mi][ni][1] + b1);
            float2 v1 = make_float2(acc[mi][ni][2] + b0, acc[mi][ni][3] + b1);
            *(float2*)(C + (size_t)row0 * DMODEL + col)       = v0;
            *(float2*)(C + (size_t)(row0 + 8) * DMODEL + col) = v1;
        }
    }
}

// ---------------------------------------------------------------------------
// Flash attention v3 (causal): fp16 single-pass MMA, fp32 softmax.
// Q in SMEM fp16 (loaded once); 4-stage cp.async K/V pipeline (uniform
// commit groups incl. empties, CP_WAIT(2)). Deferred l reduction.
// C-frag layout: c0=(r,c), c1=(r,c+1), c2=(r+8,c), c3=(r+8,c+1).
// SMEM: Q 18432 + 4 x 18432 = 92160 B -> 2 CTAs/SM.
// ---------------------------------------------------------------------------
#define FA_ROW_B    144                     // 72 fp16 pitch, 16B-aligned, cf-free
#define FA_Q_B      (128 * FA_ROW_B)        // 18432
#define FA_KV_ARR_B (64 * FA_ROW_B)         // 9216 per array (K or V)
#define FA_STAGE_B  (2 * FA_KV_ARR_B)       // 18432
#define FA_NSTAGES  4
#define FA_KV_OFF   FA_Q_B
#define FA_SMEM     (FA_Q_B + FA_NSTAGES * FA_STAGE_B)  // 92160

__global__ __launch_bounds__(256, 2) void flash_mma_kernel(
    const __half* __restrict__ Q, const __half* __restrict__ K,
    const __half* __restrict__ V,
    __nv_bfloat16* __restrict__ Chi, __nv_bfloat16* __restrict__ Clo)
{
    extern __shared__ char fsm[];
    const uint32_t sbase = smem_u32(fsm);

    const int tid  = threadIdx.x;
    const int wid  = tid >> 5;
    const int lane = tid & 31;
    const int qt = blockIdx.x;
    const int h  = blockIdx.y;
    const int b  = blockIdx.z;

    const int q0_tok = b * SEQ + qt * 128;
    const int qrow_w = qt * 128 + wid * 16;

    // ---- load Q tile (128 rows x 64 fp16) into SMEM ----
    {
        const __half* Qg = Q + (size_t)q0_tok * DMODEL + h * HDIM;
#pragma unroll
        for (int i = tid; i < 1024; i += 256) {
            const int r  = i >> 3;
            const int c8 = i & 7;
            cp_async16(sbase + r * FA_ROW_B + c8 * 16,
                       Qg + (size_t)r * DMODEL + c8 * 8);
        }
        CP_COMMIT();
    }

    float o[8][4];
    float m[2], l[2];
#pragma unroll
    for (int i = 0; i < 8; i++)
#pragma unroll
        for (int j = 0; j < 4; j++) o[i][j] = 0.f;
    m[0] = m[1] = -CUDART_INF_F;
    l[0] = l[1] = 0.f;

    // ldmatrix lane offsets (bytes)
    const uint32_t a_loff = (uint32_t)((lane & 15) * FA_ROW_B + ((lane >> 4) << 4));
    const uint32_t k_loff = (uint32_t)(((lane & 7) + ((lane >> 4) << 3)) * FA_ROW_B
                                       + (((lane >> 3) & 1) << 4));
    const uint32_t v_loff = (uint32_t)(((lane & 7) + (((lane >> 3) & 1) << 3)) * FA_ROW_B
                                       + ((lane >> 4) << 4));

    const uint32_t q_w = sbase + (uint32_t)(wid * 16) * FA_ROW_B + a_loff;

    const __half* Kh = K + h * HDIM;
    const __half* Vh = V + h * HDIM;

    auto load_tile = [&](int kt, int stg) {
        const size_t tok0 = (size_t)(b * SEQ + kt * 64);
        const uint32_t sb = sbase + FA_KV_OFF + stg * FA_STAGE_B;
#pragma unroll
        for (int i = tid; i < 512; i += 256) {
            const int r  = i >> 3;
            const int c8 = i & 7;
            cp_async16(sb + r * FA_ROW_B + c8 * 16,
                       Kh + (tok0 + r) * DMODEL + c8 * 8);
            cp_async16(sb + FA_KV_ARR_B + r * FA_ROW_B + c8 * 16,
                       Vh + (tok0 + r) * DMODEL + c8 * 8);
        }
        CP_COMMIT();
    };

    const int nkt = 2 * qt + 2;

    // prime 3 tiles (uniform group count: empty commits when out of range)
#pragma unroll
    for (int p = 0; p < 3; p++) {
        if (p < nkt) load_tile(p, p);
        else         CP_COMMIT();
    }

    for (int kt = 0; kt < nkt; kt++) {
        const int kb = kt * 64;
        const int stg = kt & 3;
        CP_WAIT(2);
        __syncthreads();
        if (kt + 3 < nkt) load_tile(kt + 3, (kt + 3) & 3);
        else              CP_COMMIT();

        if (kb > qrow_w + 15) continue;

        const uint32_t ks_b = sbase + FA_KV_OFF + stg * FA_STAGE_B;
        const uint32_t vs_b = ks_b + FA_KV_ARR_B;

        // ---- S = Q K^T (fp16), warp tile 16 x 64 ----
        float s[8][4];
#pragma unroll
        for (int i = 0; i < 8; i++)
#pragma unroll
            for (int j = 0; j < 4; j++) s[i][j] = 0.f;

#pragma unroll
        for (int t = 0; t < 4; t++) {
            uint32_t q4[4];
            ldsm_x4(q4, q_w + t * 32);
#pragma unroll
            for (int pp = 0; pp < 4; pp++) {
                const uint32_t ro = (uint32_t)(pp * 16 * FA_ROW_B + t * 32) + k_loff;
                uint32_t k4[4];
                ldsm_x4(k4, ks_b + ro);
                mma_f16(s[2 * pp],     q4, k4[0], k4[1]);
                mma_f16(s[2 * pp + 1], q4, k4[2], k4[3]);
            }
        }

        // ---- causal mask (raw scores; scale folded into exp) ----
        const int row_g0 = qrow_w + (lane >> 2);
        if (kb + 63 > qrow_w) {
#pragma unroll
            for (int nt = 0; nt < 8; nt++) {
                const int colb = kb + nt * 8 + (lane & 3) * 2;
#pragma unroll
                for (int i = 0; i < 4; i++) {
                    const int row = row_g0 + (i >> 1) * 8;
                    const int col = colb + (i & 1);
                    if (col > row) s[nt][i] = -CUDART_INF_F;
                }
            }
        }

        // ---- online softmax (m: quad shfl; l: per-thread partial) ----
        float rmax[2];
        rmax[0] = rmax[1] = -CUDART_INF_F;
#pragma unroll
        for (int nt = 0; nt < 8; nt++) {
            rmax[0] = fmaxf(rmax[0], fmaxf(s[nt][0], s[nt][1]));
            rmax[1] = fmaxf(rmax[1], fmaxf(s[nt][2], s[nt][3]));
        }
#pragma unroll
        for (int off = 1; off <= 2; off <<= 1) {
            rmax[0] = fmaxf(rmax[0], __shfl_xor_sync(0xffffffffu, rmax[0], off));
            rmax[1] = fmaxf(rmax[1], __shfl_xor_sync(0xffffffffu, rmax[1], off));
        }

        float alpha[2], rsum[2];
#pragma unroll
        for (int i = 0; i < 2; i++) {
            float mn = fmaxf(m[i], rmax[i]);
            alpha[i] = exp2f((m[i] - mn) * SCL2E);
            m[i] = mn;
            rsum[i] = 0.f;
        }

#pragma unroll
        for (int nt = 0; nt < 8; nt++) {
            s[nt][0] = exp2f((s[nt][0] - m[0]) * SCL2E);
            s[nt][1] = exp2f((s[nt][1] - m[0]) * SCL2E);
            s[nt][2] = exp2f((s[nt][2] - m[1]) * SCL2E);
            s[nt][3] = exp2f((s[nt][3] - m[1]) * SCL2E);
            rsum[0] += s[nt][0] + s[nt][1];
            rsum[1] += s[nt][2] + s[nt][3];
        }
        l[0] = l[0] * alpha[0] + rsum[0];
        l[1] = l[1] * alpha[1] + rsum[1];
#pragma unroll
        for (int nt = 0; nt < 8; nt++) {
            o[nt][0] *= alpha[0]; o[nt][1] *= alpha[0];
            o[nt][2] *= alpha[1]; o[nt][3] *= alpha[1];
        }

        // ---- O += P V (fp16); P C-frags -> A-frags in registers ----
#pragma unroll
        for (int t = 0; t < 4; t++) {
            uint32_t pa[4];
            pa[0] = pack_f16(s[2 * t][0],     s[2 * t][1]);
            pa[1] = pack_f16(s[2 * t][2],     s[2 * t][3]);
            pa[2] = pack_f16(s[2 * t + 1][0], s[2 * t + 1][1]);
            pa[3] = pack_f16(s[2 * t + 1][2], s[2 * t + 1][3]);
#pragma unroll
            for (int dp = 0; dp < 4; dp++) {
                const uint32_t ro = (uint32_t)(t * 16 * FA_ROW_B + dp * 32) + v_loff;
                uint32_t v4[4];
                ldsm_x4_trans(v4, vs_b + ro);
                mma_f16(o[2 * dp],     pa, v4[0], v4[1]);
                mma_f16(o[2 * dp + 1], pa, v4[2], v4[3]);
            }
        }
    }

    // ---- deferred l reduction over quad ----
#pragma unroll
    for (int off = 1; off <= 2; off <<= 1) {
        l[0] += __shfl_xor_sync(0xffffffffu, l[0], off);
        l[1] += __shfl_xor_sync(0xffffffffu, l[1], off);
    }

    // ---- epilogue: normalize, split to bf16 hi/lo, store ctx ----
    const float inv0 = 1.f / l[0];
    const float inv1 = 1.f / l[1];
    const int orow = q0_tok + wid * 16 + (lane >> 2);
    const int colb = h * HDIM + (lane & 3) * 2;
#pragma unroll
    for (int nt = 0; nt < 8; nt++) {
        const int col = colb + nt * 8;
        float v00 = o[nt][0] * inv0, v01 = o[nt][1] * inv0;
        float v10 = o[nt][2] * inv1, v11 = o[nt][3] * inv1;
        float h00 = __bfloat162float(__float2bfloat16(v00));
        float h01 = __bfloat162float(__float2bfloat16(v01));
        float h10 = __bfloat162float(__float2bfloat16(v10));
        float h11 = __bfloat162float(__float2bfloat16(v11));
        *(uint32_t*)(Chi + (size_t)orow * DMODEL + col)       = pack_bf16(v00, v01);
        *(uint32_t*)(Clo + (size_t)orow * DMODEL + col)       = pack_bf16(v00 - h00, v01 - h01);
        *(uint32_t*)(Chi + (size_t)(orow + 8) * DMODEL + col) = pack_bf16(v10, v11);
        *(uint32_t*)(Clo + (size_t)(orow + 8) * DMODEL + col) = pack_bf16(v10 - h10, v11 - h11);
    }
}

// ---------------------------------------------------------------------------
// Launch
// ---------------------------------------------------------------------------
extern "C" void kernel_launch(void* const* d_in, const int* in_sizes, int n_in,
                              void* d_out, int out_size)
{
    const float* x  = (const float*)d_in[0];
    const float* wq = (const float*)d_in[1];
    const float* wk = (const float*)d_in[2];
    const float* wv = (const float*)d_in[3];
    const float* wo = (const float*)d_in[4];
    const float* bo = (const float*)d_in[5];
    float* out = (float*)d_out;

    __nv_bfloat16 *xhi, *xlo, *chi, *clo;
    __half *qh, *kh, *vh;
    __nv_bfloat16 *wqhi, *wqlo, *wkhi, *wklo, *wvhi, *wvlo, *wohi, *wolo;
    cudaGetSymbolAddress((void**)&xhi,  g_xhi);
    cudaGetSymbolAddress((void**)&xlo,  g_xlo);
    cudaGetSymbolAddress((void**)&qh,   g_qh);
    cudaGetSymbolAddress((void**)&kh,   g_kh);
    cudaGetSymbolAddress((void**)&vh,   g_vh);
    cudaGetSymbolAddress((void**)&chi,  g_chi);
    cudaGetSymbolAddress((void**)&clo,  g_clo);
    cudaGetSymbolAddress((void**)&wqhi, g_wqhi);
    cudaGetSymbolAddress((void**)&wqlo, g_wqlo);
    cudaGetSymbolAddress((void**)&wkhi, g_wkhi);
    cudaGetSymbolAddress((void**)&wklo, g_wklo);
    cudaGetSymbolAddress((void**)&wvhi, g_wvhi);
    cudaGetSymbolAddress((void**)&wvlo, g_wvlo);
    cudaGetSymbolAddress((void**)&wohi, g_wohi);
    cudaGetSymbolAddress((void**)&wolo, g_wolo);

    const int nx = TOKENS * DMODEL;
    const int nw = DMODEL * DMODEL;

    split_bf16_kernel<<<nx / 4 / 256, 256>>>(x, xhi, xlo, nx);
    split_w4_kernel<<<dim3(nw / 4 / 256, 4), 256>>>(
        wq, wk, wv, wo,
        wqhi, wqlo, wkhi, wklo, wvhi, wvlo, wohi, wolo);

    cudaFuncSetAttribute(gemm_qkv,
                         cudaFuncAttributeMaxDynamicSharedMemorySize, GK_SMEM);
    cudaFuncSetAttribute(gemm_out,
                         cudaFuncAttributeMaxDynamicSharedMemorySize, GK_SMEM);

    gemm_qkv<<<dim3(DMODEL / 128, TOKENS / 128, 3), 256, GK_SMEM>>>(
        xhi, xlo, wqhi, wqlo, wkhi, wklo, wvhi, wvlo, qh, kh, vh);

    cudaFuncSetAttribute(flash_mma_kernel,
                         cudaFuncAttributeMaxDynamicSharedMemorySize, FA_SMEM);
    flash_mma_kernel<<<dim3(SEQ / 128, NHEADS, BATCH), 256, FA_SMEM>>>(
        qh, kh, vh, chi, clo);

    gemm_out<<<dim3(DMODEL / 128, TOKENS / 128), 256, GK_SMEM>>>(
        chi, clo, wohi, wolo, bo, out);
}

// round 11
// speedup vs baseline: 1.9063x; 1.3293x over previous
#include <cuda_runtime.h>
#include <cuda_fp16.h>
#include <math_constants.h>
#include <cstdint>

// Problem constants
#define BATCH   4
#define SEQ     2048
#define DMODEL  1024
#define NHEADS  16
#define HDIM    64
#define TOKENS  (BATCH * SEQ)   // 8192

#define LOG2E 1.4426950408889634f
#define SCL2E (0.125f * LOG2E)   // softmax scale folded into exponent

// ---------------------------------------------------------------------------
// Scratch (allocation-free rule: __device__ globals)
// ---------------------------------------------------------------------------
__device__ __half g_xh [TOKENS * DMODEL];
__device__ __half g_qh [TOKENS * DMODEL];
__device__ __half g_kh [TOKENS * DMODEL];
__device__ __half g_vh [TOKENS * DMODEL];
__device__ __half g_ch [TOKENS * DMODEL];
__device__ __half g_wqhi[DMODEL * DMODEL];
__device__ __half g_wqlo[DMODEL * DMODEL];
__device__ __half g_wkhi[DMODEL * DMODEL];
__device__ __half g_wklo[DMODEL * DMODEL];
__device__ __half g_wvhi[DMODEL * DMODEL];
__device__ __half g_wvlo[DMODEL * DMODEL];
__device__ __half g_wohi[DMODEL * DMODEL];
__device__ __half g_wolo[DMODEL * DMODEL];

// ---------------------------------------------------------------------------
// PTX helpers (sm_80-baseline only: cp.async, ldmatrix, mma.sync)
// ---------------------------------------------------------------------------
__device__ __forceinline__ uint32_t smem_u32(const void* p) {
    uint32_t a;
    asm("{ .reg .u64 t; cvta.to.shared.u64 t, %1; cvt.u32.u64 %0, t; }"
        : "=r"(a) : "l"(p));
    return a;
}

__device__ __forceinline__ void cp_async16(uint32_t smem, const void* gmem) {
    asm volatile("cp.async.cg.shared.global [%0], [%1], 16;\n"
                 :: "r"(smem), "l"(gmem));
}
#define CP_COMMIT() asm volatile("cp.async.commit_group;\n" ::: "memory")
#define CP_WAIT(n)  asm volatile("cp.async.wait_group %0;\n" :: "n"(n) : "memory")

__device__ __forceinline__ void ldsm_x4(uint32_t* r, uint32_t addr) {
    asm volatile("ldmatrix.sync.aligned.m8n8.x4.shared.b16 {%0,%1,%2,%3}, [%4];"
                 : "=r"(r[0]), "=r"(r[1]), "=r"(r[2]), "=r"(r[3]) : "r"(addr));
}

__device__ __forceinline__ void ldsm_x4_trans(uint32_t* r, uint32_t addr) {
    asm volatile("ldmatrix.sync.aligned.m8n8.x4.trans.shared.b16 {%0,%1,%2,%3}, [%4];"
                 : "=r"(r[0]), "=r"(r[1]), "=r"(r[2]), "=r"(r[3]) : "r"(addr));
}

__device__ __forceinline__ void mma_f16(float* c, const uint32_t* a,
                                        uint32_t b0, uint32_t b1) {
    asm volatile(
        "mma.sync.aligned.m16n8k16.row.col.f32.f16.f16.f32 "
        "{%0,%1,%2,%3}, {%4,%5,%6,%7}, {%8,%9}, {%0,%1,%2,%3};"
        : "+f"(c[0]), "+f"(c[1]), "+f"(c[2]), "+f"(c[3])
        : "r"(a[0]), "r"(a[1]), "r"(a[2]), "r"(a[3]), "r"(b0), "r"(b1));
}

__device__ __forceinline__ uint32_t pack_f16(float x, float y) {
    __half2 t = __floats2half2_rn(x, y);
    return *(uint32_t*)&t;
}

// ---------------------------------------------------------------------------
// Conversions
// ---------------------------------------------------------------------------
__global__ void cvt_f16_kernel(const float* __restrict__ in,
                               __half* __restrict__ out, int n)
{
    int i = (blockIdx.x * blockDim.x + threadIdx.x) * 4;
    if (i >= n) return;
    float4 v = *(const float4*)(in + i);
    ((__half2*)(out + i))[0] = __floats2half2_rn(v.x, v.y);
    ((__half2*)(out + i))[1] = __floats2half2_rn(v.z, v.w);
}

// Fused 4-weight split to fp16 hi/lo: blockIdx.y selects the weight.
__global__ void split_w4_kernel(
    const float* __restrict__ w0, const float* __restrict__ w1,
    const float* __restrict__ w2, const float* __restrict__ w3,
    __half* __restrict__ h0, __half* __restrict__ l0,
    __half* __restrict__ h1, __half* __restrict__ l1,
    __half* __restrict__ h2, __half* __restrict__ l2,
    __half* __restrict__ h3, __half* __restrict__ l3)
{
    const float* in;
    __half *hi, *lo;
    switch (blockIdx.y) {
        case 0:  in = w0; hi = h0; lo = l0; break;
        case 1:  in = w1; hi = h1; lo = l1; break;
        case 2:  in = w2; hi = h2; lo = l2; break;
        default: in = w3; hi = h3; lo = l3; break;
    }
    int i = (blockIdx.x * blockDim.x + threadIdx.x) * 4;
    if (i >= DMODEL * DMODEL) return;
    float4 v = *(const float4*)(in + i);
    __half a0 = __float2half_rn(v.x);
    __half a1 = __float2half_rn(v.y);
    __half a2 = __float2half_rn(v.z);
    __half a3 = __float2half_rn(v.w);
    ((__half2*)(hi + i))[0] = __half2(a0, a1);
    ((__half2*)(hi + i))[1] = __half2(a2, a3);
    ((__half2*)(lo + i))[0] = __floats2half2_rn(v.x - __half2float(a0),
                                                v.y - __half2float(a1));
    ((__half2*)(lo + i))[1] = __floats2half2_rn(v.z - __half2float(a2),
                                                v.w - __half2float(a3));
}

// ---------------------------------------------------------------------------
// GEMM core (fp16 2-pass): C = A (Bhi+Blo)^T. CTA 128x128, BK=32,
// 256 threads (8 warps, 2x4), warp tile 64x32, 3-stage cp.async pipeline
// (92,160 B SMEM), launch_bounds(256,2) -> 2 CTAs/SM.
// ---------------------------------------------------------------------------
#define GK_BK       32
#define GK_ROW_B    80
#define GK_TILE_B   (128 * GK_ROW_B)           // 10240
#define GK_STAGE_B  (3 * GK_TILE_B)            // 30720 (A, Bhi, Blo)
#define GK_STAGES   3
#define GK_SMEM     (GK_STAGES * GK_STAGE_B)   // 92160
#define GK_NCHUNKS  (DMODEL / GK_BK)           // 32

__device__ __forceinline__ void gk_load_chunk(
    const __half* const* srcs, int bm, int bn, int c, int st,
    uint32_t sbase, int tid)
{
    const int k0 = c * GK_BK;
#pragma unroll
    for (int t = 0; t < 3; t++) {
        const __half* src = srcs[t];
        const int rbase = (t < 1) ? bm : bn;
        const uint32_t tb = sbase + st * GK_STAGE_B + t * GK_TILE_B;
#pragma unroll
        for (int i = tid; i < 512; i += 256) {
            const int r = i >> 2;
            const int q = i & 3;
            cp_async16(tb + r * GK_ROW_B + q * 16,
                       src + (size_t)(rbase + r) * DMODEL + k0 + q * 8);
        }
    }
    CP_COMMIT();
}

__device__ __forceinline__ void gk_mainloop(
    const __half* const* srcs, int bm, int bn,
    uint32_t sbase, int tid, float acc[4][4][4])
{
    const int wid  = tid >> 5;
    const int lane = tid & 31;
    const int warp_m = wid >> 2;
    const int warp_n = wid & 3;

    gk_load_chunk(srcs, bm, bn, 0, 0, sbase, tid);
    gk_load_chunk(srcs, bm, bn, 1, 1, sbase, tid);

    const uint32_t lrow16 = (uint32_t)(lane & 15);
    const uint32_t lcolb  = (uint32_t)((lane >> 4) << 4);

    for (int c = 0; c < GK_NCHUNKS; c++) {
        const int st = c % GK_STAGES;
        if (c + 1 < GK_NCHUNKS) { CP_WAIT(1); } else { CP_WAIT(0); }
        __syncthreads();
        if (c + 2 < GK_NCHUNKS)
            gk_load_chunk(srcs, bm, bn, c + 2, (c + 2) % GK_STAGES, sbase, tid);

        const uint32_t stg = sbase + st * GK_STAGE_B;
        const uint32_t a_r = (uint32_t)(warp_m * 64) + lrow16;
        const uint32_t b_r = (uint32_t)(warp_n * 32) + lrow16;

#pragma unroll
        for (int ks = 0; ks < 2; ks++) {
            const uint32_t kb = lcolb + ks * 32;
            uint32_t ah[4][4], bh[2][4], bl[2][4];
#pragma unroll
            for (int mi = 0; mi < 4; mi++) {
                uint32_t ro = (a_r + mi * 16) * GK_ROW_B + kb;
                ldsm_x4(ah[mi], stg + 0 * GK_TILE_B + ro);
            }
#pragma unroll
            for (int p = 0; p < 2; p++) {
                uint32_t ro = (b_r + p * 16) * GK_ROW_B + kb;
                ldsm_x4(bh[p], stg + 1 * GK_TILE_B + ro);
                ldsm_x4(bl[p], stg + 2 * GK_TILE_B + ro);
            }
#pragma unroll
            for (int mi = 0; mi < 4; mi++)
#pragma unroll
                for (int ni = 0; ni < 4; ni++) {
                    const int p = ni >> 1, s = ni & 1;
                    mma_f16(acc[mi][ni], ah[mi], bh[p][s], bh[p][s + 2]);
                    mma_f16(acc[mi][ni], ah[mi], bl[p][s], bl[p][s + 2]);
                }
        }
        __syncthreads();
    }
}

// ---------------------------------------------------------------------------
// Fused QKV projection: grid.z in {0,1,2}. Output: fp16.
// ---------------------------------------------------------------------------
__global__ __launch_bounds__(256, 2) void gemm_qkv(
    const __half* __restrict__ xh,
    const __half* __restrict__ wqhi, const __half* __restrict__ wqlo,
    const __half* __restrict__ wkhi, const __half* __restrict__ wklo,
    const __half* __restrict__ wvhi, const __half* __restrict__ wvlo,
    __half* __restrict__ qh, __half* __restrict__ kh, __half* __restrict__ vh)
{
    extern __shared__ char smem[];
    const uint32_t sbase = smem_u32(smem);
    const int tid = threadIdx.x;
    const int bm = blockIdx.y * 128;
    const int bn = blockIdx.x * 128;

    const __half *Bhi, *Blo;
    __half* C;
    if (blockIdx.z == 0)      { Bhi = wqhi; Blo = wqlo; C = qh; }
    else if (blockIdx.z == 1) { Bhi = wkhi; Blo = wklo; C = kh; }
    else                      { Bhi = wvhi; Blo = wvlo; C = vh; }

    const __half* srcs[3] = {xh, Bhi, Blo};

    float acc[4][4][4];
#pragma unroll
    for (int i = 0; i < 4; i++)
#pragma unroll
        for (int j = 0; j < 4; j++)
#pragma unroll
            for (int r = 0; r < 4; r++) acc[i][j][r] = 0.f;

    gk_mainloop(srcs, bm, bn, sbase, tid, acc);

    const int wid  = tid >> 5;
    const int lane = tid & 31;
    const int warp_m = wid >> 2;
    const int warp_n = wid & 3;
    const int er = lane >> 2;
    const int ec = (lane & 3) * 2;
#pragma unroll
    for (int mi = 0; mi < 4; mi++) {
        const int row0 = bm + warp_m * 64 + mi * 16 + er;
#pragma unroll
        for (int ni = 0; ni < 4; ni++) {
            const int col = bn + warp_n * 32 + ni * 8 + ec;
            *(uint32_t*)(C + (size_t)row0 * DMODEL + col) =
                pack_f16(acc[mi][ni][0], acc[mi][ni][1]);
            *(uint32_t*)(C + (size_t)(row0 + 8) * DMODEL + col) =
                pack_f16(acc[mi][ni][2], acc[mi][ni][3]);
        }
    }
}

// ---------------------------------------------------------------------------
// Output projection: fp32 out + bias.
// ---------------------------------------------------------------------------
__global__ __launch_bounds__(256, 2) void gemm_out(
    const __half* __restrict__ Ah,
    const __half* __restrict__ Bhi, const __half* __restrict__ Blo,
    const float* __restrict__ bias, float* __restrict__ C)
{
    extern __shared__ char smem[];
    const uint32_t sbase = smem_u32(smem);
    const int tid = threadIdx.x;
    const int bm = blockIdx.y * 128;
    const int bn = blockIdx.x * 128;

    const __half* srcs[3] = {Ah, Bhi, Blo};

    float acc[4][4][4];
#pragma unroll
    for (int i = 0; i < 4; i++)
#pragma unroll
        for (int j = 0; j < 4; j++)
#pragma unroll
            for (int r = 0; r < 4; r++) acc[i][j][r] = 0.f;

    gk_mainloop(srcs, bm, bn, sbase, tid, acc);

    const int wid  = tid >> 5;
    const int lane = tid & 31;
    const int warp_m = wid >> 2;
    const int warp_n = wid & 3;
    const int er = lane >> 2;
    const int ec = (lane & 3) * 2;
#pragma unroll
    for (int mi = 0; mi < 4; mi++) {
        const int row0 = bm + warp_m * 64 + mi * 16 + er;
#pragma unroll
        for (int ni = 0; ni < 4; ni++) {
            const int col = bn + warp_n * 32 + ni * 8 + ec;
            const float b0 = bias[col];
            const float b1 = bias[col + 1];
            float2 v0 = make_float2(acc[mi][ni][0] + b0, acc[mi][ni][1] + b1);
            float2 v1 = make_float2(acc[mi][ni][2] + b0, acc[mi][ni][3] + b1);
            *(float2*)(C + (size_t)row0 * DMODEL + col)       = v0;
            *(float2*)(C + (size_t)(row0 + 8) * DMODEL + col) = v1;
        }
    }
}

// ---------------------------------------------------------------------------
// Flash attention v3 (causal): fp16 single-pass MMA, fp32 softmax.
// Q in SMEM fp16; 4-stage cp.async K/V pipeline; deferred l reduction.
// Output: single fp16 ctx. SMEM 92160 B -> 2 CTAs/SM.
// ---------------------------------------------------------------------------
#define FA_ROW_B    144
#define FA_Q_B      (128 * FA_ROW_B)        // 18432
#define FA_KV_ARR_B (64 * FA_ROW_B)         // 9216
#define FA_STAGE_B  (2 * FA_KV_ARR_B)       // 18432
#define FA_NSTAGES  4
#define FA_KV_OFF   FA_Q_B
#define FA_SMEM     (FA_Q_B + FA_NSTAGES * FA_STAGE_B)  // 92160

__global__ __launch_bounds__(256, 2) void flash_mma_kernel(
    const __half* __restrict__ Q, const __half* __restrict__ K,
    const __half* __restrict__ V, __half* __restrict__ C)
{
    extern __shared__ char fsm[];
    const uint32_t sbase = smem_u32(fsm);

    const int tid  = threadIdx.x;
    const int wid  = tid >> 5;
    const int lane = tid & 31;
    const int qt = blockIdx.x;
    const int h  = blockIdx.y;
    const int b  = blockIdx.z;

    const int q0_tok = b * SEQ + qt * 128;
    const int qrow_w = qt * 128 + wid * 16;

    // ---- load Q tile (128 rows x 64 fp16) into SMEM ----
    {
        const __half* Qg = Q + (size_t)q0_tok * DMODEL + h * HDIM;
#pragma unroll
        for (int i = tid; i < 1024; i += 256) {
            const int r  = i >> 3;
            const int c8 = i & 7;
            cp_async16(sbase + r * FA_ROW_B + c8 * 16,
                       Qg + (size_t)r * DMODEL + c8 * 8);
        }
        CP_COMMIT();
    }

    float o[8][4];
    float m[2], l[2];
#pragma unroll
    for (int i = 0; i < 8; i++)
#pragma unroll
        for (int j = 0; j < 4; j++) o[i][j] = 0.f;
    m[0] = m[1] = -CUDART_INF_F;
    l[0] = l[1] = 0.f;

    const uint32_t a_loff = (uint32_t)((lane & 15) * FA_ROW_B + ((lane >> 4) << 4));
    const uint32_t k_loff = (uint32_t)(((lane & 7) + ((lane >> 4) << 3)) * FA_ROW_B
                                       + (((lane >> 3) & 1) << 4));
    const uint32_t v_loff = (uint32_t)(((lane & 7) + (((lane >> 3) & 1) << 3)) * FA_ROW_B
                                       + ((lane >> 4) << 4));

    const uint32_t q_w = sbase + (uint32_t)(wid * 16) * FA_ROW_B + a_loff;

    const __half* Kh = K + h * HDIM;
    const __half* Vh = V + h * HDIM;

    auto load_tile = [&](int kt, int stg) {
        const size_t tok0 = (size_t)(b * SEQ + kt * 64);
        const uint32_t sb = sbase + FA_KV_OFF + stg * FA_STAGE_B;
#pragma unroll
        for (int i = tid; i < 512; i += 256) {
            const int r  = i >> 3;
            const int c8 = i & 7;
            cp_async16(sb + r * FA_ROW_B + c8 * 16,
                       Kh + (tok0 + r) * DMODEL + c8 * 8);
            cp_async16(sb + FA_KV_ARR_B + r * FA_ROW_B + c8 * 16,
                       Vh + (tok0 + r) * DMODEL + c8 * 8);
        }
        CP_COMMIT();
    };

    const int nkt = 2 * qt + 2;

#pragma unroll
    for (int p = 0; p < 3; p++) {
        if (p < nkt) load_tile(p, p);
        else         CP_COMMIT();
    }

    for (int kt = 0; kt < nkt; kt++) {
        const int kb = kt * 64;
        const int stg = kt & 3;
        CP_WAIT(2);
        __syncthreads();
        if (kt + 3 < nkt) load_tile(kt + 3, (kt + 3) & 3);
        else              CP_COMMIT();

        if (kb > qrow_w + 15) continue;

        const uint32_t ks_b = sbase + FA_KV_OFF + stg * FA_STAGE_B;
        const uint32_t vs_b = ks_b + FA_KV_ARR_B;

        // ---- S = Q K^T (fp16) ----
        float s[8][4];
#pragma unroll
        for (int i = 0; i < 8; i++)
#pragma unroll
            for (int j = 0; j < 4; j++) s[i][j] = 0.f;

#pragma unroll
        for (int t = 0; t < 4; t++) {
            uint32_t q4[4];
            ldsm_x4(q4, q_w + t * 32);
#pragma unroll
            for (int pp = 0; pp < 4; pp++) {
                const uint32_t ro = (uint32_t)(pp * 16 * FA_ROW_B + t * 32) + k_loff;
                uint32_t k4[4];
                ldsm_x4(k4, ks_b + ro);
                mma_f16(s[2 * pp],     q4, k4[0], k4[1]);
                mma_f16(s[2 * pp + 1], q4, k4[2], k4[3]);
            }
        }

        // ---- causal mask ----
        const int row_g0 = qrow_w + (lane >> 2);
        if (kb + 63 > qrow_w) {
#pragma unroll
            for (int nt = 0; nt < 8; nt++) {
                const int colb = kb + nt * 8 + (lane & 3) * 2;
#pragma unroll
                for (int i = 0; i < 4; i++) {
                    const int row = row_g0 + (i >> 1) * 8;
                    const int col = colb + (i & 1);
                    if (col > row) s[nt][i] = -CUDART_INF_F;
                }
            }
        }

        // ---- online softmax (m: quad shfl; l: per-thread, deferred) ----
        float rmax[2];
        rmax[0] = rmax[1] = -CUDART_INF_F;
#pragma unroll
        for (int nt = 0; nt < 8; nt++) {
            rmax[0] = fmaxf(rmax[0], fmaxf(s[nt][0], s[nt][1]));
            rmax[1] = fmaxf(rmax[1], fmaxf(s[nt][2], s[nt][3]));
        }
#pragma unroll
        for (int off = 1; off <= 2; off <<= 1) {
            rmax[0] = fmaxf(rmax[0], __shfl_xor_sync(0xffffffffu, rmax[0], off));
            rmax[1] = fmaxf(rmax[1], __shfl_xor_sync(0xffffffffu, rmax[1], off));
        }

        float alpha[2], rsum[2];
#pragma unroll
        for (int i = 0; i < 2; i++) {
            float mn = fmaxf(m[i], rmax[i]);
            alpha[i] = exp2f((m[i] - mn) * SCL2E);
            m[i] = mn;
            rsum[i] = 0.f;
        }

#pragma unroll
        for (int nt = 0; nt < 8; nt++) {
            s[nt][0] = exp2f((s[nt][0] - m[0]) * SCL2E);
            s[nt][1] = exp2f((s[nt][1] - m[0]) * SCL2E);
            s[nt][2] = exp2f((s[nt][2] - m[1]) * SCL2E);
            s[nt][3] = exp2f((s[nt][3] - m[1]) * SCL2E);
            rsum[0] += s[nt][0] + s[nt][1];
            rsum[1] += s[nt][2] + s[nt][3];
        }
        l[0] = l[0] * alpha[0] + rsum[0];
        l[1] = l[1] * alpha[1] + rsum[1];
#pragma unroll
        for (int nt = 0; nt < 8; nt++) {
            o[nt][0] *= alpha[0]; o[nt][1] *= alpha[0];
            o[nt][2] *= alpha[1]; o[nt][3] *= alpha[1];
        }

        // ---- O += P V (fp16) ----
#pragma unroll
        for (int t = 0; t < 4; t++) {
            uint32_t pa[4];
            pa[0] = pack_f16(s[2 * t][0],     s[2 * t][1]);
            pa[1] = pack_f16(s[2 * t][2],     s[2 * t][3]);
            pa[2] = pack_f16(s[2 * t + 1][0], s[2 * t + 1][1]);
            pa[3] = pack_f16(s[2 * t + 1][2], s[2 * t + 1][3]);
#pragma unroll
            for (int dp = 0; dp < 4; dp++) {
                const uint32_t ro = (uint32_t)(t * 16 * FA_ROW_B + dp * 32) + v_loff;
                uint32_t v4[4];
                ldsm_x4_trans(v4, vs_b + ro);
                mma_f16(o[2 * dp],     pa, v4[0], v4[1]);
                mma_f16(o[2 * dp + 1], pa, v4[2], v4[3]);
            }
        }
    }

    // ---- deferred l reduction over quad ----
#pragma unroll
    for (int off = 1; off <= 2; off <<= 1) {
        l[0] += __shfl_xor_sync(0xffffffffu, l[0], off);
        l[1] += __shfl_xor_sync(0xffffffffu, l[1], off);
    }

    // ---- epilogue: normalize, store fp16 ctx ----
    const float inv0 = 1.f / l[0];
    const float inv1 = 1.f / l[1];
    const int orow = q0_tok + wid * 16 + (lane >> 2);
    const int colb = h * HDIM + (lane & 3) * 2;
#pragma unroll
    for (int nt = 0; nt < 8; nt++) {
        const int col = colb + nt * 8;
        *(uint32_t*)(C + (size_t)orow * DMODEL + col) =
            pack_f16(o[nt][0] * inv0, o[nt][1] * inv0);
        *(uint32_t*)(C + (size_t)(orow + 8) * DMODEL + col) =
            pack_f16(o[nt][2] * inv1, o[nt][3] * inv1);
    }
}

// ---------------------------------------------------------------------------
// Launch
// ---------------------------------------------------------------------------
extern "C" void kernel_launch(void* const* d_in, const int* in_sizes, int n_in,
                              void* d_out, int out_size)
{
    const float* x  = (const float*)d_in[0];
    const float* wq = (const float*)d_in[1];
    const float* wk = (const float*)d_in[2];
    const float* wv = (const float*)d_in[3];
    const float* wo = (const float*)d_in[4];
    const float* bo = (const float*)d_in[5];
    float* out = (float*)d_out;

    __half *xh, *qh, *kh, *vh, *ch;
    __half *wqhi, *wqlo, *wkhi, *wklo, *wvhi, *wvlo, *wohi, *wolo;
    cudaGetSymbolAddress((void**)&xh,   g_xh);
    cudaGetSymbolAddress((void**)&qh,   g_qh);
    cudaGetSymbolAddress((void**)&kh,   g_kh);
    cudaGetSymbolAddress((void**)&vh,   g_vh);
    cudaGetSymbolAddress((void**)&ch,   g_ch);
    cudaGetSymbolAddress((void**)&wqhi, g_wqhi);
    cudaGetSymbolAddress((void**)&wqlo, g_wqlo);
    cudaGetSymbolAddress((void**)&wkhi, g_wkhi);
    cudaGetSymbolAddress((void**)&wklo, g_wklo);
    cudaGetSymbolAddress((void**)&wvhi, g_wvhi);
    cudaGetSymbolAddress((void**)&wvlo, g_wvlo);
    cudaGetSymbolAddress((void**)&wohi, g_wohi);
    cudaGetSymbolAddress((void**)&wolo, g_wolo);

    const int nx = TOKENS * DMODEL;
    const int nw = DMODEL * DMODEL;

    cvt_f16_kernel<<<nx / 4 / 256, 256>>>(x, xh, nx);
    split_w4_kernel<<<dim3(nw / 4 / 256, 4), 256>>>(
        wq, wk, wv, wo,
        wqhi, wqlo, wkhi, wklo, wvhi, wvlo, wohi, wolo);

    cudaFuncSetAttribute(gemm_qkv,
                         cudaFuncAttributeMaxDynamicSharedMemorySize, GK_SMEM);
    cudaFuncSetAttribute(gemm_out,
                         cudaFuncAttributeMaxDynamicSharedMemorySize, GK_SMEM);

    gemm_qkv<<<dim3(DMODEL / 128, TOKENS / 128, 3), 256, GK_SMEM>>>(
        xh, wqhi, wqlo, wkhi, wklo, wvhi, wvlo, qh, kh, vh);

    cudaFuncSetAttribute(flash_mma_kernel,
                         cudaFuncAttributeMaxDynamicSharedMemorySize, FA_SMEM);
    flash_mma_kernel<<<dim3(SEQ / 128, NHEADS, BATCH), 256, FA_SMEM>>>(
        qh, kh, vh, ch);

    gemm_out<<<dim3(DMODEL / 128, TOKENS / 128), 256, GK_SMEM>>>(
        ch, wohi, wolo, bo, out);
}

// round 12
// speedup vs baseline: 2.4248x; 1.2720x over previous
#include <cuda_runtime.h>
#include <cuda_fp16.h>
#include <math_constants.h>
#include <cstdint>

// Problem constants
#define BATCH   4
#define SEQ     2048
#define DMODEL  1024
#define NHEADS  16
#define HDIM    64
#define TOKENS  (BATCH * SEQ)   // 8192

#define LOG2E 1.4426950408889634f
#define SCL2E (0.125f * LOG2E)   // softmax scale folded into exponent

// ---------------------------------------------------------------------------
// Scratch (allocation-free rule: __device__ globals)
// ---------------------------------------------------------------------------
__device__ __half g_xh [TOKENS * DMODEL];
__device__ __half g_qh [TOKENS * DMODEL];
__device__ __half g_kh [TOKENS * DMODEL];
__device__ __half g_vh [TOKENS * DMODEL];
__device__ __half g_ch [TOKENS * DMODEL];
__device__ __half g_wqh [DMODEL * DMODEL];
__device__ __half g_wkh [DMODEL * DMODEL];
__device__ __half g_wvh [DMODEL * DMODEL];
__device__ __half g_wohi[DMODEL * DMODEL];
__device__ __half g_wolo[DMODEL * DMODEL];

// ---------------------------------------------------------------------------
// PTX helpers (sm_80-baseline only: cp.async, ldmatrix, mma.sync)
// ---------------------------------------------------------------------------
__device__ __forceinline__ uint32_t smem_u32(const void* p) {
    uint32_t a;
    asm("{ .reg .u64 t; cvta.to.shared.u64 t, %1; cvt.u32.u64 %0, t; }"
        : "=r"(a) : "l"(p));
    return a;
}

__device__ __forceinline__ void cp_async16(uint32_t smem, const void* gmem) {
    asm volatile("cp.async.cg.shared.global [%0], [%1], 16;\n"
                 :: "r"(smem), "l"(gmem));
}
#define CP_COMMIT() asm volatile("cp.async.commit_group;\n" ::: "memory")
#define CP_WAIT(n)  asm volatile("cp.async.wait_group %0;\n" :: "n"(n) : "memory")

__device__ __forceinline__ void ldsm_x4(uint32_t* r, uint32_t addr) {
    asm volatile("ldmatrix.sync.aligned.m8n8.x4.shared.b16 {%0,%1,%2,%3}, [%4];"
                 : "=r"(r[0]), "=r"(r[1]), "=r"(r[2]), "=r"(r[3]) : "r"(addr));
}

__device__ __forceinline__ void ldsm_x4_trans(uint32_t* r, uint32_t addr) {
    asm volatile("ldmatrix.sync.aligned.m8n8.x4.trans.shared.b16 {%0,%1,%2,%3}, [%4];"
                 : "=r"(r[0]), "=r"(r[1]), "=r"(r[2]), "=r"(r[3]) : "r"(addr));
}

__device__ __forceinline__ void mma_f16(float* c, const uint32_t* a,
                                        uint32_t b0, uint32_t b1) {
    asm volatile(
        "mma.sync.aligned.m16n8k16.row.col.f32.f16.f16.f32 "
        "{%0,%1,%2,%3}, {%4,%5,%6,%7}, {%8,%9}, {%0,%1,%2,%3};"
        : "+f"(c[0]), "+f"(c[1]), "+f"(c[2]), "+f"(c[3])
        : "r"(a[0]), "r"(a[1]), "r"(a[2]), "r"(a[3]), "r"(b0), "r"(b1));
}

__device__ __forceinline__ uint32_t pack_f16(float x, float y) {
    __half2 t = __floats2half2_rn(x, y);
    return *(uint32_t*)&t;
}

// ---------------------------------------------------------------------------
// Preprocessing
// ---------------------------------------------------------------------------
__global__ void cvt_f16_kernel(const float* __restrict__ in,
                               __half* __restrict__ out, int n)
{
    int i = (blockIdx.x * blockDim.x + threadIdx.x) * 4;
    if (i >= n) return;
    float4 v = *(const float4*)(in + i);
    ((__half2*)(out + i))[0] = __floats2half2_rn(v.x, v.y);
    ((__half2*)(out + i))[1] = __floats2half2_rn(v.z, v.w);
}

// Fused weight prep: y in {0,1,2} converts wq/wk/wv to fp16;
// y==3 splits wo into fp16 hi/lo.
__global__ void prep_w_kernel(
    const float* __restrict__ wq, const float* __restrict__ wk,
    const float* __restrict__ wv, const float* __restrict__ wo,
    __half* __restrict__ wqh, __half* __restrict__ wkh,
    __half* __restrict__ wvh,
    __half* __restrict__ wohi, __half* __restrict__ wolo)
{
    int i = (blockIdx.x * blockDim.x + threadIdx.x) * 4;
    if (i >= DMODEL * DMODEL) return;
    if (blockIdx.y < 3) {
        const float* in = (blockIdx.y == 0) ? wq : (blockIdx.y == 1) ? wk : wv;
        __half* out = (blockIdx.y == 0) ? wqh : (blockIdx.y == 1) ? wkh : wvh;
        float4 v = *(const float4*)(in + i);
        ((__half2*)(out + i))[0] = __floats2half2_rn(v.x, v.y);
        ((__half2*)(out + i))[1] = __floats2half2_rn(v.z, v.w);
    } else {
        float4 v = *(const float4*)(wo + i);
        __half a0 = __float2half_rn(v.x);
        __half a1 = __float2half_rn(v.y);
        __half a2 = __float2half_rn(v.z);
        __half a3 = __float2half_rn(v.w);
        ((__half2*)(wohi + i))[0] = __half2(a0, a1);
        ((__half2*)(wohi + i))[1] = __half2(a2, a3);
        ((__half2*)(wolo + i))[0] = __floats2half2_rn(v.x - __half2float(a0),
                                                      v.y - __half2float(a1));
        ((__half2*)(wolo + i))[1] = __floats2half2_rn(v.z - __half2float(a2),
                                                      v.w - __half2float(a3));
    }
}

// ---------------------------------------------------------------------------
// Shared GEMM geometry: CTA 128x128, BK=32, 256 threads (8 warps, 2x4),
// warp tile 64x32, launch_bounds(256,2).
// ---------------------------------------------------------------------------
#define GK_BK       32
#define GK_ROW_B    80
#define GK_TILE_B   (128 * GK_ROW_B)           // 10240
#define GK_NCHUNKS  (DMODEL / GK_BK)           // 32

// -- single-pass variant (QKV): 2 tiles/stage, 4 stages = 81920 B --
#define G1_STAGE_B  (2 * GK_TILE_B)            // 20480
#define G1_STAGES   4
#define G1_SMEM     (G1_STAGES * G1_STAGE_B)   // 81920

// -- two-pass variant (out-proj): 3 tiles/stage, 3 stages = 92160 B --
#define G2_STAGE_B  (3 * GK_TILE_B)            // 30720
#define G2_STAGES   3
#define G2_SMEM     (G2_STAGES * G2_STAGE_B)   // 92160

// ---------------------------------------------------------------------------
// Fused QKV projection (single-pass fp16): grid.z selects W/output.
// ---------------------------------------------------------------------------
__global__ __launch_bounds__(256, 2) void gemm_qkv(
    const __half* __restrict__ xh,
    const __half* __restrict__ wqh, const __half* __restrict__ wkh,
    const __half* __restrict__ wvh,
    __half* __restrict__ qh, __half* __restrict__ kh, __half* __restrict__ vh)
{
    extern __shared__ char smem[];
    const uint32_t sbase = smem_u32(smem);
    const int tid = threadIdx.x;
    const int bm = blockIdx.y * 128;
    const int bn = blockIdx.x * 128;

    const __half* B;
    __half* C;
    if (blockIdx.z == 0)      { B = wqh; C = qh; }
    else if (blockIdx.z == 1) { B = wkh; C = kh; }
    else                      { B = wvh; C = vh; }

    const int wid  = tid >> 5;
    const int lane = tid & 31;
    const int warp_m = wid >> 2;
    const int warp_n = wid & 3;

    float acc[4][4][4];
#pragma unroll
    for (int i = 0; i < 4; i++)
#pragma unroll
        for (int j = 0; j < 4; j++)
#pragma unroll
            for (int r = 0; r < 4; r++) acc[i][j][r] = 0.f;

    auto load_chunk = [&](int c, int st) {
        const int k0 = c * GK_BK;
        const uint32_t sb = sbase + st * G1_STAGE_B;
#pragma unroll
        for (int i = tid; i < 512; i += 256) {
            const int r = i >> 2;
            const int q = i & 3;
            cp_async16(sb + r * GK_ROW_B + q * 16,
                       xh + (size_t)(bm + r) * DMODEL + k0 + q * 8);
            cp_async16(sb + GK_TILE_B + r * GK_ROW_B + q * 16,
                       B + (size_t)(bn + r) * DMODEL + k0 + q * 8);
        }
        CP_COMMIT();
    };

    load_chunk(0, 0);
    load_chunk(1, 1);
    load_chunk(2, 2);

    const uint32_t lrow16 = (uint32_t)(lane & 15);
    const uint32_t lcolb  = (uint32_t)((lane >> 4) << 4);

    for (int c = 0; c < GK_NCHUNKS; c++) {
        const int st = c % G1_STAGES;
        CP_WAIT(2);
        __syncthreads();
        if (c + 3 < GK_NCHUNKS) load_chunk(c + 3, (c + 3) % G1_STAGES);
        else                    CP_COMMIT();

        const uint32_t stg = sbase + st * G1_STAGE_B;
        const uint32_t a_r = (uint32_t)(warp_m * 64) + lrow16;
        const uint32_t b_r = (uint32_t)(warp_n * 32) + lrow16;

#pragma unroll
        for (int ks = 0; ks < 2; ks++) {
            const uint32_t kb = lcolb + ks * 32;
            uint32_t ah[4][4], bb[2][4];
#pragma unroll
            for (int mi = 0; mi < 4; mi++)
                ldsm_x4(ah[mi], stg + (a_r + mi * 16) * GK_ROW_B + kb);
#pragma unroll
            for (int p = 0; p < 2; p++)
                ldsm_x4(bb[p], stg + GK_TILE_B + (b_r + p * 16) * GK_ROW_B + kb);
#pragma unroll
            for (int mi = 0; mi < 4; mi++)
#pragma unroll
                for (int ni = 0; ni < 4; ni++) {
                    const int p = ni >> 1, s = ni & 1;
                    mma_f16(acc[mi][ni], ah[mi], bb[p][s], bb[p][s + 2]);
                }
        }
        __syncthreads();
    }

    const int er = lane >> 2;
    const int ec = (lane & 3) * 2;
#pragma unroll
    for (int mi = 0; mi < 4; mi++) {
        const int row0 = bm + warp_m * 64 + mi * 16 + er;
#pragma unroll
        for (int ni = 0; ni < 4; ni++) {
            const int col = bn + warp_n * 32 + ni * 8 + ec;
            *(uint32_t*)(C + (size_t)row0 * DMODEL + col) =
                pack_f16(acc[mi][ni][0], acc[mi][ni][1]);
            *(uint32_t*)(C + (size_t)(row0 + 8) * DMODEL + col) =
                pack_f16(acc[mi][ni][2], acc[mi][ni][3]);
        }
    }
}

// ---------------------------------------------------------------------------
// Output projection (two-pass fp16 hi/lo weights): fp32 out + bias.
// ---------------------------------------------------------------------------
__global__ __launch_bounds__(256, 2) void gemm_out(
    const __half* __restrict__ Ah,
    const __half* __restrict__ Bhi, const __half* __restrict__ Blo,
    const float* __restrict__ bias, float* __restrict__ C)
{
    extern __shared__ char smem[];
    const uint32_t sbase = smem_u32(smem);
    const int tid = threadIdx.x;
    const int bm = blockIdx.y * 128;
    const int bn = blockIdx.x * 128;

    const int wid  = tid >> 5;
    const int lane = tid & 31;
    const int warp_m = wid >> 2;
    const int warp_n = wid & 3;

    const __half* srcs[3] = {Ah, Bhi, Blo};

    float acc[4][4][4];
#pragma unroll
    for (int i = 0; i < 4; i++)
#pragma unroll
        for (int j = 0; j < 4; j++)
#pragma unroll
            for (int r = 0; r < 4; r++) acc[i][j][r] = 0.f;

    auto load_chunk = [&](int c, int st) {
        const int k0 = c * GK_BK;
#pragma unroll
        for (int t = 0; t < 3; t++) {
            const __half* src = srcs[t];
            const int rbase = (t < 1) ? bm : bn;
            const uint32_t tb = sbase + st * G2_STAGE_B + t * GK_TILE_B;
#pragma unroll
            for (int i = tid; i < 512; i += 256) {
                const int r = i >> 2;
                const int q = i & 3;
                cp_async16(tb + r * GK_ROW_B + q * 16,
                           src + (size_t)(rbase + r) * DMODEL + k0 + q * 8);
            }
        }
        CP_COMMIT();
    };

    load_chunk(0, 0);
    load_chunk(1, 1);

    const uint32_t lrow16 = (uint32_t)(lane & 15);
    const uint32_t lcolb  = (uint32_t)((lane >> 4) << 4);

    for (int c = 0; c < GK_NCHUNKS; c++) {
        const int st = c % G2_STAGES;
        if (c + 1 < GK_NCHUNKS) { CP_WAIT(1); } else { CP_WAIT(0); }
        __syncthreads();
        if (c + 2 < GK_NCHUNKS)
            load_chunk(c + 2, (c + 2) % G2_STAGES);

        const uint32_t stg = sbase + st * G2_STAGE_B;
        const uint32_t a_r = (uint32_t)(warp_m * 64) + lrow16;
        const uint32_t b_r = (uint32_t)(warp_n * 32) + lrow16;

#pragma unroll
        for (int ks = 0; ks < 2; ks++) {
            const uint32_t kb = lcolb + ks * 32;
            uint32_t ah[4][4], bh[2][4], bl[2][4];
#pragma unroll
            for (int mi = 0; mi < 4; mi++)
                ldsm_x4(ah[mi], stg + 0 * GK_TILE_B + (a_r + mi * 16) * GK_ROW_B + kb);
#pragma unroll
            for (int p = 0; p < 2; p++) {
                uint32_t ro = (b_r + p * 16) * GK_ROW_B + kb;
                ldsm_x4(bh[p], stg + 1 * GK_TILE_B + ro);
                ldsm_x4(bl[p], stg + 2 * GK_TILE_B + ro);
            }
#pragma unroll
            for (int mi = 0; mi < 4; mi++)
#pragma unroll
                for (int ni = 0; ni < 4; ni++) {
                    const int p = ni >> 1, s = ni & 1;
                    mma_f16(acc[mi][ni], ah[mi], bh[p][s], bh[p][s + 2]);
                    mma_f16(acc[mi][ni], ah[mi], bl[p][s], bl[p][s + 2]);
                }
        }
        __syncthreads();
    }

    const int er = lane >> 2;
    const int ec = (lane & 3) * 2;
#pragma unroll
    for (int mi = 0; mi < 4; mi++) {
        const int row0 = bm + warp_m * 64 + mi * 16 + er;
#pragma unroll
        for (int ni = 0; ni < 4; ni++) {
            const int col = bn + warp_n * 32 + ni * 8 + ec;
            const float b0 = bias[col];
            const float b1 = bias[col + 1];
            float2 v0 = make_float2(acc[mi][ni][0] + b0, acc[mi][ni][1] + b1);
            float2 v1 = make_float2(acc[mi][ni][2] + b0, acc[mi][ni][3] + b1);
            *(float2*)(C + (size_t)row0 * DMODEL + col)       = v0;
            *(float2*)(C + (size_t)(row0 + 8) * DMODEL + col) = v1;
        }
    }
}

// ---------------------------------------------------------------------------
// Flash attention v3 (causal): fp16 single-pass MMA, fp32 softmax.
// (unchanged from round 11 — known good)
// ---------------------------------------------------------------------------
#define FA_ROW_B    144
#define FA_Q_B      (128 * FA_ROW_B)        // 18432
#define FA_KV_ARR_B (64 * FA_ROW_B)         // 9216
#define FA_STAGE_B  (2 * FA_KV_ARR_B)       // 18432
#define FA_NSTAGES  4
#define FA_KV_OFF   FA_Q_B
#define FA_SMEM     (FA_Q_B + FA_NSTAGES * FA_STAGE_B)  // 92160

__global__ __launch_bounds__(256, 2) void flash_mma_kernel(
    const __half* __restrict__ Q, const __half* __restrict__ K,
    const __half* __restrict__ V, __half* __restrict__ C)
{
    extern __shared__ char fsm[];
    const uint32_t sbase = smem_u32(fsm);

    const int tid  = threadIdx.x;
    const int wid  = tid >> 5;
    const int lane = tid & 31;
    const int qt = blockIdx.x;
    const int h  = blockIdx.y;
    const int b  = blockIdx.z;

    const int q0_tok = b * SEQ + qt * 128;
    const int qrow_w = qt * 128 + wid * 16;

    {
        const __half* Qg = Q + (size_t)q0_tok * DMODEL + h * HDIM;
#pragma unroll
        for (int i = tid; i < 1024; i += 256) {
            const int r  = i >> 3;
            const int c8 = i & 7;
            cp_async16(sbase + r * FA_ROW_B + c8 * 16,
                       Qg + (size_t)r * DMODEL + c8 * 8);
        }
        CP_COMMIT();
    }

    float o[8][4];
    float m[2], l[2];
#pragma unroll
    for (int i = 0; i < 8; i++)
#pragma unroll
        for (int j = 0; j < 4; j++) o[i][j] = 0.f;
    m[0] = m[1] = -CUDART_INF_F;
    l[0] = l[1] = 0.f;

    const uint32_t a_loff = (uint32_t)((lane & 15) * FA_ROW_B + ((lane >> 4) << 4));
    const uint32_t k_loff = (uint32_t)(((lane & 7) + ((lane >> 4) << 3)) * FA_ROW_B
                                       + (((lane >> 3) & 1) << 4));
    const uint32_t v_loff = (uint32_t)(((lane & 7) + (((lane >> 3) & 1) << 3)) * FA_ROW_B
                                       + ((lane >> 4) << 4));

    const uint32_t q_w = sbase + (uint32_t)(wid * 16) * FA_ROW_B + a_loff;

    const __half* Kh = K + h * HDIM;
    const __half* Vh = V + h * HDIM;

    auto load_tile = [&](int kt, int stg) {
        const size_t tok0 = (size_t)(b * SEQ + kt * 64);
        const uint32_t sb = sbase + FA_KV_OFF + stg * FA_STAGE_B;
#pragma unroll
        for (int i = tid; i < 512; i += 256) {
            const int r  = i >> 3;
            const int c8 = i & 7;
            cp_async16(sb + r * FA_ROW_B + c8 * 16,
                       Kh + (tok0 + r) * DMODEL + c8 * 8);
            cp_async16(sb + FA_KV_ARR_B + r * FA_ROW_B + c8 * 16,
                       Vh + (tok0 + r) * DMODEL + c8 * 8);
        }
        CP_COMMIT();
    };

    const int nkt = 2 * qt + 2;

#pragma unroll
    for (int p = 0; p < 3; p++) {
        if (p < nkt) load_tile(p, p);
        else         CP_COMMIT();
    }

    for (int kt = 0; kt < nkt; kt++) {
        const int kb = kt * 64;
        const int stg = kt & 3;
        CP_WAIT(2);
        __syncthreads();
        if (kt + 3 < nkt) load_tile(kt + 3, (kt + 3) & 3);
        else              CP_COMMIT();

        if (kb > qrow_w + 15) continue;

        const uint32_t ks_b = sbase + FA_KV_OFF + stg * FA_STAGE_B;
        const uint32_t vs_b = ks_b + FA_KV_ARR_B;

        float s[8][4];
#pragma unroll
        for (int i = 0; i < 8; i++)
#pragma unroll
            for (int j = 0; j < 4; j++) s[i][j] = 0.f;

#pragma unroll
        for (int t = 0; t < 4; t++) {
            uint32_t q4[4];
            ldsm_x4(q4, q_w + t * 32);
#pragma unroll
            for (int pp = 0; pp < 4; pp++) {
                const uint32_t ro = (uint32_t)(pp * 16 * FA_ROW_B + t * 32) + k_loff;
                uint32_t k4[4];
                ldsm_x4(k4, ks_b + ro);
                mma_f16(s[2 * pp],     q4, k4[0], k4[1]);
                mma_f16(s[2 * pp + 1], q4, k4[2], k4[3]);
            }
        }

        const int row_g0 = qrow_w + (lane >> 2);
        if (kb + 63 > qrow_w) {
#pragma unroll
            for (int nt = 0; nt < 8; nt++) {
                const int colb = kb + nt * 8 + (lane & 3) * 2;
#pragma unroll
                for (int i = 0; i < 4; i++) {
                    const int row = row_g0 + (i >> 1) * 8;
                    const int col = colb + (i & 1);
                    if (col > row) s[nt][i] = -CUDART_INF_F;
                }
            }
        }

        float rmax[2];
        rmax[0] = rmax[1] = -CUDART_INF_F;
#pragma unroll
        for (int nt = 0; nt < 8; nt++) {
            rmax[0] = fmaxf(rmax[0], fmaxf(s[nt][0], s[nt][1]));
            rmax[1] = fmaxf(rmax[1], fmaxf(s[nt][2], s[nt][3]));
        }
#pragma unroll
        for (int off = 1; off <= 2; off <<= 1) {
            rmax[0] = fmaxf(rmax[0], __shfl_xor_sync(0xffffffffu, rmax[0], off));
            rmax[1] = fmaxf(rmax[1], __shfl_xor_sync(0xffffffffu, rmax[1], off));
        }

        float alpha[2], rsum[2];
#pragma unroll
        for (int i = 0; i < 2; i++) {
            float mn = fmaxf(m[i], rmax[i]);
            alpha[i] = exp2f((m[i] - mn) * SCL2E);
            m[i] = mn;
            rsum[i] = 0.f;
        }

#pragma unroll
        for (int nt = 0; nt < 8; nt++) {
            s[nt][0] = exp2f((s[nt][0] - m[0]) * SCL2E);
            s[nt][1] = exp2f((s[nt][1] - m[0]) * SCL2E);
            s[nt][2] = exp2f((s[nt][2] - m[1]) * SCL2E);
            s[nt][3] = exp2f((s[nt][3] - m[1]) * SCL2E);
            rsum[0] += s[nt][0] + s[nt][1];
            rsum[1] += s[nt][2] + s[nt][3];
        }
        l[0] = l[0] * alpha[0] + rsum[0];
        l[1] = l[1] * alpha[1] + rsum[1];
#pragma unroll
        for (int nt = 0; nt < 8; nt++) {
            o[nt][0] *= alpha[0]; o[nt][1] *= alpha[0];
            o[nt][2] *= alpha[1]; o[nt][3] *= alpha[1];
        }

#pragma unroll
        for (int t = 0; t < 4; t++) {
            uint32_t pa[4];
            pa[0] = pack_f16(s[2 * t][0],     s[2 * t][1]);
            pa[1] = pack_f16(s[2 * t][2],     s[2 * t][3]);
            pa[2] = pack_f16(s[2 * t + 1][0], s[2 * t + 1][1]);
            pa[3] = pack_f16(s[2 * t + 1][2], s[2 * t + 1][3]);
#pragma unroll
            for (int dp = 0; dp < 4; dp++) {
                const uint32_t ro = (uint32_t)(t * 16 * FA_ROW_B + dp * 32) + v_loff;
                uint32_t v4[4];
                ldsm_x4_trans(v4, vs_b + ro);
                mma_f16(o[2 * dp],     pa, v4[0], v4[1]);
                mma_f16(o[2 * dp + 1], pa, v4[2], v4[3]);
            }
        }
    }

#pragma unroll
    for (int off = 1; off <= 2; off <<= 1) {
        l[0] += __shfl_xor_sync(0xffffffffu, l[0], off);
        l[1] += __shfl_xor_sync(0xffffffffu, l[1], off);
    }

    const float inv0 = 1.f / l[0];
    const float inv1 = 1.f / l[1];
    const int orow = q0_tok + wid * 16 + (lane >> 2);
    const int colb = h * HDIM + (lane & 3) * 2;
#pragma unroll
    for (int nt = 0; nt < 8; nt++) {
        const int col = colb + nt * 8;
        *(uint32_t*)(C + (size_t)orow * DMODEL + col) =
            pack_f16(o[nt][0] * inv0, o[nt][1] * inv0);
        *(uint32_t*)(C + (size_t)(orow + 8) * DMODEL + col) =
            pack_f16(o[nt][2] * inv1, o[nt][3] * inv1);
    }
}

// ---------------------------------------------------------------------------
// Launch
// ---------------------------------------------------------------------------
extern "C" void kernel_launch(void* const* d_in, const int* in_sizes, int n_in,
                              void* d_out, int out_size)
{
    const float* x  = (const float*)d_in[0];
    const float* wq = (const float*)d_in[1];
    const float* wk = (const float*)d_in[2];
    const float* wv = (const float*)d_in[3];
    const float* wo = (const float*)d_in[4];
    const float* bo = (const float*)d_in[5];
    float* out = (float*)d_out;

    __half *xh, *qh, *kh, *vh, *ch;
    __half *wqh, *wkh, *wvh, *wohi, *wolo;
    cudaGetSymbolAddress((void**)&xh,   g_xh);
    cudaGetSymbolAddress((void**)&qh,   g_qh);
    cudaGetSymbolAddress((void**)&kh,   g_kh);
    cudaGetSymbolAddress((void**)&vh,   g_vh);
    cudaGetSymbolAddress((void**)&ch,   g_ch);
    cudaGetSymbolAddress((void**)&wqh,  g_wqh);
    cudaGetSymbolAddress((void**)&wkh,  g_wkh);
    cudaGetSymbolAddress((void**)&wvh,  g_wvh);
    cudaGetSymbolAddress((void**)&wohi, g_wohi);
    cudaGetSymbolAddress((void**)&wolo, g_wolo);

    const int nx = TOKENS * DMODEL;
    const int nw = DMODEL * DMODEL;

    cvt_f16_kernel<<<nx / 4 / 256, 256>>>(x, xh, nx);
    prep_w_kernel<<<dim3(nw / 4 / 256, 4), 256>>>(
        wq, wk, wv, wo, wqh, wkh, wvh, wohi, wolo);

    cudaFuncSetAttribute(gemm_qkv,
                         cudaFuncAttributeMaxDynamicSharedMemorySize, G1_SMEM);
    cudaFuncSetAttribute(gemm_out,
                         cudaFuncAttributeMaxDynamicSharedMemorySize, G2_SMEM);

    gemm_qkv<<<dim3(DMODEL / 128, TOKENS / 128, 3), 256, G1_SMEM>>>(
        xh, wqh, wkh, wvh, qh, kh, vh);

    cudaFuncSetAttribute(flash_mma_kernel,
                         cudaFuncAttributeMaxDynamicSharedMemorySize, FA_SMEM);
    flash_mma_kernel<<<dim3(SEQ / 128, NHEADS, BATCH), 256, FA_SMEM>>>(
        qh, kh, vh, ch);

    gemm_out<<<dim3(DMODEL / 128, TOKENS / 128), 256, G2_SMEM>>>(
        ch, wohi, wolo, bo, out);
}

// round 13
// speedup vs baseline: 2.7658x; 1.1406x over previous
#include <cuda_runtime.h>
#include <cuda_fp16.h>
#include <math_constants.h>
#include <cstdint>

// Problem constants
#define BATCH   4
#define SEQ     2048
#define DMODEL  1024
#define NHEADS  16
#define HDIM    64
#define TOKENS  (BATCH * SEQ)   // 8192

#define LOG2E 1.4426950408889634f
#define SCL2E (0.125f * LOG2E)   // softmax scale folded into exponent

// ---------------------------------------------------------------------------
// Scratch (allocation-free rule: __device__ globals)
// ---------------------------------------------------------------------------
__device__ __half g_xh [TOKENS * DMODEL];
__device__ __half g_qh [TOKENS * DMODEL];
__device__ __half g_kh [TOKENS * DMODEL];
__device__ __half g_vh [TOKENS * DMODEL];
__device__ __half g_ch [TOKENS * DMODEL];
__device__ __half g_wqh[DMODEL * DMODEL];
__device__ __half g_wkh[DMODEL * DMODEL];
__device__ __half g_wvh[DMODEL * DMODEL];
__device__ __half g_woh[DMODEL * DMODEL];

// ---------------------------------------------------------------------------
// PTX helpers (sm_80-baseline only: cp.async, ldmatrix, mma.sync)
// ---------------------------------------------------------------------------
__device__ __forceinline__ uint32_t smem_u32(const void* p) {
    uint32_t a;
    asm("{ .reg .u64 t; cvta.to.shared.u64 t, %1; cvt.u32.u64 %0, t; }"
        : "=r"(a) : "l"(p));
    return a;
}

__device__ __forceinline__ void cp_async16(uint32_t smem, const void* gmem) {
    asm volatile("cp.async.cg.shared.global [%0], [%1], 16;\n"
                 :: "r"(smem), "l"(gmem));
}
#define CP_COMMIT() asm volatile("cp.async.commit_group;\n" ::: "memory")
#define CP_WAIT(n)  asm volatile("cp.async.wait_group %0;\n" :: "n"(n) : "memory")

__device__ __forceinline__ void ldsm_x4(uint32_t* r, uint32_t addr) {
    asm volatile("ldmatrix.sync.aligned.m8n8.x4.shared.b16 {%0,%1,%2,%3}, [%4];"
                 : "=r"(r[0]), "=r"(r[1]), "=r"(r[2]), "=r"(r[3]) : "r"(addr));
}

__device__ __forceinline__ void ldsm_x4_trans(uint32_t* r, uint32_t addr) {
    asm volatile("ldmatrix.sync.aligned.m8n8.x4.trans.shared.b16 {%0,%1,%2,%3}, [%4];"
                 : "=r"(r[0]), "=r"(r[1]), "=r"(r[2]), "=r"(r[3]) : "r"(addr));
}

__device__ __forceinline__ void mma_f16(float* c, const uint32_t* a,
                                        uint32_t b0, uint32_t b1) {
    asm volatile(
        "mma.sync.aligned.m16n8k16.row.col.f32.f16.f16.f32 "
        "{%0,%1,%2,%3}, {%4,%5,%6,%7}, {%8,%9}, {%0,%1,%2,%3};"
        : "+f"(c[0]), "+f"(c[1]), "+f"(c[2]), "+f"(c[3])
        : "r"(a[0]), "r"(a[1]), "r"(a[2]), "r"(a[3]), "r"(b0), "r"(b1));
}

__device__ __forceinline__ uint32_t pack_f16(float x, float y) {
    __half2 t = __floats2half2_rn(x, y);
    return *(uint32_t*)&t;
}

// Single-MUFU exp2 (approx, ftz). -inf -> 0, which is what the mask needs.
__device__ __forceinline__ float ex2f(float x) {
    float r;
    asm("ex2.approx.ftz.f32 %0, %1;" : "=f"(r) : "f"(x));
    return r;
}

// ---------------------------------------------------------------------------
// Preprocessing: fp32 -> fp16 conversion (x and all 4 weights).
// ---------------------------------------------------------------------------
__global__ void cvt_f16_kernel(const float* __restrict__ in,
                               __half* __restrict__ out, int n)
{
    int i = (blockIdx.x * blockDim.x + threadIdx.x) * 4;
    if (i >= n) return;
    float4 v = *(const float4*)(in + i);
    ((__half2*)(out + i))[0] = __floats2half2_rn(v.x, v.y);
    ((__half2*)(out + i))[1] = __floats2half2_rn(v.z, v.w);
}

__global__ void prep_w_kernel(
    const float* __restrict__ wq, const float* __restrict__ wk,
    const float* __restrict__ wv, const float* __restrict__ wo,
    __half* __restrict__ wqh, __half* __restrict__ wkh,
    __half* __restrict__ wvh, __half* __restrict__ woh)
{
    const float* in = (blockIdx.y == 0) ? wq : (blockIdx.y == 1) ? wk
                    : (blockIdx.y == 2) ? wv : wo;
    __half* out = (blockIdx.y == 0) ? wqh : (blockIdx.y == 1) ? wkh
                : (blockIdx.y == 2) ? wvh : woh;
    int i = (blockIdx.x * blockDim.x + threadIdx.x) * 4;
    if (i >= DMODEL * DMODEL) return;
    float4 v = *(const float4*)(in + i);
    ((__half2*)(out + i))[0] = __floats2half2_rn(v.x, v.y);
    ((__half2*)(out + i))[1] = __floats2half2_rn(v.z, v.w);
}

// ---------------------------------------------------------------------------
// Single-pass fp16 GEMM core: CTA 128x128, BK=32, 256 threads (8 warps,
// 2x4), warp tile 64x32, 4-stage cp.async (81,920 B), launch_bounds(256,2).
// ---------------------------------------------------------------------------
#define GK_BK       32
#define GK_ROW_B    80
#define GK_TILE_B   (128 * GK_ROW_B)           // 10240
#define GK_NCHUNKS  (DMODEL / GK_BK)           // 32
#define G1_STAGE_B  (2 * GK_TILE_B)            // 20480
#define G1_STAGES   4
#define G1_SMEM     (G1_STAGES * G1_STAGE_B)   // 81920

// Mainloop: A tile at bm, B tile at bn, both fp16, single pass.
__device__ __forceinline__ void g1_mainloop(
    const __half* __restrict__ A, const __half* __restrict__ B,
    int bm, int bn, uint32_t sbase, int tid, float acc[4][4][4])
{
    const int wid  = tid >> 5;
    const int lane = tid & 31;
    const int warp_m = wid >> 2;
    const int warp_n = wid & 3;

    auto load_chunk = [&](int c, int st) {
        const int k0 = c * GK_BK;
        const uint32_t sb = sbase + st * G1_STAGE_B;
#pragma unroll
        for (int i = tid; i < 512; i += 256) {
            const int r = i >> 2;
            const int q = i & 3;
            cp_async16(sb + r * GK_ROW_B + q * 16,
                       A + (size_t)(bm + r) * DMODEL + k0 + q * 8);
            cp_async16(sb + GK_TILE_B + r * GK_ROW_B + q * 16,
                       B + (size_t)(bn + r) * DMODEL + k0 + q * 8);
        }
        CP_COMMIT();
    };

    load_chunk(0, 0);
    load_chunk(1, 1);
    load_chunk(2, 2);

    const uint32_t lrow16 = (uint32_t)(lane & 15);
    const uint32_t lcolb  = (uint32_t)((lane >> 4) << 4);

    for (int c = 0; c < GK_NCHUNKS; c++) {
        const int st = c % G1_STAGES;
        CP_WAIT(2);
        __syncthreads();
        if (c + 3 < GK_NCHUNKS) load_chunk(c + 3, (c + 3) % G1_STAGES);
        else                    CP_COMMIT();

        const uint32_t stg = sbase + st * G1_STAGE_B;
        const uint32_t a_r = (uint32_t)(warp_m * 64) + lrow16;
        const uint32_t b_r = (uint32_t)(warp_n * 32) + lrow16;

#pragma unroll
        for (int ks = 0; ks < 2; ks++) {
            const uint32_t kb = lcolb + ks * 32;
            uint32_t ah[4][4], bb[2][4];
#pragma unroll
            for (int mi = 0; mi < 4; mi++)
                ldsm_x4(ah[mi], stg + (a_r + mi * 16) * GK_ROW_B + kb);
#pragma unroll
            for (int p = 0; p < 2; p++)
                ldsm_x4(bb[p], stg + GK_TILE_B + (b_r + p * 16) * GK_ROW_B + kb);
#pragma unroll
            for (int mi = 0; mi < 4; mi++)
#pragma unroll
                for (int ni = 0; ni < 4; ni++) {
                    const int p = ni >> 1, s = ni & 1;
                    mma_f16(acc[mi][ni], ah[mi], bb[p][s], bb[p][s + 2]);
                }
        }
        __syncthreads();
    }
}

// ---------------------------------------------------------------------------
// Fused QKV projection (single-pass fp16): grid.z selects W/output.
// ---------------------------------------------------------------------------
__global__ __launch_bounds__(256, 2) void gemm_qkv(
    const __half* __restrict__ xh,
    const __half* __restrict__ wqh, const __half* __restrict__ wkh,
    const __half* __restrict__ wvh,
    __half* __restrict__ qh, __half* __restrict__ kh, __half* __restrict__ vh)
{
    extern __shared__ char smem[];
    const uint32_t sbase = smem_u32(smem);
    const int tid = threadIdx.x;
    const int bm = blockIdx.y * 128;
    const int bn = blockIdx.x * 128;

    const __half* B;
    __half* C;
    if (blockIdx.z == 0)      { B = wqh; C = qh; }
    else if (blockIdx.z == 1) { B = wkh; C = kh; }
    else                      { B = wvh; C = vh; }

    float acc[4][4][4];
#pragma unroll
    for (int i = 0; i < 4; i++)
#pragma unroll
        for (int j = 0; j < 4; j++)
#pragma unroll
            for (int r = 0; r < 4; r++) acc[i][j][r] = 0.f;

    g1_mainloop(xh, B, bm, bn, sbase, tid, acc);

    const int wid  = tid >> 5;
    const int lane = tid & 31;
    const int warp_m = wid >> 2;
    const int warp_n = wid & 3;
    const int er = lane >> 2;
    const int ec = (lane & 3) * 2;
#pragma unroll
    for (int mi = 0; mi < 4; mi++) {
        const int row0 = bm + warp_m * 64 + mi * 16 + er;
#pragma unroll
        for (int ni = 0; ni < 4; ni++) {
            const int col = bn + warp_n * 32 + ni * 8 + ec;
            *(uint32_t*)(C + (size_t)row0 * DMODEL + col) =
                pack_f16(acc[mi][ni][0], acc[mi][ni][1]);
            *(uint32_t*)(C + (size_t)(row0 + 8) * DMODEL + col) =
                pack_f16(acc[mi][ni][2], acc[mi][ni][3]);
        }
    }
}

// ---------------------------------------------------------------------------
// Output projection (single-pass fp16): fp32 out + bias.
// ---------------------------------------------------------------------------
__global__ __launch_bounds__(256, 2) void gemm_out(
    const __half* __restrict__ Ah, const __half* __restrict__ Bh,
    const float* __restrict__ bias, float* __restrict__ C)
{
    extern __shared__ char smem[];
    const uint32_t sbase = smem_u32(smem);
    const int tid = threadIdx.x;
    const int bm = blockIdx.y * 128;
    const int bn = blockIdx.x * 128;

    float acc[4][4][4];
#pragma unroll
    for (int i = 0; i < 4; i++)
#pragma unroll
        for (int j = 0; j < 4; j++)
#pragma unroll
            for (int r = 0; r < 4; r++) acc[i][j][r] = 0.f;

    g1_mainloop(Ah, Bh, bm, bn, sbase, tid, acc);

    const int wid  = tid >> 5;
    const int lane = tid & 31;
    const int warp_m = wid >> 2;
    const int warp_n = wid & 3;
    const int er = lane >> 2;
    const int ec = (lane & 3) * 2;
#pragma unroll
    for (int mi = 0; mi < 4; mi++) {
        const int row0 = bm + warp_m * 64 + mi * 16 + er;
#pragma unroll
        for (int ni = 0; ni < 4; ni++) {
            const int col = bn + warp_n * 32 + ni * 8 + ec;
            const float b0 = bias[col];
            const float b1 = bias[col + 1];
            float2 v0 = make_float2(acc[mi][ni][0] + b0, acc[mi][ni][1] + b1);
            float2 v1 = make_float2(acc[mi][ni][2] + b0, acc[mi][ni][3] + b1);
            *(float2*)(C + (size_t)row0 * DMODEL + col)       = v0;
            *(float2*)(C + (size_t)(row0 + 8) * DMODEL + col) = v1;
        }
    }
}

// ---------------------------------------------------------------------------
// Flash attention v3 (causal): fp16 single-pass MMA, fp32 softmax with
// single-MUFU ex2.approx. Q in SMEM; 4-stage cp.async K/V pipeline;
// deferred l reduction. SMEM 92160 B -> 2 CTAs/SM.
// ---------------------------------------------------------------------------
#define FA_ROW_B    144
#define FA_Q_B      (128 * FA_ROW_B)        // 18432
#define FA_KV_ARR_B (64 * FA_ROW_B)         // 9216
#define FA_STAGE_B  (2 * FA_KV_ARR_B)       // 18432
#define FA_NSTAGES  4
#define FA_KV_OFF   FA_Q_B
#define FA_SMEM     (FA_Q_B + FA_NSTAGES * FA_STAGE_B)  // 92160

__global__ __launch_bounds__(256, 2) void flash_mma_kernel(
    const __half* __restrict__ Q, const __half* __restrict__ K,
    const __half* __restrict__ V, __half* __restrict__ C)
{
    extern __shared__ char fsm[];
    const uint32_t sbase = smem_u32(fsm);

    const int tid  = threadIdx.x;
    const int wid  = tid >> 5;
    const int lane = tid & 31;
    const int qt = blockIdx.x;
    const int h  = blockIdx.y;
    const int b  = blockIdx.z;

    const int q0_tok = b * SEQ + qt * 128;
    const int qrow_w = qt * 128 + wid * 16;

    {
        const __half* Qg = Q + (size_t)q0_tok * DMODEL + h * HDIM;
#pragma unroll
        for (int i = tid; i < 1024; i += 256) {
            const int r  = i >> 3;
            const int c8 = i & 7;
            cp_async16(sbase + r * FA_ROW_B + c8 * 16,
                       Qg + (size_t)r * DMODEL + c8 * 8);
        }
        CP_COMMIT();
    }

    float o[8][4];
    float m[2], l[2];
#pragma unroll
    for (int i = 0; i < 8; i++)
#pragma unroll
        for (int j = 0; j < 4; j++) o[i][j] = 0.f;
    m[0] = m[1] = -CUDART_INF_F;
    l[0] = l[1] = 0.f;

    const uint32_t a_loff = (uint32_t)((lane & 15) * FA_ROW_B + ((lane >> 4) << 4));
    const uint32_t k_loff = (uint32_t)(((lane & 7) + ((lane >> 4) << 3)) * FA_ROW_B
                                       + (((lane >> 3) & 1) << 4));
    const uint32_t v_loff = (uint32_t)(((lane & 7) + (((lane >> 3) & 1) << 3)) * FA_ROW_B
                                       + ((lane >> 4) << 4));

    const uint32_t q_w = sbase + (uint32_t)(wid * 16) * FA_ROW_B + a_loff;

    const __half* Kh = K + h * HDIM;
    const __half* Vh = V + h * HDIM;

    auto load_tile = [&](int kt, int stg) {
        const size_t tok0 = (size_t)(b * SEQ + kt * 64);
        const uint32_t sb = sbase + FA_KV_OFF + stg * FA_STAGE_B;
#pragma unroll
        for (int i = tid; i < 512; i += 256) {
            const int r  = i >> 3;
            const int c8 = i & 7;
            cp_async16(sb + r * FA_ROW_B + c8 * 16,
                       Kh + (tok0 + r) * DMODEL + c8 * 8);
            cp_async16(sb + FA_KV_ARR_B + r * FA_ROW_B + c8 * 16,
                       Vh + (tok0 + r) * DMODEL + c8 * 8);
        }
        CP_COMMIT();
    };

    const int nkt = 2 * qt + 2;

#pragma unroll
    for (int p = 0; p < 3; p++) {
        if (p < nkt) load_tile(p, p);
        else         CP_COMMIT();
    }

    for (int kt = 0; kt < nkt; kt++) {
        const int kb = kt * 64;
        const int stg = kt & 3;
        CP_WAIT(2);
        __syncthreads();
        if (kt + 3 < nkt) load_tile(kt + 3, (kt + 3) & 3);
        else              CP_COMMIT();

        if (kb > qrow_w + 15) continue;

        const uint32_t ks_b = sbase + FA_KV_OFF + stg * FA_STAGE_B;
        const uint32_t vs_b = ks_b + FA_KV_ARR_B;

        float s[8][4];
#pragma unroll
        for (int i = 0; i < 8; i++)
#pragma unroll
            for (int j = 0; j < 4; j++) s[i][j] = 0.f;

#pragma unroll
        for (int t = 0; t < 4; t++) {
            uint32_t q4[4];
            ldsm_x4(q4, q_w + t * 32);
#pragma unroll
            for (int pp = 0; pp < 4; pp++) {
                const uint32_t ro = (uint32_t)(pp * 16 * FA_ROW_B + t * 32) + k_loff;
                uint32_t k4[4];
                ldsm_x4(k4, ks_b + ro);
                mma_f16(s[2 * pp],     q4, k4[0], k4[1]);
                mma_f16(s[2 * pp + 1], q4, k4[2], k4[3]);
            }
        }

        const int row_g0 = qrow_w + (lane >> 2);
        if (kb + 63 > qrow_w) {
#pragma unroll
            for (int nt = 0; nt < 8; nt++) {
                const int colb = kb + nt * 8 + (lane & 3) * 2;
#pragma unroll
                for (int i = 0; i < 4; i++) {
                    const int row = row_g0 + (i >> 1) * 8;
                    const int col = colb + (i & 1);
                    if (col > row) s[nt][i] = -CUDART_INF_F;
                }
            }
        }

        float rmax[2];
        rmax[0] = rmax[1] = -CUDART_INF_F;
#pragma unroll
        for (int nt = 0; nt < 8; nt++) {
            rmax[0] = fmaxf(rmax[0], fmaxf(s[nt][0], s[nt][1]));
            rmax[1] = fmaxf(rmax[1], fmaxf(s[nt][2], s[nt][3]));
        }
#pragma unroll
        for (int off = 1; off <= 2; off <<= 1) {
            rmax[0] = fmaxf(rmax[0], __shfl_xor_sync(0xffffffffu, rmax[0], off));
            rmax[1] = fmaxf(rmax[1], __shfl_xor_sync(0xffffffffu, rmax[1], off));
        }

        float alpha[2], rsum[2];
#pragma unroll
        for (int i = 0; i < 2; i++) {
            float mn = fmaxf(m[i], rmax[i]);
            alpha[i] = ex2f((m[i] - mn) * SCL2E);
            m[i] = mn;
            rsum[i] = 0.f;
        }

#pragma unroll
        for (int nt = 0; nt < 8; nt++) {
            s[nt][0] = ex2f((s[nt][0] - m[0]) * SCL2E);
            s[nt][1] = ex2f((s[nt][1] - m[0]) * SCL2E);
            s[nt][2] = ex2f((s[nt][2] - m[1]) * SCL2E);
            s[nt][3] = ex2f((s[nt][3] - m[1]) * SCL2E);
            rsum[0] += s[nt][0] + s[nt][1];
            rsum[1] += s[nt][2] + s[nt][3];
        }
        l[0] = l[0] * alpha[0] + rsum[0];
        l[1] = l[1] * alpha[1] + rsum[1];
#pragma unroll
        for (int nt = 0; nt < 8; nt++) {
            o[nt][0] *= alpha[0]; o[nt][1] *= alpha[0];
            o[nt][2] *= alpha[1]; o[nt][3] *= alpha[1];
        }

#pragma unroll
        for (int t = 0; t < 4; t++) {
            uint32_t pa[4];
            pa[0] = pack_f16(s[2 * t][0],     s[2 * t][1]);
            pa[1] = pack_f16(s[2 * t][2],     s[2 * t][3]);
            pa[2] = pack_f16(s[2 * t + 1][0], s[2 * t + 1][1]);
            pa[3] = pack_f16(s[2 * t + 1][2], s[2 * t + 1][3]);
#pragma unroll
            for (int dp = 0; dp < 4; dp++) {
                const uint32_t ro = (uint32_t)(t * 16 * FA_ROW_B + dp * 32) + v_loff;
                uint32_t v4[4];
                ldsm_x4_trans(v4, vs_b + ro);
                mma_f16(o[2 * dp],     pa, v4[0], v4[1]);
                mma_f16(o[2 * dp + 1], pa, v4[2], v4[3]);
            }
        }
    }

#pragma unroll
    for (int off = 1; off <= 2; off <<= 1) {
        l[0] += __shfl_xor_sync(0xffffffffu, l[0], off);
        l[1] += __shfl_xor_sync(0xffffffffu, l[1], off);
    }

    const float inv0 = 1.f / l[0];
    const float inv1 = 1.f / l[1];
    const int orow = q0_tok + wid * 16 + (lane >> 2);
    const int colb = h * HDIM + (lane & 3) * 2;
#pragma unroll
    for (int nt = 0; nt < 8; nt++) {
        const int col = colb + nt * 8;
        *(uint32_t*)(C + (size_t)orow * DMODEL + col) =
            pack_f16(o[nt][0] * inv0, o[nt][1] * inv0);
        *(uint32_t*)(C + (size_t)(orow + 8) * DMODEL + col) =
            pack_f16(o[nt][2] * inv1, o[nt][3] * inv1);
    }
}

// ---------------------------------------------------------------------------
// Launch
// ---------------------------------------------------------------------------
extern "C" void kernel_launch(void* const* d_in, const int* in_sizes, int n_in,
                              void* d_out, int out_size)
{
    const float* x  = (const float*)d_in[0];
    const float* wq = (const float*)d_in[1];
    const float* wk = (const float*)d_in[2];
    const float* wv = (const float*)d_in[3];
    const float* wo = (const float*)d_in[4];
    const float* bo = (const float*)d_in[5];
    float* out = (float*)d_out;

    __half *xh, *qh, *kh, *vh, *ch;
    __half *wqh, *wkh, *wvh, *woh;
    cudaGetSymbolAddress((void**)&xh,  g_xh);
    cudaGetSymbolAddress((void**)&qh,  g_qh);
    cudaGetSymbolAddress((void**)&kh,  g_kh);
    cudaGetSymbolAddress((void**)&vh,  g_vh);
    cudaGetSymbolAddress((void**)&ch,  g_ch);
    cudaGetSymbolAddress((void**)&wqh, g_wqh);
    cudaGetSymbolAddress((void**)&wkh, g_wkh);
    cudaGetSymbolAddress((void**)&wvh, g_wvh);
    cudaGetSymbolAddress((void**)&woh, g_woh);

    const int nx = TOKENS * DMODEL;
    const int nw = DMODEL * DMODEL;

    cvt_f16_kernel<<<nx / 4 / 256, 256>>>(x, xh, nx);
    prep_w_kernel<<<dim3(nw / 4 / 256, 4), 256>>>(
        wq, wk, wv, wo, wqh, wkh, wvh, woh);

    cudaFuncSetAttribute(gemm_qkv,
                         cudaFuncAttributeMaxDynamicSharedMemorySize, G1_SMEM);
    cudaFuncSetAttribute(gemm_out,
                         cudaFuncAttributeMaxDynamicSharedMemorySize, G1_SMEM);

    gemm_qkv<<<dim3(DMODEL / 128, TOKENS / 128, 3), 256, G1_SMEM>>>(
        xh, wqh, wkh, wvh, qh, kh, vh);

    cudaFuncSetAttribute(flash_mma_kernel,
                         cudaFuncAttributeMaxDynamicSharedMemorySize, FA_SMEM);
    flash_mma_kernel<<<dim3(SEQ / 128, NHEADS, BATCH), 256, FA_SMEM>>>(
        qh, kh, vh, ch);

    gemm_out<<<dim3(DMODEL / 128, TOKENS / 128), 256, G1_SMEM>>>(
        ch, woh, bo, out);
}

// round 14
// speedup vs baseline: 2.8797x; 1.0412x over previous
#include <cuda_runtime.h>
#include <cuda_fp16.h>
#include <math_constants.h>
#include <cstdint>

// Problem constants
#define BATCH   4
#define SEQ     2048
#define DMODEL  1024
#define NHEADS  16
#define HDIM    64
#define TOKENS  (BATCH * SEQ)   // 8192

#define LOG2E 1.4426950408889634f
#define SCL2E (0.125f * LOG2E)   // softmax scale folded into exponent

// ---------------------------------------------------------------------------
// Scratch (allocation-free rule: __device__ globals)
// ---------------------------------------------------------------------------
__device__ __half g_xh [TOKENS * DMODEL];
__device__ __half g_qh [TOKENS * DMODEL];
__device__ __half g_kh [TOKENS * DMODEL];
__device__ __half g_vh [TOKENS * DMODEL];
__device__ __half g_ch [TOKENS * DMODEL];
__device__ __half g_wqh[DMODEL * DMODEL];
__device__ __half g_wkh[DMODEL * DMODEL];
__device__ __half g_wvh[DMODEL * DMODEL];
__device__ __half g_woh[DMODEL * DMODEL];

// ---------------------------------------------------------------------------
// PTX helpers (sm_80-baseline only: cp.async, ldmatrix, mma.sync)
// ---------------------------------------------------------------------------
__device__ __forceinline__ uint32_t smem_u32(const void* p) {
    uint32_t a;
    asm("{ .reg .u64 t; cvta.to.shared.u64 t, %1; cvt.u32.u64 %0, t; }"
        : "=r"(a) : "l"(p));
    return a;
}

__device__ __forceinline__ void cp_async16(uint32_t smem, const void* gmem) {
    asm volatile("cp.async.cg.shared.global [%0], [%1], 16;\n"
                 :: "r"(smem), "l"(gmem));
}
#define CP_COMMIT() asm volatile("cp.async.commit_group;\n" ::: "memory")
#define CP_WAIT(n)  asm volatile("cp.async.wait_group %0;\n" :: "n"(n) : "memory")

__device__ __forceinline__ void ldsm_x4(uint32_t* r, uint32_t addr) {
    asm volatile("ldmatrix.sync.aligned.m8n8.x4.shared.b16 {%0,%1,%2,%3}, [%4];"
                 : "=r"(r[0]), "=r"(r[1]), "=r"(r[2]), "=r"(r[3]) : "r"(addr));
}

__device__ __forceinline__ void ldsm_x4_trans(uint32_t* r, uint32_t addr) {
    asm volatile("ldmatrix.sync.aligned.m8n8.x4.trans.shared.b16 {%0,%1,%2,%3}, [%4];"
                 : "=r"(r[0]), "=r"(r[1]), "=r"(r[2]), "=r"(r[3]) : "r"(addr));
}

__device__ __forceinline__ void mma_f16(float* c, const uint32_t* a,
                                        uint32_t b0, uint32_t b1) {
    asm volatile(
        "mma.sync.aligned.m16n8k16.row.col.f32.f16.f16.f32 "
        "{%0,%1,%2,%3}, {%4,%5,%6,%7}, {%8,%9}, {%0,%1,%2,%3};"
        : "+f"(c[0]), "+f"(c[1]), "+f"(c[2]), "+f"(c[3])
        : "r"(a[0]), "r"(a[1]), "r"(a[2]), "r"(a[3]), "r"(b0), "r"(b1));
}

__device__ __forceinline__ uint32_t pack_f16(float x, float y) {
    __half2 t = __floats2half2_rn(x, y);
    return *(uint32_t*)&t;
}

// Single-MUFU exp2 (approx, ftz). -inf -> 0, which is what the mask needs.
__device__ __forceinline__ float ex2f(float x) {
    float r;
    asm("ex2.approx.ftz.f32 %0, %1;" : "=f"(r) : "f"(x));
    return r;
}

// ---------------------------------------------------------------------------
// Preprocessing: fp32 -> fp16 conversion (x and all 4 weights).
// ---------------------------------------------------------------------------
__global__ void cvt_f16_kernel(const float* __restrict__ in,
                               __half* __restrict__ out, int n)
{
    int i = (blockIdx.x * blockDim.x + threadIdx.x) * 4;
    if (i >= n) return;
    float4 v = *(const float4*)(in + i);
    ((__half2*)(out + i))[0] = __floats2half2_rn(v.x, v.y);
    ((__half2*)(out + i))[1] = __floats2half2_rn(v.z, v.w);
}

__global__ void prep_w_kernel(
    const float* __restrict__ wq, const float* __restrict__ wk,
    const float* __restrict__ wv, const float* __restrict__ wo,
    __half* __restrict__ wqh, __half* __restrict__ wkh,
    __half* __restrict__ wvh, __half* __restrict__ woh)
{
    const float* in = (blockIdx.y == 0) ? wq : (blockIdx.y == 1) ? wk
                    : (blockIdx.y == 2) ? wv : wo;
    __half* out = (blockIdx.y == 0) ? wqh : (blockIdx.y == 1) ? wkh
                : (blockIdx.y == 2) ? wvh : woh;
    int i = (blockIdx.x * blockDim.x + threadIdx.x) * 4;
    if (i >= DMODEL * DMODEL) return;
    float4 v = *(const float4*)(in + i);
    ((__half2*)(out + i))[0] = __floats2half2_rn(v.x, v.y);
    ((__half2*)(out + i))[1] = __floats2half2_rn(v.z, v.w);
}

// ---------------------------------------------------------------------------
// Single-pass fp16 GEMM core: CTA 128x128, BK=64, 256 threads (8 warps,
// 2x4), warp tile 64x32, 3-stage cp.async (110,592 B), launch_bounds(256,2).
// Row pitch 144 B (128 data + 16 pad): 9*16B units -> ldmatrix conflict-free.
// ---------------------------------------------------------------------------
#define GK_BK       64
#define GK_ROW_B    144
#define GK_TILE_B   (128 * GK_ROW_B)           // 18432
#define GK_NCHUNKS  (DMODEL / GK_BK)           // 16
#define G1_STAGE_B  (2 * GK_TILE_B)            // 36864
#define G1_STAGES   3
#define G1_SMEM     (G1_STAGES * G1_STAGE_B)   // 110592

// Mainloop: A tile at bm, B tile at bn, both fp16, single pass.
__device__ __forceinline__ void g1_mainloop(
    const __half* __restrict__ A, const __half* __restrict__ B,
    int bm, int bn, uint32_t sbase, int tid, float acc[4][4][4])
{
    const int wid  = tid >> 5;
    const int lane = tid & 31;
    const int warp_m = wid >> 2;
    const int warp_n = wid & 3;

    auto load_chunk = [&](int c, int st) {
        const int k0 = c * GK_BK;
        const uint32_t sb = sbase + st * G1_STAGE_B;
#pragma unroll
        for (int i = tid; i < 1024; i += 256) {
            const int r = i >> 3;
            const int q = i & 7;
            cp_async16(sb + r * GK_ROW_B + q * 16,
                       A + (size_t)(bm + r) * DMODEL + k0 + q * 8);
            cp_async16(sb + GK_TILE_B + r * GK_ROW_B + q * 16,
                       B + (size_t)(bn + r) * DMODEL + k0 + q * 8);
        }
        CP_COMMIT();
    };

    load_chunk(0, 0);
    load_chunk(1, 1);

    const uint32_t lrow16 = (uint32_t)(lane & 15);
    const uint32_t lcolb  = (uint32_t)((lane >> 4) << 4);

    for (int c = 0; c < GK_NCHUNKS; c++) {
        const int st = c % G1_STAGES;
        if (c + 1 < GK_NCHUNKS) { CP_WAIT(1); } else { CP_WAIT(0); }
        __syncthreads();
        if (c + 2 < GK_NCHUNKS) load_chunk(c + 2, (c + 2) % G1_STAGES);

        const uint32_t stg = sbase + st * G1_STAGE_B;
        const uint32_t a_r = (uint32_t)(warp_m * 64) + lrow16;
        const uint32_t b_r = (uint32_t)(warp_n * 32) + lrow16;

#pragma unroll
        for (int ks = 0; ks < 4; ks++) {
            const uint32_t kb = lcolb + ks * 32;
            uint32_t ah[4][4], bb[2][4];
#pragma unroll
            for (int mi = 0; mi < 4; mi++)
                ldsm_x4(ah[mi], stg + (a_r + mi * 16) * GK_ROW_B + kb);
#pragma unroll
            for (int p = 0; p < 2; p++)
                ldsm_x4(bb[p], stg + GK_TILE_B + (b_r + p * 16) * GK_ROW_B + kb);
#pragma unroll
            for (int mi = 0; mi < 4; mi++)
#pragma unroll
                for (int ni = 0; ni < 4; ni++) {
                    const int p = ni >> 1, s = ni & 1;
                    mma_f16(acc[mi][ni], ah[mi], bb[p][s], bb[p][s + 2]);
                }
        }
        __syncthreads();
    }
}

// ---------------------------------------------------------------------------
// Fused QKV projection (single-pass fp16): grid.z selects W/output.
// ---------------------------------------------------------------------------
__global__ __launch_bounds__(256, 2) void gemm_qkv(
    const __half* __restrict__ xh,
    const __half* __restrict__ wqh, const __half* __restrict__ wkh,
    const __half* __restrict__ wvh,
    __half* __restrict__ qh, __half* __restrict__ kh, __half* __restrict__ vh)
{
    extern __shared__ char smem[];
    const uint32_t sbase = smem_u32(smem);
    const int tid = threadIdx.x;
    const int bm = blockIdx.y * 128;
    const int bn = blockIdx.x * 128;

    const __half* B;
    __half* C;
    if (blockIdx.z == 0)      { B = wqh; C = qh; }
    else if (blockIdx.z == 1) { B = wkh; C = kh; }
    else                      { B = wvh; C = vh; }

    float acc[4][4][4];
#pragma unroll
    for (int i = 0; i < 4; i++)
#pragma unroll
        for (int j = 0; j < 4; j++)
#pragma unroll
            for (int r = 0; r < 4; r++) acc[i][j][r] = 0.f;

    g1_mainloop(xh, B, bm, bn, sbase, tid, acc);

    const int wid  = tid >> 5;
    const int lane = tid & 31;
    const int warp_m = wid >> 2;
    const int warp_n = wid & 3;
    const int er = lane >> 2;
    const int ec = (lane & 3) * 2;
#pragma unroll
    for (int mi = 0; mi < 4; mi++) {
        const int row0 = bm + warp_m * 64 + mi * 16 + er;
#pragma unroll
        for (int ni = 0; ni < 4; ni++) {
            const int col = bn + warp_n * 32 + ni * 8 + ec;
            *(uint32_t*)(C + (size_t)row0 * DMODEL + col) =
                pack_f16(acc[mi][ni][0], acc[mi][ni][1]);
            *(uint32_t*)(C + (size_t)(row0 + 8) * DMODEL + col) =
                pack_f16(acc[mi][ni][2], acc[mi][ni][3]);
        }
    }
}

// ---------------------------------------------------------------------------
// Output projection (single-pass fp16): fp32 out + bias.
// ---------------------------------------------------------------------------
__global__ __launch_bounds__(256, 2) void gemm_out(
    const __half* __restrict__ Ah, const __half* __restrict__ Bh,
    const float* __restrict__ bias, float* __restrict__ C)
{
    extern __shared__ char smem[];
    const uint32_t sbase = smem_u32(smem);
    const int tid = threadIdx.x;
    const int bm = blockIdx.y * 128;
    const int bn = blockIdx.x * 128;

    float acc[4][4][4];
#pragma unroll
    for (int i = 0; i < 4; i++)
#pragma unroll
        for (int j = 0; j < 4; j++)
#pragma unroll
            for (int r = 0; r < 4; r++) acc[i][j][r] = 0.f;

    g1_mainloop(Ah, Bh, bm, bn, sbase, tid, acc);

    const int wid  = tid >> 5;
    const int lane = tid & 31;
    const int warp_m = wid >> 2;
    const int warp_n = wid & 3;
    const int er = lane >> 2;
    const int ec = (lane & 3) * 2;
#pragma unroll
    for (int mi = 0; mi < 4; mi++) {
        const int row0 = bm + warp_m * 64 + mi * 16 + er;
#pragma unroll
        for (int ni = 0; ni < 4; ni++) {
            const int col = bn + warp_n * 32 + ni * 8 + ec;
            const float b0 = bias[col];
            const float b1 = bias[col + 1];
            float2 v0 = make_float2(acc[mi][ni][0] + b0, acc[mi][ni][1] + b1);
            float2 v1 = make_float2(acc[mi][ni][2] + b0, acc[mi][ni][3] + b1);
            *(float2*)(C + (size_t)row0 * DMODEL + col)       = v0;
            *(float2*)(C + (size_t)(row0 + 8) * DMODEL + col) = v1;
        }
    }
}

// ---------------------------------------------------------------------------
// Flash attention v3 (causal): fp16 single-pass MMA, fp32 softmax with
// single-MUFU ex2.approx. (unchanged from round 13 — known good)
// ---------------------------------------------------------------------------
#define FA_ROW_B    144
#define FA_Q_B      (128 * FA_ROW_B)        // 18432
#define FA_KV_ARR_B (64 * FA_ROW_B)         // 9216
#define FA_STAGE_B  (2 * FA_KV_ARR_B)       // 18432
#define FA_NSTAGES  4
#define FA_KV_OFF   FA_Q_B
#define FA_SMEM     (FA_Q_B + FA_NSTAGES * FA_STAGE_B)  // 92160

__global__ __launch_bounds__(256, 2) void flash_mma_kernel(
    const __half* __restrict__ Q, const __half* __restrict__ K,
    const __half* __restrict__ V, __half* __restrict__ C)
{
    extern __shared__ char fsm[];
    const uint32_t sbase = smem_u32(fsm);

    const int tid  = threadIdx.x;
    const int wid  = tid >> 5;
    const int lane = tid & 31;
    const int qt = blockIdx.x;
    const int h  = blockIdx.y;
    const int b  = blockIdx.z;

    const int q0_tok = b * SEQ + qt * 128;
    const int qrow_w = qt * 128 + wid * 16;

    {
        const __half* Qg = Q + (size_t)q0_tok * DMODEL + h * HDIM;
#pragma unroll
        for (int i = tid; i < 1024; i += 256) {
            const int r  = i >> 3;
            const int c8 = i & 7;
            cp_async16(sbase + r * FA_ROW_B + c8 * 16,
                       Qg + (size_t)r * DMODEL + c8 * 8);
        }
        CP_COMMIT();
    }

    float o[8][4];
    float m[2], l[2];
#pragma unroll
    for (int i = 0; i < 8; i++)
#pragma unroll
        for (int j = 0; j < 4; j++) o[i][j] = 0.f;
    m[0] = m[1] = -CUDART_INF_F;
    l[0] = l[1] = 0.f;

    const uint32_t a_loff = (uint32_t)((lane & 15) * FA_ROW_B + ((lane >> 4) << 4));
    const uint32_t k_loff = (uint32_t)(((lane & 7) + ((lane >> 4) << 3)) * FA_ROW_B
                                       + (((lane >> 3) & 1) << 4));
    const uint32_t v_loff = (uint32_t)(((lane & 7) + (((lane >> 3) & 1) << 3)) * FA_ROW_B
                                       + ((lane >> 4) << 4));

    const uint32_t q_w = sbase + (uint32_t)(wid * 16) * FA_ROW_B + a_loff;

    const __half* Kh = K + h * HDIM;
    const __half* Vh = V + h * HDIM;

    auto load_tile = [&](int kt, int stg) {
        const size_t tok0 = (size_t)(b * SEQ + kt * 64);
        const uint32_t sb = sbase + FA_KV_OFF + stg * FA_STAGE_B;
#pragma unroll
        for (int i = tid; i < 512; i += 256) {
            const int r  = i >> 3;
            const int c8 = i & 7;
            cp_async16(sb + r * FA_ROW_B + c8 * 16,
                       Kh + (tok0 + r) * DMODEL + c8 * 8);
            cp_async16(sb + FA_KV_ARR_B + r * FA_ROW_B + c8 * 16,
                       Vh + (tok0 + r) * DMODEL + c8 * 8);
        }
        CP_COMMIT();
    };

    const int nkt = 2 * qt + 2;

#pragma unroll
    for (int p = 0; p < 3; p++) {
        if (p < nkt) load_tile(p, p);
        else         CP_COMMIT();
    }

    for (int kt = 0; kt < nkt; kt++) {
        const int kb = kt * 64;
        const int stg = kt & 3;
        CP_WAIT(2);
        __syncthreads();
        if (kt + 3 < nkt) load_tile(kt + 3, (kt + 3) & 3);
        else              CP_COMMIT();

        if (kb > qrow_w + 15) continue;

        const uint32_t ks_b = sbase + FA_KV_OFF + stg * FA_STAGE_B;
        const uint32_t vs_b = ks_b + FA_KV_ARR_B;

        float s[8][4];
#pragma unroll
        for (int i = 0; i < 8; i++)
#pragma unroll
            for (int j = 0; j < 4; j++) s[i][j] = 0.f;

#pragma unroll
        for (int t = 0; t < 4; t++) {
            uint32_t q4[4];
            ldsm_x4(q4, q_w + t * 32);
#pragma unroll
            for (int pp = 0; pp < 4; pp++) {
                const uint32_t ro = (uint32_t)(pp * 16 * FA_ROW_B + t * 32) + k_loff;
                uint32_t k4[4];
                ldsm_x4(k4, ks_b + ro);
                mma_f16(s[2 * pp],     q4, k4[0], k4[1]);
                mma_f16(s[2 * pp + 1], q4, k4[2], k4[3]);
            }
        }

        const int row_g0 = qrow_w + (lane >> 2);
        if (kb + 63 > qrow_w) {
#pragma unroll
            for (int nt = 0; nt < 8; nt++) {
                const int colb = kb + nt * 8 + (lane & 3) * 2;
#pragma unroll
                for (int i = 0; i < 4; i++) {
                    const int row = row_g0 + (i >> 1) * 8;
                    const int col = colb + (i & 1);
                    if (col > row) s[nt][i] = -CUDART_INF_F;
                }
            }
        }

        float rmax[2];
        rmax[0] = rmax[1] = -CUDART_INF_F;
#pragma unroll
        for (int nt = 0; nt < 8; nt++) {
            rmax[0] = fmaxf(rmax[0], fmaxf(s[nt][0], s[nt][1]));
            rmax[1] = fmaxf(rmax[1], fmaxf(s[nt][2], s[nt][3]));
        }
#pragma unroll
        for (int off = 1; off <= 2; off <<= 1) {
            rmax[0] = fmaxf(rmax[0], __shfl_xor_sync(0xffffffffu, rmax[0], off));
            rmax[1] = fmaxf(rmax[1], __shfl_xor_sync(0xffffffffu, rmax[1], off));
        }

        float alpha[2], rsum[2];
#pragma unroll
        for (int i = 0; i < 2; i++) {
            float mn = fmaxf(m[i], rmax[i]);
            alpha[i] = ex2f((m[i] - mn) * SCL2E);
            m[i] = mn;
            rsum[i] = 0.f;
        }

#pragma unroll
        for (int nt = 0; nt < 8; nt++) {
            s[nt][0] = ex2f((s[nt][0] - m[0]) * SCL2E);
            s[nt][1] = ex2f((s[nt][1] - m[0]) * SCL2E);
            s[nt][2] = ex2f((s[nt][2] - m[1]) * SCL2E);
            s[nt][3] = ex2f((s[nt][3] - m[1]) * SCL2E);
            rsum[0] += s[nt][0] + s[nt][1];
            rsum[1] += s[nt][2] + s[nt][3];
        }
        l[0] = l[0] * alpha[0] + rsum[0];
        l[1] = l[1] * alpha[1] + rsum[1];
#pragma unroll
        for (int nt = 0; nt < 8; nt++) {
            o[nt][0] *= alpha[0]; o[nt][1] *= alpha[0];
            o[nt][2] *= alpha[1]; o[nt][3] *= alpha[1];
        }

#pragma unroll
        for (int t = 0; t < 4; t++) {
            uint32_t pa[4];
            pa[0] = pack_f16(s[2 * t][0],     s[2 * t][1]);
            pa[1] = pack_f16(s[2 * t][2],     s[2 * t][3]);
            pa[2] = pack_f16(s[2 * t + 1][0], s[2 * t + 1][1]);
            pa[3] = pack_f16(s[2 * t + 1][2], s[2 * t + 1][3]);
#pragma unroll
            for (int dp = 0; dp < 4; dp++) {
                const uint32_t ro = (uint32_t)(t * 16 * FA_ROW_B + dp * 32) + v_loff;
                uint32_t v4[4];
                ldsm_x4_trans(v4, vs_b + ro);
                mma_f16(o[2 * dp],     pa, v4[0], v4[1]);
                mma_f16(o[2 * dp + 1], pa, v4[2], v4[3]);
            }
        }
    }

#pragma unroll
    for (int off = 1; off <= 2; off <<= 1) {
        l[0] += __shfl_xor_sync(0xffffffffu, l[0], off);
        l[1] += __shfl_xor_sync(0xffffffffu, l[1], off);
    }

    const float inv0 = 1.f / l[0];
    const float inv1 = 1.f / l[1];
    const int orow = q0_tok + wid * 16 + (lane >> 2);
    const int colb = h * HDIM + (lane & 3) * 2;
#pragma unroll
    for (int nt = 0; nt < 8; nt++) {
        const int col = colb + nt * 8;
        *(uint32_t*)(C + (size_t)orow * DMODEL + col) =
            pack_f16(o[nt][0] * inv0, o[nt][1] * inv0);
        *(uint32_t*)(C + (size_t)(orow + 8) * DMODEL + col) =
            pack_f16(o[nt][2] * inv1, o[nt][3] * inv1);
    }
}

// ---------------------------------------------------------------------------
// Launch
// ---------------------------------------------------------------------------
extern "C" void kernel_launch(void* const* d_in, const int* in_sizes, int n_in,
                              void* d_out, int out_size)
{
    const float* x  = (const float*)d_in[0];
    const float* wq = (const float*)d_in[1];
    const float* wk = (const float*)d_in[2];
    const float* wv = (const float*)d_in[3];
    const float* wo = (const float*)d_in[4];
    const float* bo = (const float*)d_in[5];
    float* out = (float*)d_out;

    __half *xh, *qh, *kh, *vh, *ch;
    __half *wqh, *wkh, *wvh, *woh;
    cudaGetSymbolAddress((void**)&xh,  g_xh);
    cudaGetSymbolAddress((void**)&qh,  g_qh);
    cudaGetSymbolAddress((void**)&kh,  g_kh);
    cudaGetSymbolAddress((void**)&vh,  g_vh);
    cudaGetSymbolAddress((void**)&ch,  g_ch);
    cudaGetSymbolAddress((void**)&wqh, g_wqh);
    cudaGetSymbolAddress((void**)&wkh, g_wkh);
    cudaGetSymbolAddress((void**)&wvh, g_wvh);
    cudaGetSymbolAddress((void**)&woh, g_woh);

    const int nx = TOKENS * DMODEL;
    const int nw = DMODEL * DMODEL;

    cvt_f16_kernel<<<nx / 4 / 256, 256>>>(x, xh, nx);
    prep_w_kernel<<<dim3(nw / 4 / 256, 4), 256>>>(
        wq, wk, wv, wo, wqh, wkh, wvh, woh);

    cudaFuncSetAttribute(gemm_qkv,
                         cudaFuncAttributeMaxDynamicSharedMemorySize, G1_SMEM);
    cudaFuncSetAttribute(gemm_out,
                         cudaFuncAttributeMaxDynamicSharedMemorySize, G1_SMEM);

    gemm_qkv<<<dim3(DMODEL / 128, TOKENS / 128, 3), 256, G1_SMEM>>>(
        xh, wqh, wkh, wvh, qh, kh, vh);

    cudaFuncSetAttribute(flash_mma_kernel,
                         cudaFuncAttributeMaxDynamicSharedMemorySize, FA_SMEM);
    flash_mma_kernel<<<dim3(SEQ / 128, NHEADS, BATCH), 256, FA_SMEM>>>(
        qh, kh, vh, ch);

    gemm_out<<<dim3(DMODEL / 128, TOKENS / 128), 256, G1_SMEM>>>(
        ch, woh, bo, out);
}